// round 1
// baseline (speedup 1.0000x reference)
#include <cuda_runtime.h>
#include <math.h>

#define NN 50000
#define EE 800000

// ---------------- scratch (device globals; no allocation allowed) ----------
__device__ float g_mmax[NN * 64];
__device__ float g_den [NN * 64];
__device__ float g_num [NN * 64];
__device__ float g_h1  [NN * 128];
__device__ float g_x2  [NN * 128];
__device__ float g_xp  [NN * 128];
__device__ float g_aggr[NN * 128];
__device__ float g_o2  [NN * 64];
__device__ float g_sum[128], g_sumsq[128], g_mu[128], g_istd[128];

__device__ __forceinline__ float sigmoidf_(float v) { return 1.0f / (1.0f + __expf(-v)); }

// ---------------- zero init (must run every launch: graph replays) ---------
__global__ void k_zero(int n) {
    long i = (long)blockIdx.x * blockDim.x + threadIdx.x;   // float4 index
    float4 z = make_float4(0.f, 0.f, 0.f, 0.f);
    long n64 = (long)n * 16;    // float4 count for 64-wide arrays
    long n128 = (long)n * 32;   // float4 count for 128-wide arrays
    if (i < n64) {
        ((float4*)g_mmax)[i] = z;
        ((float4*)g_den)[i]  = z;
        ((float4*)g_num)[i]  = z;
    }
    if (i < n128) ((float4*)g_aggr)[i] = z;
    if (i < 32) { ((float4*)g_sum)[i] = z; ((float4*)g_sumsq)[i] = z; }
}

// ---------------- GENConv edge pass 1: segment max ------------------------
// msg = relu(x[src]) + eps  (strictly > 0, so int-bit atomicMax vs init 0 works)
__global__ void k_edge_max(const float* __restrict__ x,
                           const int* __restrict__ src, const int* __restrict__ dst,
                           int E) {
    int tid = blockIdx.x * blockDim.x + threadIdx.x;
    if (tid >= E * 16) return;
    int e = tid >> 4, c = tid & 15;
    int s = src[e], d = dst[e];
    float4 v = ((const float4*)x)[s * 16 + c];
    float m0 = fmaxf(v.x, 0.f) + 1e-7f;
    float m1 = fmaxf(v.y, 0.f) + 1e-7f;
    float m2 = fmaxf(v.z, 0.f) + 1e-7f;
    float m3 = fmaxf(v.w, 0.f) + 1e-7f;
    int* base = (int*)&g_mmax[d * 64 + c * 4];
    atomicMax(base + 0, __float_as_int(m0));
    atomicMax(base + 1, __float_as_int(m1));
    atomicMax(base + 2, __float_as_int(m2));
    atomicMax(base + 3, __float_as_int(m3));
}

// ---------------- GENConv edge pass 2: exp-sums ----------------------------
__global__ void k_edge_soft(const float* __restrict__ x,
                            const int* __restrict__ src, const int* __restrict__ dst,
                            int E) {
    int tid = blockIdx.x * blockDim.x + threadIdx.x;
    if (tid >= E * 16) return;
    int e = tid >> 4, c = tid & 15;
    int s = src[e], d = dst[e];
    float4 v = ((const float4*)x)[s * 16 + c];
    float4 mm = ((const float4*)g_mmax)[d * 16 + c];
    float m0 = fmaxf(v.x, 0.f) + 1e-7f;
    float m1 = fmaxf(v.y, 0.f) + 1e-7f;
    float m2 = fmaxf(v.z, 0.f) + 1e-7f;
    float m3 = fmaxf(v.w, 0.f) + 1e-7f;
    float e0 = expf(m0 - mm.x), e1 = expf(m1 - mm.y);
    float e2 = expf(m2 - mm.z), e3 = expf(m3 - mm.w);
    float* dn = &g_den[d * 64 + c * 4];
    float* nm = &g_num[d * 64 + c * 4];
    atomicAdd(dn + 0, e0); atomicAdd(dn + 1, e1);
    atomicAdd(dn + 2, e2); atomicAdd(dn + 3, e3);
    atomicAdd(nm + 0, e0 * m0); atomicAdd(nm + 1, e1 * m1);
    atomicAdd(nm + 2, e2 * m2); atomicAdd(nm + 3, e3 * m3);
}

// ---------------- GEMM1: (agg + x) @ W1 + b1 -> h1 [N,128] -----------------
__global__ void __launch_bounds__(128) k_gemm1(const float* __restrict__ x,
                                               const float* __restrict__ W1,
                                               const float* __restrict__ b1, int n) {
    __shared__ float Ws[64 * 128];
    __shared__ float bs[128];
    for (int i = threadIdx.x; i < 64 * 128; i += 128) Ws[i] = W1[i];
    if (threadIdx.x < 128) bs[threadIdx.x] = b1[threadIdx.x];
    __syncthreads();
    int nd = blockIdx.x * 128 + threadIdx.x;
    if (nd >= n) return;
    float in[64];
    const float4* nu4 = (const float4*)&g_num[nd * 64];
    const float4* de4 = (const float4*)&g_den[nd * 64];
    const float4* x4  = (const float4*)&x[(size_t)nd * 64];
#pragma unroll
    for (int i = 0; i < 16; i++) {
        float4 nu = nu4[i], de = de4[i], xv = x4[i];
        in[4 * i + 0] = nu.x / (de.x > 0.f ? de.x : 1.f) + xv.x;
        in[4 * i + 1] = nu.y / (de.y > 0.f ? de.y : 1.f) + xv.y;
        in[4 * i + 2] = nu.z / (de.z > 0.f ? de.z : 1.f) + xv.z;
        in[4 * i + 3] = nu.w / (de.w > 0.f ? de.w : 1.f) + xv.w;
    }
    for (int c = 0; c < 128; c += 8) {
        float acc[8];
#pragma unroll
        for (int j = 0; j < 8; j++) acc[j] = bs[c + j];
#pragma unroll
        for (int k = 0; k < 64; k++) {
            float a = in[k];
            float4 w0 = *(const float4*)&Ws[k * 128 + c];
            float4 w1 = *(const float4*)&Ws[k * 128 + c + 4];
            acc[0] += a * w0.x; acc[1] += a * w0.y; acc[2] += a * w0.z; acc[3] += a * w0.w;
            acc[4] += a * w1.x; acc[5] += a * w1.y; acc[6] += a * w1.z; acc[7] += a * w1.w;
        }
        float4* o = (float4*)&g_h1[(size_t)nd * 128 + c];
        o[0] = make_float4(acc[0], acc[1], acc[2], acc[3]);
        o[1] = make_float4(acc[4], acc[5], acc[6], acc[7]);
    }
}

// ---------------- BatchNorm column stats -----------------------------------
__global__ void k_colstats(int n) {
    int f = threadIdx.x;   // 128 threads
    int start = blockIdx.x * 256;
    int end = min(n, start + 256);
    float s = 0.f, s2 = 0.f;
    for (int nd = start; nd < end; nd++) {
        float v = g_h1[(size_t)nd * 128 + f];
        s += v; s2 += v * v;
    }
    atomicAdd(&g_sum[f], s);
    atomicAdd(&g_sumsq[f], s2);
}

__global__ void k_stats_final(int n) {
    int f = threadIdx.x;
    float mu = g_sum[f] / (float)n;
    float var = g_sumsq[f] / (float)n - mu * mu;
    g_mu[f] = mu;
    g_istd[f] = rsqrtf(var + 1e-5f);
}

// ---------------- GEMM2: relu(BN(h1)) @ W2 + b2 ; build x2 = sigmoid(cat) ---
__global__ void __launch_bounds__(128) k_gemm2(const float* __restrict__ x,
                                               const float* __restrict__ gamma,
                                               const float* __restrict__ beta,
                                               const float* __restrict__ W2,
                                               const float* __restrict__ b2, int n) {
    __shared__ float Ws[128 * 64];
    __shared__ float sg[128], sb[128], smu[128], sis[128], sb2[64];
    for (int i = threadIdx.x; i < 128 * 64; i += 128) Ws[i] = W2[i];
    if (threadIdx.x < 128) {
        sg[threadIdx.x] = gamma[threadIdx.x];
        sb[threadIdx.x] = beta[threadIdx.x];
        smu[threadIdx.x] = g_mu[threadIdx.x];
        sis[threadIdx.x] = g_istd[threadIdx.x];
    }
    if (threadIdx.x < 64) sb2[threadIdx.x] = b2[threadIdx.x];
    __syncthreads();
    int nd = blockIdx.x * 128 + threadIdx.x;
    if (nd >= n) return;
    float hn[128];
#pragma unroll
    for (int k = 0; k < 128; k++) {
        float v = g_h1[(size_t)nd * 128 + k];
        v = (v - smu[k]) * sis[k] * sg[k] + sb[k];
        hn[k] = fmaxf(v, 0.f);
    }
    // first half of x2 = sigmoid(x)
    const float4* x4 = (const float4*)&x[(size_t)nd * 64];
#pragma unroll
    for (int i = 0; i < 16; i++) {
        float4 xv = x4[i];
        float4 o = make_float4(sigmoidf_(xv.x), sigmoidf_(xv.y), sigmoidf_(xv.z), sigmoidf_(xv.w));
        ((float4*)&g_x2[(size_t)nd * 128])[i] = o;
    }
    for (int c = 0; c < 64; c += 8) {
        float acc[8];
#pragma unroll
        for (int j = 0; j < 8; j++) acc[j] = sb2[c + j];
#pragma unroll
        for (int k = 0; k < 128; k++) {
            float a = hn[k];
            float4 w0 = *(const float4*)&Ws[k * 64 + c];
            float4 w1 = *(const float4*)&Ws[k * 64 + c + 4];
            acc[0] += a * w0.x; acc[1] += a * w0.y; acc[2] += a * w0.z; acc[3] += a * w0.w;
            acc[4] += a * w1.x; acc[5] += a * w1.y; acc[6] += a * w1.z; acc[7] += a * w1.w;
        }
#pragma unroll
        for (int j = 0; j < 8; j++)
            g_x2[(size_t)nd * 128 + 64 + c + j] = sigmoidf_(acc[j]);
    }
}

// ---------------- GEMM3: xp = relu(x2 @ Wp + bp)  (Wp 128x128, 2 smem halves)
__global__ void __launch_bounds__(128) k_gemm3(const float* __restrict__ Wp,
                                               const float* __restrict__ bp, int n) {
    __shared__ float Ws[128 * 64];
    __shared__ float bs[128];
    if (threadIdx.x < 128) bs[threadIdx.x] = bp[threadIdx.x];
    int nd = blockIdx.x * 128 + threadIdx.x;
    bool act = nd < n;
    float row[128];
    if (act) {
#pragma unroll
        for (int i = 0; i < 32; i++) {
            float4 v = ((const float4*)&g_x2[(size_t)nd * 128])[i];
            row[4 * i + 0] = v.x; row[4 * i + 1] = v.y; row[4 * i + 2] = v.z; row[4 * i + 3] = v.w;
        }
    }
    for (int half = 0; half < 2; half++) {
        __syncthreads();
        for (int i = threadIdx.x; i < 128 * 64; i += 128) {
            int k = i >> 6, cc = i & 63;
            Ws[i] = Wp[k * 128 + half * 64 + cc];
        }
        __syncthreads();
        if (act) {
            for (int c = 0; c < 64; c += 8) {
                float acc[8];
#pragma unroll
                for (int j = 0; j < 8; j++) acc[j] = bs[half * 64 + c + j];
#pragma unroll
                for (int k = 0; k < 128; k++) {
                    float a = row[k];
                    float4 w0 = *(const float4*)&Ws[k * 64 + c];
                    float4 w1 = *(const float4*)&Ws[k * 64 + c + 4];
                    acc[0] += a * w0.x; acc[1] += a * w0.y; acc[2] += a * w0.z; acc[3] += a * w0.w;
                    acc[4] += a * w1.x; acc[5] += a * w1.y; acc[6] += a * w1.z; acc[7] += a * w1.w;
                }
                float4* o = (float4*)&g_xp[(size_t)nd * 128 + half * 64 + c];
                o[0] = make_float4(fmaxf(acc[0], 0.f), fmaxf(acc[1], 0.f), fmaxf(acc[2], 0.f), fmaxf(acc[3], 0.f));
                o[1] = make_float4(fmaxf(acc[4], 0.f), fmaxf(acc[5], 0.f), fmaxf(acc[6], 0.f), fmaxf(acc[7], 0.f));
            }
        }
    }
}

// ---------------- SAGE edge aggregation: aggr[dst] += xp[src] --------------
__global__ void k_edge_sum(const int* __restrict__ src, const int* __restrict__ dst, int E) {
    int tid = blockIdx.x * blockDim.x + threadIdx.x;
    if (tid >= E * 32) return;
    int e = tid >> 5, c = tid & 31;
    int s = src[e], d = dst[e];
    float4 v = ((const float4*)g_xp)[(size_t)s * 32 + c];
    float* base = &g_aggr[(size_t)d * 128 + c * 4];
    atomicAdd(base + 0, v.x);
    atomicAdd(base + 1, v.y);
    atomicAdd(base + 2, v.z);
    atomicAdd(base + 3, v.w);
}

// ---------------- GEMM4a: o2 = aggr @ Wl + bl -------------------------------
__global__ void __launch_bounds__(128) k_gemm4a(const float* __restrict__ Wl,
                                                const float* __restrict__ bl, int n) {
    __shared__ float Ws[128 * 64];
    __shared__ float bs[64];
    for (int i = threadIdx.x; i < 128 * 64; i += 128) Ws[i] = Wl[i];
    if (threadIdx.x < 64) bs[threadIdx.x] = bl[threadIdx.x];
    __syncthreads();
    int nd = blockIdx.x * 128 + threadIdx.x;
    if (nd >= n) return;
    float row[128];
#pragma unroll
    for (int i = 0; i < 32; i++) {
        float4 v = ((const float4*)&g_aggr[(size_t)nd * 128])[i];
        row[4 * i + 0] = v.x; row[4 * i + 1] = v.y; row[4 * i + 2] = v.z; row[4 * i + 3] = v.w;
    }
    for (int c = 0; c < 64; c += 8) {
        float acc[8];
#pragma unroll
        for (int j = 0; j < 8; j++) acc[j] = bs[c + j];
#pragma unroll
        for (int k = 0; k < 128; k++) {
            float a = row[k];
            float4 w0 = *(const float4*)&Ws[k * 64 + c];
            float4 w1 = *(const float4*)&Ws[k * 64 + c + 4];
            acc[0] += a * w0.x; acc[1] += a * w0.y; acc[2] += a * w0.z; acc[3] += a * w0.w;
            acc[4] += a * w1.x; acc[5] += a * w1.y; acc[6] += a * w1.z; acc[7] += a * w1.w;
        }
        float4* o = (float4*)&g_o2[(size_t)nd * 64 + c];
        o[0] = make_float4(acc[0], acc[1], acc[2], acc[3]);
        o[1] = make_float4(acc[4], acc[5], acc[6], acc[7]);
    }
}

// ---------------- GEMM4b: out2 = sigmoid(o2 + x2 @ Wr); fc; write outputs ---
__global__ void __launch_bounds__(128) k_gemm4b(const float* __restrict__ Wr,
                                                const float* __restrict__ Wf,
                                                const float* __restrict__ bf,
                                                float* __restrict__ out,
                                                int n, int write_logits) {
    __shared__ float Ws[128 * 64];
    __shared__ float wf[64];
    for (int i = threadIdx.x; i < 128 * 64; i += 128) Ws[i] = Wr[i];
    if (threadIdx.x < 64) wf[threadIdx.x] = Wf[threadIdx.x];
    __syncthreads();
    int nd = blockIdx.x * 128 + threadIdx.x;
    if (nd >= n) return;
    float row[128];
#pragma unroll
    for (int i = 0; i < 32; i++) {
        float4 v = ((const float4*)&g_x2[(size_t)nd * 128])[i];
        row[4 * i + 0] = v.x; row[4 * i + 1] = v.y; row[4 * i + 2] = v.z; row[4 * i + 3] = v.w;
    }
    float logit = bf[0];
    for (int c = 0; c < 64; c += 8) {
        float acc[8];
        float4 a0 = ((const float4*)&g_o2[(size_t)nd * 64 + c])[0];
        float4 a1 = ((const float4*)&g_o2[(size_t)nd * 64 + c])[1];
        acc[0] = a0.x; acc[1] = a0.y; acc[2] = a0.z; acc[3] = a0.w;
        acc[4] = a1.x; acc[5] = a1.y; acc[6] = a1.z; acc[7] = a1.w;
#pragma unroll
        for (int k = 0; k < 128; k++) {
            float a = row[k];
            float4 w0 = *(const float4*)&Ws[k * 64 + c];
            float4 w1 = *(const float4*)&Ws[k * 64 + c + 4];
            acc[0] += a * w0.x; acc[1] += a * w0.y; acc[2] += a * w0.z; acc[3] += a * w0.w;
            acc[4] += a * w1.x; acc[5] += a * w1.y; acc[6] += a * w1.z; acc[7] += a * w1.w;
        }
#pragma unroll
        for (int j = 0; j < 8; j++) {
            float s = sigmoidf_(acc[j]);
            logit += s * wf[c + j];
        }
    }
    out[nd] = sigmoidf_(logit);                  // probs
    if (write_logits) out[n + nd] = logit;       // logits
}

// ---------------- launch ----------------------------------------------------
extern "C" void kernel_launch(void* const* d_in, const int* in_sizes, int n_in,
                              void* d_out, int out_size) {
    const float* x   = (const float*)d_in[0];
    const int*   ei  = (const int*)d_in[1];
    const float* W1  = (const float*)d_in[2];
    const float* b1  = (const float*)d_in[3];
    const float* gamma = (const float*)d_in[4];
    const float* beta  = (const float*)d_in[5];
    const float* W2  = (const float*)d_in[6];
    const float* b2  = (const float*)d_in[7];
    const float* Wp  = (const float*)d_in[8];
    const float* bp  = (const float*)d_in[9];
    const float* Wl  = (const float*)d_in[10];
    const float* bl  = (const float*)d_in[11];
    const float* Wr  = (const float*)d_in[12];
    const float* Wf  = (const float*)d_in[13];
    const float* bf  = (const float*)d_in[14];
    float* out = (float*)d_out;

    int n = in_sizes[0] / 64;
    int E = in_sizes[1] / 2;
    const int* src = ei;
    const int* dst = ei + E;
    int write_logits = (out_size >= 2 * n) ? 1 : 0;

    // zero scratch
    {
        long tot4 = (long)n * 32;  // covers largest
        int blocks = (int)((tot4 + 255) / 256);
        k_zero<<<blocks, 256>>>(n);
    }
    // GENConv edge passes
    {
        int t = E * 16;
        k_edge_max<<<(t + 255) / 256, 256>>>(x, src, dst, E);
        k_edge_soft<<<(t + 255) / 256, 256>>>(x, src, dst, E);
    }
    int nb = (n + 127) / 128;
    k_gemm1<<<nb, 128>>>(x, W1, b1, n);
    k_colstats<<<(n + 255) / 256, 128>>>(n);
    k_stats_final<<<1, 128>>>(n);
    k_gemm2<<<nb, 128>>>(x, gamma, beta, W2, b2, n);
    k_gemm3<<<nb, 128>>>(Wp, bp, n);
    {
        int t = E * 32;
        k_edge_sum<<<(t + 255) / 256, 256>>>(src, dst, E);
    }
    k_gemm4a<<<nb, 128>>>(Wl, bl, n);
    k_gemm4b<<<nb, 128>>>(Wr, Wf, bf, out, n, write_logits);
}

// round 2
// speedup vs baseline: 1.7053x; 1.7053x over previous
#include <cuda_runtime.h>
#include <math.h>

#define NN 50000
#define EE 800000

// ---------------- scratch (device globals; no allocation allowed) ----------
__device__ float g_pq    [NN * 128];   // per-node: p=exp(msg) [0..63], q=p*msg [64..127]
__device__ float g_dennum[NN * 128];   // den [0..63], num [64..127]
__device__ float g_h1    [NN * 128];
__device__ float g_x2    [NN * 128];
__device__ float g_xp    [NN * 128];
__device__ float g_aggr  [NN * 128];
__device__ float g_o2    [NN * 64];
__device__ float g_sum[128], g_sumsq[128], g_mu[128], g_istd[128];

__device__ __forceinline__ float sigmoidf_(float v) { return 1.0f / (1.0f + __expf(-v)); }

__device__ __forceinline__ void red4(float* addr, float4 v) {
    asm volatile("red.global.v4.f32.add [%0], {%1,%2,%3,%4};"
                 :: "l"(__cvta_generic_to_global(addr)),
                    "f"(v.x), "f"(v.y), "f"(v.z), "f"(v.w)
                 : "memory");
}

// ---------------- zero init (must run every replay) ------------------------
__global__ void k_zero(int n) {
    long i = (long)blockIdx.x * blockDim.x + threadIdx.x;   // float4 index
    float4 z = make_float4(0.f, 0.f, 0.f, 0.f);
    long n128 = (long)n * 32;   // float4 count for 128-wide arrays
    if (i < n128) {
        ((float4*)g_dennum)[i] = z;
        ((float4*)g_aggr)[i]   = z;
    }
    if (i < 32) { ((float4*)g_sum)[i] = z; ((float4*)g_sumsq)[i] = z; }
}

// ---------------- per-node precompute: p = exp(msg), q = p*msg -------------
__global__ void k_prep(const float* __restrict__ x, int n) {
    int tid = blockIdx.x * blockDim.x + threadIdx.x;
    if (tid >= n * 16) return;
    int nd = tid >> 4, c = tid & 15;
    float4 v = ((const float4*)x)[(size_t)nd * 16 + c];
    float m0 = fmaxf(v.x, 0.f) + 1e-7f;
    float m1 = fmaxf(v.y, 0.f) + 1e-7f;
    float m2 = fmaxf(v.z, 0.f) + 1e-7f;
    float m3 = fmaxf(v.w, 0.f) + 1e-7f;
    float p0 = expf(m0), p1 = expf(m1), p2 = expf(m2), p3 = expf(m3);
    float4* row = (float4*)&g_pq[(size_t)nd * 128];
    row[c]      = make_float4(p0, p1, p2, p3);
    row[16 + c] = make_float4(p0 * m0, p1 * m1, p2 * m2, p3 * m3);
}

// ---------------- GENConv edge reduce: dennum[dst] += pq[src] --------------
__global__ void k_edge_gen(const int* __restrict__ src, const int* __restrict__ dst, int E) {
    int tid = blockIdx.x * blockDim.x + threadIdx.x;
    if (tid >= E * 32) return;
    int e = tid >> 5, c = tid & 31;
    int s = src[e], d = dst[e];
    float4 v = ((const float4*)g_pq)[(size_t)s * 32 + c];
    red4(&g_dennum[(size_t)d * 128 + c * 4], v);
}

// ---------------- GEMM1: (num/den + x) @ W1 + b1 -> h1 [N,128] -------------
__global__ void __launch_bounds__(128) k_gemm1(const float* __restrict__ x,
                                               const float* __restrict__ W1,
                                               const float* __restrict__ b1, int n) {
    __shared__ float Ws[64 * 128];
    __shared__ float bs[128];
    for (int i = threadIdx.x; i < 64 * 128; i += 128) Ws[i] = W1[i];
    if (threadIdx.x < 128) bs[threadIdx.x] = b1[threadIdx.x];
    __syncthreads();
    int nd = blockIdx.x * 128 + threadIdx.x;
    if (nd >= n) return;
    float in[64];
    const float4* de4 = (const float4*)&g_dennum[(size_t)nd * 128];
    const float4* nu4 = de4 + 16;
    const float4* x4  = (const float4*)&x[(size_t)nd * 64];
#pragma unroll
    for (int i = 0; i < 16; i++) {
        float4 nu = nu4[i], de = de4[i], xv = x4[i];
        in[4 * i + 0] = nu.x / (de.x > 0.f ? de.x : 1.f) + xv.x;
        in[4 * i + 1] = nu.y / (de.y > 0.f ? de.y : 1.f) + xv.y;
        in[4 * i + 2] = nu.z / (de.z > 0.f ? de.z : 1.f) + xv.z;
        in[4 * i + 3] = nu.w / (de.w > 0.f ? de.w : 1.f) + xv.w;
    }
    for (int c = 0; c < 128; c += 8) {
        float acc[8];
#pragma unroll
        for (int j = 0; j < 8; j++) acc[j] = bs[c + j];
#pragma unroll
        for (int k = 0; k < 64; k++) {
            float a = in[k];
            float4 w0 = *(const float4*)&Ws[k * 128 + c];
            float4 w1 = *(const float4*)&Ws[k * 128 + c + 4];
            acc[0] += a * w0.x; acc[1] += a * w0.y; acc[2] += a * w0.z; acc[3] += a * w0.w;
            acc[4] += a * w1.x; acc[5] += a * w1.y; acc[6] += a * w1.z; acc[7] += a * w1.w;
        }
        float4* o = (float4*)&g_h1[(size_t)nd * 128 + c];
        o[0] = make_float4(acc[0], acc[1], acc[2], acc[3]);
        o[1] = make_float4(acc[4], acc[5], acc[6], acc[7]);
    }
}

// ---------------- BatchNorm column stats -----------------------------------
__global__ void k_colstats(int n) {
    int f = threadIdx.x;   // 128 threads
    int start = blockIdx.x * 256;
    int end = min(n, start + 256);
    float s = 0.f, s2 = 0.f;
    for (int nd = start; nd < end; nd++) {
        float v = g_h1[(size_t)nd * 128 + f];
        s += v; s2 += v * v;
    }
    atomicAdd(&g_sum[f], s);
    atomicAdd(&g_sumsq[f], s2);
}

__global__ void k_stats_final(int n) {
    int f = threadIdx.x;
    float mu = g_sum[f] / (float)n;
    float var = g_sumsq[f] / (float)n - mu * mu;
    g_mu[f] = mu;
    g_istd[f] = rsqrtf(var + 1e-5f);
}

// ---------------- GEMM2: relu(BN(h1)) @ W2 + b2 ; build x2 = sigmoid(cat) ---
__global__ void __launch_bounds__(128) k_gemm2(const float* __restrict__ x,
                                               const float* __restrict__ gamma,
                                               const float* __restrict__ beta,
                                               const float* __restrict__ W2,
                                               const float* __restrict__ b2, int n) {
    __shared__ float Ws[128 * 64];
    __shared__ float sg[128], sb[128], smu[128], sis[128], sb2[64];
    for (int i = threadIdx.x; i < 128 * 64; i += 128) Ws[i] = W2[i];
    if (threadIdx.x < 128) {
        sg[threadIdx.x] = gamma[threadIdx.x];
        sb[threadIdx.x] = beta[threadIdx.x];
        smu[threadIdx.x] = g_mu[threadIdx.x];
        sis[threadIdx.x] = g_istd[threadIdx.x];
    }
    if (threadIdx.x < 64) sb2[threadIdx.x] = b2[threadIdx.x];
    __syncthreads();
    int nd = blockIdx.x * 128 + threadIdx.x;
    if (nd >= n) return;
    float hn[128];
#pragma unroll
    for (int k = 0; k < 128; k++) {
        float v = g_h1[(size_t)nd * 128 + k];
        v = (v - smu[k]) * sis[k] * sg[k] + sb[k];
        hn[k] = fmaxf(v, 0.f);
    }
    const float4* x4 = (const float4*)&x[(size_t)nd * 64];
#pragma unroll
    for (int i = 0; i < 16; i++) {
        float4 xv = x4[i];
        float4 o = make_float4(sigmoidf_(xv.x), sigmoidf_(xv.y), sigmoidf_(xv.z), sigmoidf_(xv.w));
        ((float4*)&g_x2[(size_t)nd * 128])[i] = o;
    }
    for (int c = 0; c < 64; c += 8) {
        float acc[8];
#pragma unroll
        for (int j = 0; j < 8; j++) acc[j] = sb2[c + j];
#pragma unroll
        for (int k = 0; k < 128; k++) {
            float a = hn[k];
            float4 w0 = *(const float4*)&Ws[k * 64 + c];
            float4 w1 = *(const float4*)&Ws[k * 64 + c + 4];
            acc[0] += a * w0.x; acc[1] += a * w0.y; acc[2] += a * w0.z; acc[3] += a * w0.w;
            acc[4] += a * w1.x; acc[5] += a * w1.y; acc[6] += a * w1.z; acc[7] += a * w1.w;
        }
#pragma unroll
        for (int j = 0; j < 8; j++)
            g_x2[(size_t)nd * 128 + 64 + c + j] = sigmoidf_(acc[j]);
    }
}

// ---------------- GEMM3: xp = relu(x2 @ Wp + bp) ----------------------------
__global__ void __launch_bounds__(128) k_gemm3(const float* __restrict__ Wp,
                                               const float* __restrict__ bp, int n) {
    __shared__ float Ws[128 * 64];
    __shared__ float bs[128];
    if (threadIdx.x < 128) bs[threadIdx.x] = bp[threadIdx.x];
    int nd = blockIdx.x * 128 + threadIdx.x;
    bool act = nd < n;
    float row[128];
    if (act) {
#pragma unroll
        for (int i = 0; i < 32; i++) {
            float4 v = ((const float4*)&g_x2[(size_t)nd * 128])[i];
            row[4 * i + 0] = v.x; row[4 * i + 1] = v.y; row[4 * i + 2] = v.z; row[4 * i + 3] = v.w;
        }
    }
    for (int half = 0; half < 2; half++) {
        __syncthreads();
        for (int i = threadIdx.x; i < 128 * 64; i += 128) {
            int k = i >> 6, cc = i & 63;
            Ws[i] = Wp[k * 128 + half * 64 + cc];
        }
        __syncthreads();
        if (act) {
            for (int c = 0; c < 64; c += 8) {
                float acc[8];
#pragma unroll
                for (int j = 0; j < 8; j++) acc[j] = bs[half * 64 + c + j];
#pragma unroll
                for (int k = 0; k < 128; k++) {
                    float a = row[k];
                    float4 w0 = *(const float4*)&Ws[k * 64 + c];
                    float4 w1 = *(const float4*)&Ws[k * 64 + c + 4];
                    acc[0] += a * w0.x; acc[1] += a * w0.y; acc[2] += a * w0.z; acc[3] += a * w0.w;
                    acc[4] += a * w1.x; acc[5] += a * w1.y; acc[6] += a * w1.z; acc[7] += a * w1.w;
                }
                float4* o = (float4*)&g_xp[(size_t)nd * 128 + half * 64 + c];
                o[0] = make_float4(fmaxf(acc[0], 0.f), fmaxf(acc[1], 0.f), fmaxf(acc[2], 0.f), fmaxf(acc[3], 0.f));
                o[1] = make_float4(fmaxf(acc[4], 0.f), fmaxf(acc[5], 0.f), fmaxf(acc[6], 0.f), fmaxf(acc[7], 0.f));
            }
        }
    }
}

// ---------------- SAGE edge reduce: aggr[dst] += xp[src] -------------------
__global__ void k_edge_sage(const int* __restrict__ src, const int* __restrict__ dst, int E) {
    int tid = blockIdx.x * blockDim.x + threadIdx.x;
    if (tid >= E * 32) return;
    int e = tid >> 5, c = tid & 31;
    int s = src[e], d = dst[e];
    float4 v = ((const float4*)g_xp)[(size_t)s * 32 + c];
    red4(&g_aggr[(size_t)d * 128 + c * 4], v);
}

// ---------------- GEMM4a: o2 = aggr @ Wl + bl -------------------------------
__global__ void __launch_bounds__(128) k_gemm4a(const float* __restrict__ Wl,
                                                const float* __restrict__ bl, int n) {
    __shared__ float Ws[128 * 64];
    __shared__ float bs[64];
    for (int i = threadIdx.x; i < 128 * 64; i += 128) Ws[i] = Wl[i];
    if (threadIdx.x < 64) bs[threadIdx.x] = bl[threadIdx.x];
    __syncthreads();
    int nd = blockIdx.x * 128 + threadIdx.x;
    if (nd >= n) return;
    float row[128];
#pragma unroll
    for (int i = 0; i < 32; i++) {
        float4 v = ((const float4*)&g_aggr[(size_t)nd * 128])[i];
        row[4 * i + 0] = v.x; row[4 * i + 1] = v.y; row[4 * i + 2] = v.z; row[4 * i + 3] = v.w;
    }
    for (int c = 0; c < 64; c += 8) {
        float acc[8];
#pragma unroll
        for (int j = 0; j < 8; j++) acc[j] = bs[c + j];
#pragma unroll
        for (int k = 0; k < 128; k++) {
            float a = row[k];
            float4 w0 = *(const float4*)&Ws[k * 64 + c];
            float4 w1 = *(const float4*)&Ws[k * 64 + c + 4];
            acc[0] += a * w0.x; acc[1] += a * w0.y; acc[2] += a * w0.z; acc[3] += a * w0.w;
            acc[4] += a * w1.x; acc[5] += a * w1.y; acc[6] += a * w1.z; acc[7] += a * w1.w;
        }
        float4* o = (float4*)&g_o2[(size_t)nd * 64 + c];
        o[0] = make_float4(acc[0], acc[1], acc[2], acc[3]);
        o[1] = make_float4(acc[4], acc[5], acc[6], acc[7]);
    }
}

// ---------------- GEMM4b: out2 = sigmoid(o2 + x2 @ Wr); fc; outputs --------
__global__ void __launch_bounds__(128) k_gemm4b(const float* __restrict__ Wr,
                                                const float* __restrict__ Wf,
                                                const float* __restrict__ bf,
                                                float* __restrict__ out,
                                                int n, int write_logits) {
    __shared__ float Ws[128 * 64];
    __shared__ float wf[64];
    for (int i = threadIdx.x; i < 128 * 64; i += 128) Ws[i] = Wr[i];
    if (threadIdx.x < 64) wf[threadIdx.x] = Wf[threadIdx.x];
    __syncthreads();
    int nd = blockIdx.x * 128 + threadIdx.x;
    if (nd >= n) return;
    float row[128];
#pragma unroll
    for (int i = 0; i < 32; i++) {
        float4 v = ((const float4*)&g_x2[(size_t)nd * 128])[i];
        row[4 * i + 0] = v.x; row[4 * i + 1] = v.y; row[4 * i + 2] = v.z; row[4 * i + 3] = v.w;
    }
    float logit = bf[0];
    for (int c = 0; c < 64; c += 8) {
        float acc[8];
        float4 a0 = ((const float4*)&g_o2[(size_t)nd * 64 + c])[0];
        float4 a1 = ((const float4*)&g_o2[(size_t)nd * 64 + c])[1];
        acc[0] = a0.x; acc[1] = a0.y; acc[2] = a0.z; acc[3] = a0.w;
        acc[4] = a1.x; acc[5] = a1.y; acc[6] = a1.z; acc[7] = a1.w;
#pragma unroll
        for (int k = 0; k < 128; k++) {
            float a = row[k];
            float4 w0 = *(const float4*)&Ws[k * 64 + c];
            float4 w1 = *(const float4*)&Ws[k * 64 + c + 4];
            acc[0] += a * w0.x; acc[1] += a * w0.y; acc[2] += a * w0.z; acc[3] += a * w0.w;
            acc[4] += a * w1.x; acc[5] += a * w1.y; acc[6] += a * w1.z; acc[7] += a * w1.w;
        }
#pragma unroll
        for (int j = 0; j < 8; j++) {
            float s = sigmoidf_(acc[j]);
            logit += s * wf[c + j];
        }
    }
    out[nd] = sigmoidf_(logit);                  // probs
    if (write_logits) out[n + nd] = logit;       // logits
}

// ---------------- launch ----------------------------------------------------
extern "C" void kernel_launch(void* const* d_in, const int* in_sizes, int n_in,
                              void* d_out, int out_size) {
    const float* x   = (const float*)d_in[0];
    const int*   ei  = (const int*)d_in[1];
    const float* W1  = (const float*)d_in[2];
    const float* b1  = (const float*)d_in[3];
    const float* gamma = (const float*)d_in[4];
    const float* beta  = (const float*)d_in[5];
    const float* W2  = (const float*)d_in[6];
    const float* b2  = (const float*)d_in[7];
    const float* Wp  = (const float*)d_in[8];
    const float* bp  = (const float*)d_in[9];
    const float* Wl  = (const float*)d_in[10];
    const float* bl  = (const float*)d_in[11];
    const float* Wr  = (const float*)d_in[12];
    const float* Wf  = (const float*)d_in[13];
    const float* bf  = (const float*)d_in[14];
    float* out = (float*)d_out;

    int n = in_sizes[0] / 64;
    int E = in_sizes[1] / 2;
    const int* src = ei;
    const int* dst = ei + E;
    int write_logits = (out_size >= 2 * n) ? 1 : 0;

    {
        long tot4 = (long)n * 32;
        k_zero<<<(int)((tot4 + 255) / 256), 256>>>(n);
    }
    k_prep<<<(n * 16 + 255) / 256, 256>>>(x, n);
    {
        long t = (long)E * 32;
        k_edge_gen<<<(int)((t + 255) / 256), 256>>>(src, dst, E);
    }
    int nb = (n + 127) / 128;
    k_gemm1<<<nb, 128>>>(x, W1, b1, n);
    k_colstats<<<(n + 255) / 256, 128>>>(n);
    k_stats_final<<<1, 128>>>(n);
    k_gemm2<<<nb, 128>>>(x, gamma, beta, W2, b2, n);
    k_gemm3<<<nb, 128>>>(Wp, bp, n);
    {
        long t = (long)E * 32;
        k_edge_sage<<<(int)((t + 255) / 256), 256>>>(src, dst, E);
    }
    k_gemm4a<<<nb, 128>>>(Wl, bl, n);
    k_gemm4b<<<nb, 128>>>(Wr, Wf, bf, out, n, write_logits);
}

// round 4
// speedup vs baseline: 1.7266x; 1.0125x over previous
#include <cuda_runtime.h>
#include <math.h>

#define NN 50000
#define EE 800000

// ---------------- scratch (device globals; no allocation allowed) ----------
__device__ float g_pq    [NN * 128];   // p=exp(msg) [0..63], q=p*msg [64..127]
__device__ float g_dennum[NN * 128];   // den [0..63], num [64..127]
__device__ float g_h1    [NN * 128];
__device__ float g_x2    [NN * 128];
__device__ float g_xp    [NN * 128];
__device__ float g_aggr  [NN * 128];
__device__ float g_o2    [NN * 64];
__device__ float g_sum[128], g_sumsq[128], g_mu[128], g_istd[128];

__device__ __forceinline__ float sigmoidf_(float v) { return 1.0f / (1.0f + __expf(-v)); }

__device__ __forceinline__ void red4(float* addr, float4 v) {
    asm volatile("red.global.v4.f32.add [%0], {%1,%2,%3,%4};"
                 :: "l"(__cvta_generic_to_global(addr)),
                    "f"(v.x), "f"(v.y), "f"(v.z), "f"(v.w)
                 : "memory");
}

#define AT_S 68   // transposed A tile row stride (64 nodes + 4 pad floats)

// ---------------- zero init (every replay) ---------------------------------
__global__ void k_zero(int n) {
    long i = (long)blockIdx.x * blockDim.x + threadIdx.x;
    float4 z = make_float4(0.f, 0.f, 0.f, 0.f);
    long n128 = (long)n * 32;
    if (i < n128) {
        ((float4*)g_dennum)[i] = z;
        ((float4*)g_aggr)[i]   = z;
    }
    if (i < 32) { ((float4*)g_sum)[i] = z; ((float4*)g_sumsq)[i] = z; }
}

// ---------------- per-node precompute: p, q, and sigmoid(x) ----------------
__global__ void k_prep(const float* __restrict__ x, int n) {
    int tid = blockIdx.x * blockDim.x + threadIdx.x;
    if (tid >= n * 16) return;
    int nd = tid >> 4, c = tid & 15;
    float4 v = ((const float4*)x)[(size_t)nd * 16 + c];
    float m0 = fmaxf(v.x, 0.f) + 1e-7f;
    float m1 = fmaxf(v.y, 0.f) + 1e-7f;
    float m2 = fmaxf(v.z, 0.f) + 1e-7f;
    float m3 = fmaxf(v.w, 0.f) + 1e-7f;
    float p0 = expf(m0), p1 = expf(m1), p2 = expf(m2), p3 = expf(m3);
    float4* row = (float4*)&g_pq[(size_t)nd * 128];
    row[c]      = make_float4(p0, p1, p2, p3);
    row[16 + c] = make_float4(p0 * m0, p1 * m1, p2 * m2, p3 * m3);
    // x2 first half = sigmoid(x)
    ((float4*)&g_x2[(size_t)nd * 128])[c] =
        make_float4(sigmoidf_(v.x), sigmoidf_(v.y), sigmoidf_(v.z), sigmoidf_(v.w));
}

// ---------------- GENConv edge reduce ---------------------------------------
__global__ void k_edge_gen(const int* __restrict__ src, const int* __restrict__ dst, int E) {
    int tid = blockIdx.x * blockDim.x + threadIdx.x;
    if (tid >= E * 32) return;
    int e = tid >> 5, c = tid & 31;
    int s = src[e], d = dst[e];
    float4 v = ((const float4*)g_pq)[(size_t)s * 32 + c];
    red4(&g_dennum[(size_t)d * 128 + c * 4], v);
}

// ============ tiled GEMM bodies =============================================
// Block covers 64 nodes. Thread tile: 4 nodes x 8 cols.
// A^T tile in smem [Cin][AT_S]; W tile in smem [Cin][Cout].

#define MAINLOOP(CIN, COUT, CGMASK, NGSHIFT)                                    \
    int cg = tid & (CGMASK);                                                    \
    int ng = tid >> (NGSHIFT);                                                  \
    float acc[4][8];                                                            \
    _Pragma("unroll")                                                           \
    for (int i = 0; i < 4; i++)                                                 \
        _Pragma("unroll")                                                       \
        for (int j = 0; j < 8; j++) acc[i][j] = 0.f;                            \
    const float* Ap = At + ng * 4;                                              \
    const float* Wp_ = Ws + cg * 8;                                             \
    _Pragma("unroll 8")                                                         \
    for (int k = 0; k < (CIN); k++) {                                           \
        float4 a4 = *(const float4*)&Ap[k * AT_S];                              \
        float4 w0 = *(const float4*)&Wp_[k * (COUT)];                           \
        float4 w1 = *(const float4*)&Wp_[k * (COUT) + 4];                       \
        float av[4] = {a4.x, a4.y, a4.z, a4.w};                                 \
        float wv[8] = {w0.x, w0.y, w0.z, w0.w, w1.x, w1.y, w1.z, w1.w};         \
        _Pragma("unroll")                                                       \
        for (int i = 0; i < 4; i++)                                             \
            _Pragma("unroll")                                                   \
            for (int j = 0; j < 8; j++) acc[i][j] += av[i] * wv[j];             \
    }

// ---------------- GEMM1: (num/den + x) @ W1 + b1 -> h1 [N,128] --------------
__global__ void __launch_bounds__(256) k_gemm1(const float* __restrict__ x,
                                               const float* __restrict__ W1,
                                               const float* __restrict__ b1, int n) {
    extern __shared__ float sm[];
    float* Ws = sm;               // 64*128
    float* At = Ws + 64 * 128;    // 64*AT_S
    float* bs = At + 64 * AT_S;   // 128
    int tid = threadIdx.x;
    for (int i = tid; i < 2048; i += 256) ((float4*)Ws)[i] = ((const float4*)W1)[i];
    if (tid < 128) bs[tid] = b1[tid];
    int base = blockIdx.x * 64;
    for (int i = tid; i < 1024; i += 256) {
        int ndl = i >> 4, c4 = i & 15;
        int nd = base + ndl;
        float4 in4 = make_float4(0.f, 0.f, 0.f, 0.f);
        if (nd < n) {
            float4 de = ((const float4*)&g_dennum[(size_t)nd * 128])[c4];
            float4 nu = ((const float4*)&g_dennum[(size_t)nd * 128])[16 + c4];
            float4 xv = ((const float4*)x)[(size_t)nd * 16 + c4];
            in4.x = nu.x / (de.x > 0.f ? de.x : 1.f) + xv.x;
            in4.y = nu.y / (de.y > 0.f ? de.y : 1.f) + xv.y;
            in4.z = nu.z / (de.z > 0.f ? de.z : 1.f) + xv.z;
            in4.w = nu.w / (de.w > 0.f ? de.w : 1.f) + xv.w;
        }
        int k0 = c4 * 4;
        At[(k0 + 0) * AT_S + ndl] = in4.x;
        At[(k0 + 1) * AT_S + ndl] = in4.y;
        At[(k0 + 2) * AT_S + ndl] = in4.z;
        At[(k0 + 3) * AT_S + ndl] = in4.w;
    }
    __syncthreads();
    {
        MAINLOOP(64, 128, 15, 4)
#pragma unroll
        for (int i = 0; i < 4; i++) {
            int nd = base + ng * 4 + i;
            if (nd >= n) break;
            float4 o0 = make_float4(acc[i][0] + bs[cg * 8 + 0], acc[i][1] + bs[cg * 8 + 1],
                                    acc[i][2] + bs[cg * 8 + 2], acc[i][3] + bs[cg * 8 + 3]);
            float4 o1 = make_float4(acc[i][4] + bs[cg * 8 + 4], acc[i][5] + bs[cg * 8 + 5],
                                    acc[i][6] + bs[cg * 8 + 6], acc[i][7] + bs[cg * 8 + 7]);
            float4* o = (float4*)&g_h1[(size_t)nd * 128 + cg * 8];
            o[0] = o0; o[1] = o1;
        }
    }
}

// ---------------- BatchNorm column stats ------------------------------------
__global__ void k_colstats(int n) {
    int f = threadIdx.x;
    int start = blockIdx.x * 256;
    int end = min(n, start + 256);
    float s = 0.f, s2 = 0.f;
    for (int nd = start; nd < end; nd++) {
        float v = g_h1[(size_t)nd * 128 + f];
        s += v; s2 += v * v;
    }
    atomicAdd(&g_sum[f], s);
    atomicAdd(&g_sumsq[f], s2);
}

__global__ void k_stats_final(int n) {
    int f = threadIdx.x;
    float mu = g_sum[f] / (float)n;
    float var = g_sumsq[f] / (float)n - mu * mu;
    g_mu[f] = mu;
    g_istd[f] = rsqrtf(var + 1e-5f);
}

// ---------------- GEMM2: relu(BN(h1)) @ W2 + b2 -> x2[64..127] (sigmoid) ----
__global__ void __launch_bounds__(128) k_gemm2(const float* __restrict__ gamma,
                                               const float* __restrict__ beta,
                                               const float* __restrict__ W2,
                                               const float* __restrict__ b2, int n) {
    extern __shared__ float sm[];
    float* Ws = sm;                 // 128*64
    float* At = Ws + 128 * 64;      // 128*AT_S
    float* prm = At + 128 * AT_S;   // sg,sb,smu,sis : 4*128
    float* bs = prm + 512;          // 64
    int tid = threadIdx.x;
    for (int i = tid; i < 2048; i += 128) ((float4*)Ws)[i] = ((const float4*)W2)[i];
    if (tid < 128) {
        prm[tid]       = gamma[tid];
        prm[128 + tid] = beta[tid];
        prm[256 + tid] = g_mu[tid];
        prm[384 + tid] = g_istd[tid];
    }
    if (tid < 64) bs[tid] = b2[tid];
    __syncthreads();   // params ready before A transform
    int base = blockIdx.x * 64;
    for (int i = tid; i < 2048; i += 128) {
        int ndl = i >> 5, c4 = i & 31;
        int nd = base + ndl;
        float4 v = make_float4(0.f, 0.f, 0.f, 0.f);
        if (nd < n) v = ((const float4*)&g_h1[(size_t)nd * 128])[c4];
        int k0 = c4 * 4;
#pragma unroll
        for (int q = 0; q < 4; q++) {
            float val = (q == 0) ? v.x : (q == 1) ? v.y : (q == 2) ? v.z : v.w;
            int col = k0 + q;
            val = (val - prm[256 + col]) * prm[384 + col] * prm[col] + prm[128 + col];
            At[col * AT_S + ndl] = fmaxf(val, 0.f);
        }
    }
    __syncthreads();
    {
        MAINLOOP(128, 64, 7, 3)
#pragma unroll
        for (int i = 0; i < 4; i++) {
            int nd = base + ng * 4 + i;
            if (nd >= n) break;
            float4 o0 = make_float4(sigmoidf_(acc[i][0] + bs[cg * 8 + 0]),
                                    sigmoidf_(acc[i][1] + bs[cg * 8 + 1]),
                                    sigmoidf_(acc[i][2] + bs[cg * 8 + 2]),
                                    sigmoidf_(acc[i][3] + bs[cg * 8 + 3]));
            float4 o1 = make_float4(sigmoidf_(acc[i][4] + bs[cg * 8 + 4]),
                                    sigmoidf_(acc[i][5] + bs[cg * 8 + 5]),
                                    sigmoidf_(acc[i][6] + bs[cg * 8 + 6]),
                                    sigmoidf_(acc[i][7] + bs[cg * 8 + 7]));
            float4* o = (float4*)&g_x2[(size_t)nd * 128 + 64 + cg * 8];
            o[0] = o0; o[1] = o1;
        }
    }
}

// ---------------- GEMM3: xp = relu(x2 @ Wp + bp)  [N,128] --------------------
__global__ void __launch_bounds__(256) k_gemm3(const float* __restrict__ Wp,
                                               const float* __restrict__ bp, int n) {
    extern __shared__ float sm[];
    float* Ws = sm;                // 128*128
    float* At = Ws + 128 * 128;    // 128*AT_S
    float* bs = At + 128 * AT_S;   // 128
    int tid = threadIdx.x;
    for (int i = tid; i < 4096; i += 256) ((float4*)Ws)[i] = ((const float4*)Wp)[i];
    if (tid < 128) bs[tid] = bp[tid];
    int base = blockIdx.x * 64;
    for (int i = tid; i < 2048; i += 256) {
        int ndl = i >> 5, c4 = i & 31;
        int nd = base + ndl;
        float4 v = make_float4(0.f, 0.f, 0.f, 0.f);
        if (nd < n) v = ((const float4*)&g_x2[(size_t)nd * 128])[c4];
        int k0 = c4 * 4;
        At[(k0 + 0) * AT_S + ndl] = v.x;
        At[(k0 + 1) * AT_S + ndl] = v.y;
        At[(k0 + 2) * AT_S + ndl] = v.z;
        At[(k0 + 3) * AT_S + ndl] = v.w;
    }
    __syncthreads();
    {
        MAINLOOP(128, 128, 15, 4)
#pragma unroll
        for (int i = 0; i < 4; i++) {
            int nd = base + ng * 4 + i;
            if (nd >= n) break;
            float4 o0 = make_float4(fmaxf(acc[i][0] + bs[cg * 8 + 0], 0.f),
                                    fmaxf(acc[i][1] + bs[cg * 8 + 1], 0.f),
                                    fmaxf(acc[i][2] + bs[cg * 8 + 2], 0.f),
                                    fmaxf(acc[i][3] + bs[cg * 8 + 3], 0.f));
            float4 o1 = make_float4(fmaxf(acc[i][4] + bs[cg * 8 + 4], 0.f),
                                    fmaxf(acc[i][5] + bs[cg * 8 + 5], 0.f),
                                    fmaxf(acc[i][6] + bs[cg * 8 + 6], 0.f),
                                    fmaxf(acc[i][7] + bs[cg * 8 + 7], 0.f));
            float4* o = (float4*)&g_xp[(size_t)nd * 128 + cg * 8];
            o[0] = o0; o[1] = o1;
        }
    }
}

// ---------------- SAGE edge reduce ------------------------------------------
__global__ void k_edge_sage(const int* __restrict__ src, const int* __restrict__ dst, int E) {
    int tid = blockIdx.x * blockDim.x + threadIdx.x;
    if (tid >= E * 32) return;
    int e = tid >> 5, c = tid & 31;
    int s = src[e], d = dst[e];
    float4 v = ((const float4*)g_xp)[(size_t)s * 32 + c];
    red4(&g_aggr[(size_t)d * 128 + c * 4], v);
}

// ---------------- GEMM4a: o2 = aggr @ Wl + bl --------------------------------
__global__ void __launch_bounds__(128) k_gemm4a(const float* __restrict__ Wl,
                                                const float* __restrict__ bl, int n) {
    extern __shared__ float sm[];
    float* Ws = sm;               // 128*64
    float* At = Ws + 128 * 64;    // 128*AT_S
    float* bs = At + 128 * AT_S;  // 64
    int tid = threadIdx.x;
    for (int i = tid; i < 2048; i += 128) ((float4*)Ws)[i] = ((const float4*)Wl)[i];
    if (tid < 64) bs[tid] = bl[tid];
    int base = blockIdx.x * 64;
    for (int i = tid; i < 2048; i += 128) {
        int ndl = i >> 5, c4 = i & 31;
        int nd = base + ndl;
        float4 v = make_float4(0.f, 0.f, 0.f, 0.f);
        if (nd < n) v = ((const float4*)&g_aggr[(size_t)nd * 128])[c4];
        int k0 = c4 * 4;
        At[(k0 + 0) * AT_S + ndl] = v.x;
        At[(k0 + 1) * AT_S + ndl] = v.y;
        At[(k0 + 2) * AT_S + ndl] = v.z;
        At[(k0 + 3) * AT_S + ndl] = v.w;
    }
    __syncthreads();
    {
        MAINLOOP(128, 64, 7, 3)
#pragma unroll
        for (int i = 0; i < 4; i++) {
            int nd = base + ng * 4 + i;
            if (nd >= n) break;
            float4 o0 = make_float4(acc[i][0] + bs[cg * 8 + 0], acc[i][1] + bs[cg * 8 + 1],
                                    acc[i][2] + bs[cg * 8 + 2], acc[i][3] + bs[cg * 8 + 3]);
            float4 o1 = make_float4(acc[i][4] + bs[cg * 8 + 4], acc[i][5] + bs[cg * 8 + 5],
                                    acc[i][6] + bs[cg * 8 + 6], acc[i][7] + bs[cg * 8 + 7]);
            float4* o = (float4*)&g_o2[(size_t)nd * 64 + cg * 8];
            o[0] = o0; o[1] = o1;
        }
    }
}

// ---------------- GEMM4b: sigmoid(o2 + x2 @ Wr) @ Wf + bf -> out -------------
__global__ void __launch_bounds__(128) k_gemm4b(const float* __restrict__ Wr,
                                                const float* __restrict__ Wf,
                                                const float* __restrict__ bf,
                                                float* __restrict__ out,
                                                int n, int write_logits) {
    extern __shared__ float sm[];
    float* Ws = sm;               // 128*64
    float* At = Ws + 128 * 64;    // 128*AT_S
    float* wf = At + 128 * AT_S;  // 64
    int tid = threadIdx.x;
    for (int i = tid; i < 2048; i += 128) ((float4*)Ws)[i] = ((const float4*)Wr)[i];
    if (tid < 64) wf[tid] = Wf[tid];
    int base = blockIdx.x * 64;
    for (int i = tid; i < 2048; i += 128) {
        int ndl = i >> 5, c4 = i & 31;
        int nd = base + ndl;
        float4 v = make_float4(0.f, 0.f, 0.f, 0.f);
        if (nd < n) v = ((const float4*)&g_x2[(size_t)nd * 128])[c4];
        int k0 = c4 * 4;
        At[(k0 + 0) * AT_S + ndl] = v.x;
        At[(k0 + 1) * AT_S + ndl] = v.y;
        At[(k0 + 2) * AT_S + ndl] = v.z;
        At[(k0 + 3) * AT_S + ndl] = v.w;
    }
    __syncthreads();
    {
        MAINLOOP(128, 64, 7, 3)
        float bf0 = bf[0];
#pragma unroll
        for (int i = 0; i < 4; i++) {
            int nd = base + ng * 4 + i;
            float lp = 0.f;
            if (nd < n) {
                float4 a0 = ((const float4*)&g_o2[(size_t)nd * 64 + cg * 8])[0];
                float4 a1 = ((const float4*)&g_o2[(size_t)nd * 64 + cg * 8])[1];
                float ov[8] = {a0.x, a0.y, a0.z, a0.w, a1.x, a1.y, a1.z, a1.w};
#pragma unroll
                for (int j = 0; j < 8; j++)
                    lp += sigmoidf_(acc[i][j] + ov[j]) * wf[cg * 8 + j];
            }
            // reduce over 8 col-groups (adjacent lanes)
            lp += __shfl_xor_sync(0xffffffffu, lp, 1);
            lp += __shfl_xor_sync(0xffffffffu, lp, 2);
            lp += __shfl_xor_sync(0xffffffffu, lp, 4);
            if (cg == 0 && nd < n) {
                float logit = lp + bf0;
                out[nd] = sigmoidf_(logit);
                if (write_logits) out[n + nd] = logit;
            }
        }
    }
}

// ---------------- launch ------------------------------------------------------
extern "C" void kernel_launch(void* const* d_in, const int* in_sizes, int n_in,
                              void* d_out, int out_size) {
    const float* x   = (const float*)d_in[0];
    const int*   ei  = (const int*)d_in[1];
    const float* W1  = (const float*)d_in[2];
    const float* b1  = (const float*)d_in[3];
    const float* gamma = (const float*)d_in[4];
    const float* beta  = (const float*)d_in[5];
    const float* W2  = (const float*)d_in[6];
    const float* b2  = (const float*)d_in[7];
    const float* Wp  = (const float*)d_in[8];
    const float* bp  = (const float*)d_in[9];
    const float* Wl  = (const float*)d_in[10];
    const float* bl  = (const float*)d_in[11];
    const float* Wr  = (const float*)d_in[12];
    const float* Wf  = (const float*)d_in[13];
    const float* bf  = (const float*)d_in[14];
    float* out = (float*)d_out;

    int n = in_sizes[0] / 64;
    int E = in_sizes[1] / 2;
    const int* src = ei;
    const int* dst = ei + E;
    int write_logits = (out_size >= 2 * n) ? 1 : 0;

    // dynamic smem sizes (bytes)
    const int S1 = (64 * 128 + 64 * AT_S + 128) * 4;
    const int S2 = (128 * 64 + 128 * AT_S + 512 + 64) * 4;
    const int S3 = (128 * 128 + 128 * AT_S + 128) * 4;
    const int S4a = (128 * 64 + 128 * AT_S + 64) * 4;
    const int S4b = (128 * 64 + 128 * AT_S + 64) * 4;
    cudaFuncSetAttribute(k_gemm1,  cudaFuncAttributeMaxDynamicSharedMemorySize, S1);
    cudaFuncSetAttribute(k_gemm2,  cudaFuncAttributeMaxDynamicSharedMemorySize, S2);
    cudaFuncSetAttribute(k_gemm3,  cudaFuncAttributeMaxDynamicSharedMemorySize, S3);
    cudaFuncSetAttribute(k_gemm4a, cudaFuncAttributeMaxDynamicSharedMemorySize, S4a);
    cudaFuncSetAttribute(k_gemm4b, cudaFuncAttributeMaxDynamicSharedMemorySize, S4b);

    {
        long tot4 = (long)n * 32;
        k_zero<<<(int)((tot4 + 255) / 256), 256>>>(n);
    }
    k_prep<<<(n * 16 + 255) / 256, 256>>>(x, n);
    {
        long t = (long)E * 32;
        k_edge_gen<<<(int)((t + 255) / 256), 256>>>(src, dst, E);
    }
    int nb = (n + 63) / 64;
    k_gemm1<<<nb, 256, S1>>>(x, W1, b1, n);
    k_colstats<<<(n + 255) / 256, 128>>>(n);
    k_stats_final<<<1, 128>>>(n);
    k_gemm2<<<nb, 128, S2>>>(gamma, beta, W2, b2, n);
    k_gemm3<<<nb, 256, S3>>>(Wp, bp, n);
    {
        long t = (long)E * 32;
        k_edge_sage<<<(int)((t + 255) / 256), 256>>>(src, dst, E);
    }
    k_gemm4a<<<nb, 128, S4a>>>(Wl, bl, n);
    k_gemm4b<<<nb, 128, S4b>>>(Wr, Wf, bf, out, n, write_logits);
}

// round 5
// speedup vs baseline: 1.8370x; 1.0639x over previous
#include <cuda_runtime.h>
#include <math.h>

#define NN 50000
#define EE 800000

// ---------------- scratch (device globals) ----------------------------------
__device__ float g_pq    [NN * 128];   // p=exp(msg) [0..63], q=p*msg [64..127]
__device__ float g_dennum[NN * 128];   // den [0..63], num [64..127]
__device__ float g_h1    [NN * 128];
__device__ float g_x2    [NN * 128];
__device__ float g_xp    [NN * 128];
__device__ float g_aggr  [NN * 128];
__device__ float g_o2    [NN * 64];
__device__ float g_sum[128], g_sumsq[128], g_mu[128], g_istd[128];
// CSR
__device__ int g_deg[NN];
__device__ int g_off[NN + 1];
__device__ int g_cur[NN];
__device__ int g_adj[EE];

__device__ __forceinline__ float sigmoidf_(float v) { return 1.0f / (1.0f + __expf(-v)); }

#define AT_S 68   // transposed A tile row stride (64 nodes + 4 pad)

// ---------------- small zero init -------------------------------------------
__global__ void k_zero_small(int n) {
    int i = blockIdx.x * blockDim.x + threadIdx.x;
    if (i < n) g_deg[i] = 0;
    if (i < 128) { g_sum[i] = 0.f; g_sumsq[i] = 0.f; }
}

// ---------------- per-node precompute: p, q, sigmoid(x) ---------------------
__global__ void k_prep(const float* __restrict__ x, int n) {
    int tid = blockIdx.x * blockDim.x + threadIdx.x;
    if (tid >= n * 16) return;
    int nd = tid >> 4, c = tid & 15;
    float4 v = ((const float4*)x)[(size_t)nd * 16 + c];
    float m0 = fmaxf(v.x, 0.f) + 1e-7f;
    float m1 = fmaxf(v.y, 0.f) + 1e-7f;
    float m2 = fmaxf(v.z, 0.f) + 1e-7f;
    float m3 = fmaxf(v.w, 0.f) + 1e-7f;
    float p0 = expf(m0), p1 = expf(m1), p2 = expf(m2), p3 = expf(m3);
    float4* row = (float4*)&g_pq[(size_t)nd * 128];
    row[c]      = make_float4(p0, p1, p2, p3);
    row[16 + c] = make_float4(p0 * m0, p1 * m1, p2 * m2, p3 * m3);
    ((float4*)&g_x2[(size_t)nd * 128])[c] =
        make_float4(sigmoidf_(v.x), sigmoidf_(v.y), sigmoidf_(v.z), sigmoidf_(v.w));
}

// ---------------- CSR build --------------------------------------------------
__global__ void k_hist(const int* __restrict__ dst, int E) {
    int e = blockIdx.x * blockDim.x + threadIdx.x;
    if (e < E) atomicAdd(&g_deg[dst[e]], 1);
}

__global__ void __launch_bounds__(1024) k_scan(int n, int E) {
    __shared__ int part[1024];
    int t = threadIdx.x;
    int chunk = (n + 1023) / 1024;
    int s0 = t * chunk, s1 = min(n, s0 + chunk);
    int s = 0;
    for (int i = s0; i < s1; i++) s += g_deg[i];
    part[t] = s;
    __syncthreads();
    if (t == 0) {
        int run = 0;
        for (int i = 0; i < 1024; i++) { int tmp = part[i]; part[i] = run; run += tmp; }
    }
    __syncthreads();
    int run = part[t];
    for (int i = s0; i < s1; i++) {
        g_off[i] = run; g_cur[i] = run;
        run += g_deg[i];
    }
    if (t == 1023) g_off[n] = E;
}

__global__ void k_scatter(const int* __restrict__ src, const int* __restrict__ dst, int E) {
    int e = blockIdx.x * blockDim.x + threadIdx.x;
    if (e >= E) return;
    int pos = atomicAdd(&g_cur[dst[e]], 1);
    g_adj[pos] = src[e];
}

// ---------------- warp-per-dst gathers (atomic-free) ------------------------
__global__ void k_gather_gen(int n) {
    int w = (blockIdx.x * blockDim.x + threadIdx.x) >> 5;
    int lane = threadIdx.x & 31;
    if (w >= n) return;
    int e = g_off[w], end = g_off[w + 1];
    float4 acc = make_float4(0.f, 0.f, 0.f, 0.f);
    for (; e + 4 <= end; e += 4) {
        int s0 = g_adj[e], s1 = g_adj[e + 1], s2 = g_adj[e + 2], s3 = g_adj[e + 3];
        float4 v0 = ((const float4*)g_pq)[(size_t)s0 * 32 + lane];
        float4 v1 = ((const float4*)g_pq)[(size_t)s1 * 32 + lane];
        float4 v2 = ((const float4*)g_pq)[(size_t)s2 * 32 + lane];
        float4 v3 = ((const float4*)g_pq)[(size_t)s3 * 32 + lane];
        acc.x += v0.x + v1.x + v2.x + v3.x;
        acc.y += v0.y + v1.y + v2.y + v3.y;
        acc.z += v0.z + v1.z + v2.z + v3.z;
        acc.w += v0.w + v1.w + v2.w + v3.w;
    }
    for (; e < end; e++) {
        int s = g_adj[e];
        float4 v = ((const float4*)g_pq)[(size_t)s * 32 + lane];
        acc.x += v.x; acc.y += v.y; acc.z += v.z; acc.w += v.w;
    }
    ((float4*)g_dennum)[(size_t)w * 32 + lane] = acc;
}

__global__ void k_gather_sage(int n) {
    int w = (blockIdx.x * blockDim.x + threadIdx.x) >> 5;
    int lane = threadIdx.x & 31;
    if (w >= n) return;
    int e = g_off[w], end = g_off[w + 1];
    float4 acc = make_float4(0.f, 0.f, 0.f, 0.f);
    for (; e + 4 <= end; e += 4) {
        int s0 = g_adj[e], s1 = g_adj[e + 1], s2 = g_adj[e + 2], s3 = g_adj[e + 3];
        float4 v0 = ((const float4*)g_xp)[(size_t)s0 * 32 + lane];
        float4 v1 = ((const float4*)g_xp)[(size_t)s1 * 32 + lane];
        float4 v2 = ((const float4*)g_xp)[(size_t)s2 * 32 + lane];
        float4 v3 = ((const float4*)g_xp)[(size_t)s3 * 32 + lane];
        acc.x += v0.x + v1.x + v2.x + v3.x;
        acc.y += v0.y + v1.y + v2.y + v3.y;
        acc.z += v0.z + v1.z + v2.z + v3.z;
        acc.w += v0.w + v1.w + v2.w + v3.w;
    }
    for (; e < end; e++) {
        int s = g_adj[e];
        float4 v = ((const float4*)g_xp)[(size_t)s * 32 + lane];
        acc.x += v.x; acc.y += v.y; acc.z += v.z; acc.w += v.w;
    }
    ((float4*)g_aggr)[(size_t)w * 32 + lane] = acc;
}

// ============ tiled GEMM bodies =============================================
#define MAINLOOP(CIN, COUT, CGMASK, NGSHIFT)                                    \
    int cg = tid & (CGMASK);                                                    \
    int ng = tid >> (NGSHIFT);                                                  \
    float acc[4][8];                                                            \
    _Pragma("unroll")                                                           \
    for (int i = 0; i < 4; i++)                                                 \
        _Pragma("unroll")                                                       \
        for (int j = 0; j < 8; j++) acc[i][j] = 0.f;                            \
    const float* Ap = At + ng * 4;                                              \
    const float* Wp_ = Ws + cg * 8;                                             \
    _Pragma("unroll 8")                                                         \
    for (int k = 0; k < (CIN); k++) {                                           \
        float4 a4 = *(const float4*)&Ap[k * AT_S];                              \
        float4 w0 = *(const float4*)&Wp_[k * (COUT)];                           \
        float4 w1 = *(const float4*)&Wp_[k * (COUT) + 4];                       \
        float av[4] = {a4.x, a4.y, a4.z, a4.w};                                 \
        float wv[8] = {w0.x, w0.y, w0.z, w0.w, w1.x, w1.y, w1.z, w1.w};         \
        _Pragma("unroll")                                                       \
        for (int i = 0; i < 4; i++)                                             \
            _Pragma("unroll")                                                   \
            for (int j = 0; j < 8; j++) acc[i][j] += av[i] * wv[j];             \
    }

// ---------------- GEMM1 ------------------------------------------------------
__global__ void __launch_bounds__(256) k_gemm1(const float* __restrict__ x,
                                               const float* __restrict__ W1,
                                               const float* __restrict__ b1, int n) {
    extern __shared__ float sm[];
    float* Ws = sm;
    float* At = Ws + 64 * 128;
    float* bs = At + 64 * AT_S;
    int tid = threadIdx.x;
    for (int i = tid; i < 2048; i += 256) ((float4*)Ws)[i] = ((const float4*)W1)[i];
    if (tid < 128) bs[tid] = b1[tid];
    int base = blockIdx.x * 64;
    for (int i = tid; i < 1024; i += 256) {
        int ndl = i >> 4, c4 = i & 15;
        int nd = base + ndl;
        float4 in4 = make_float4(0.f, 0.f, 0.f, 0.f);
        if (nd < n) {
            float4 de = ((const float4*)&g_dennum[(size_t)nd * 128])[c4];
            float4 nu = ((const float4*)&g_dennum[(size_t)nd * 128])[16 + c4];
            float4 xv = ((const float4*)x)[(size_t)nd * 16 + c4];
            in4.x = nu.x / (de.x > 0.f ? de.x : 1.f) + xv.x;
            in4.y = nu.y / (de.y > 0.f ? de.y : 1.f) + xv.y;
            in4.z = nu.z / (de.z > 0.f ? de.z : 1.f) + xv.z;
            in4.w = nu.w / (de.w > 0.f ? de.w : 1.f) + xv.w;
        }
        int k0 = c4 * 4;
        At[(k0 + 0) * AT_S + ndl] = in4.x;
        At[(k0 + 1) * AT_S + ndl] = in4.y;
        At[(k0 + 2) * AT_S + ndl] = in4.z;
        At[(k0 + 3) * AT_S + ndl] = in4.w;
    }
    __syncthreads();
    {
        MAINLOOP(64, 128, 15, 4)
#pragma unroll
        for (int i = 0; i < 4; i++) {
            int nd = base + ng * 4 + i;
            if (nd >= n) break;
            float4 o0 = make_float4(acc[i][0] + bs[cg * 8 + 0], acc[i][1] + bs[cg * 8 + 1],
                                    acc[i][2] + bs[cg * 8 + 2], acc[i][3] + bs[cg * 8 + 3]);
            float4 o1 = make_float4(acc[i][4] + bs[cg * 8 + 4], acc[i][5] + bs[cg * 8 + 5],
                                    acc[i][6] + bs[cg * 8 + 6], acc[i][7] + bs[cg * 8 + 7]);
            float4* o = (float4*)&g_h1[(size_t)nd * 128 + cg * 8];
            o[0] = o0; o[1] = o1;
        }
    }
}

// ---------------- BatchNorm stats --------------------------------------------
__global__ void k_colstats(int n) {
    int f = threadIdx.x;
    int start = blockIdx.x * 256;
    int end = min(n, start + 256);
    float s = 0.f, s2 = 0.f;
    for (int nd = start; nd < end; nd++) {
        float v = g_h1[(size_t)nd * 128 + f];
        s += v; s2 += v * v;
    }
    atomicAdd(&g_sum[f], s);
    atomicAdd(&g_sumsq[f], s2);
}

__global__ void k_stats_final(int n) {
    int f = threadIdx.x;
    float mu = g_sum[f] / (float)n;
    float var = g_sumsq[f] / (float)n - mu * mu;
    g_mu[f] = mu;
    g_istd[f] = rsqrtf(var + 1e-5f);
}

// ---------------- GEMM2 ------------------------------------------------------
__global__ void __launch_bounds__(128) k_gemm2(const float* __restrict__ gamma,
                                               const float* __restrict__ beta,
                                               const float* __restrict__ W2,
                                               const float* __restrict__ b2, int n) {
    extern __shared__ float sm[];
    float* Ws = sm;
    float* At = Ws + 128 * 64;
    float* prm = At + 128 * AT_S;
    float* bs = prm + 512;
    int tid = threadIdx.x;
    for (int i = tid; i < 2048; i += 128) ((float4*)Ws)[i] = ((const float4*)W2)[i];
    if (tid < 128) {
        prm[tid]       = gamma[tid];
        prm[128 + tid] = beta[tid];
        prm[256 + tid] = g_mu[tid];
        prm[384 + tid] = g_istd[tid];
    }
    if (tid < 64) bs[tid] = b2[tid];
    __syncthreads();
    int base = blockIdx.x * 64;
    for (int i = tid; i < 2048; i += 128) {
        int ndl = i >> 5, c4 = i & 31;
        int nd = base + ndl;
        float4 v = make_float4(0.f, 0.f, 0.f, 0.f);
        if (nd < n) v = ((const float4*)&g_h1[(size_t)nd * 128])[c4];
        int k0 = c4 * 4;
#pragma unroll
        for (int q = 0; q < 4; q++) {
            float val = (q == 0) ? v.x : (q == 1) ? v.y : (q == 2) ? v.z : v.w;
            int col = k0 + q;
            val = (val - prm[256 + col]) * prm[384 + col] * prm[col] + prm[128 + col];
            At[col * AT_S + ndl] = fmaxf(val, 0.f);
        }
    }
    __syncthreads();
    {
        MAINLOOP(128, 64, 7, 3)
#pragma unroll
        for (int i = 0; i < 4; i++) {
            int nd = base + ng * 4 + i;
            if (nd >= n) break;
            float4 o0 = make_float4(sigmoidf_(acc[i][0] + bs[cg * 8 + 0]),
                                    sigmoidf_(acc[i][1] + bs[cg * 8 + 1]),
                                    sigmoidf_(acc[i][2] + bs[cg * 8 + 2]),
                                    sigmoidf_(acc[i][3] + bs[cg * 8 + 3]));
            float4 o1 = make_float4(sigmoidf_(acc[i][4] + bs[cg * 8 + 4]),
                                    sigmoidf_(acc[i][5] + bs[cg * 8 + 5]),
                                    sigmoidf_(acc[i][6] + bs[cg * 8 + 6]),
                                    sigmoidf_(acc[i][7] + bs[cg * 8 + 7]));
            float4* o = (float4*)&g_x2[(size_t)nd * 128 + 64 + cg * 8];
            o[0] = o0; o[1] = o1;
        }
    }
}

// ---------------- GEMM3 ------------------------------------------------------
__global__ void __launch_bounds__(256) k_gemm3(const float* __restrict__ Wp,
                                               const float* __restrict__ bp, int n) {
    extern __shared__ float sm[];
    float* Ws = sm;
    float* At = Ws + 128 * 128;
    float* bs = At + 128 * AT_S;
    int tid = threadIdx.x;
    for (int i = tid; i < 4096; i += 256) ((float4*)Ws)[i] = ((const float4*)Wp)[i];
    if (tid < 128) bs[tid] = bp[tid];
    int base = blockIdx.x * 64;
    for (int i = tid; i < 2048; i += 256) {
        int ndl = i >> 5, c4 = i & 31;
        int nd = base + ndl;
        float4 v = make_float4(0.f, 0.f, 0.f, 0.f);
        if (nd < n) v = ((const float4*)&g_x2[(size_t)nd * 128])[c4];
        int k0 = c4 * 4;
        At[(k0 + 0) * AT_S + ndl] = v.x;
        At[(k0 + 1) * AT_S + ndl] = v.y;
        At[(k0 + 2) * AT_S + ndl] = v.z;
        At[(k0 + 3) * AT_S + ndl] = v.w;
    }
    __syncthreads();
    {
        MAINLOOP(128, 128, 15, 4)
#pragma unroll
        for (int i = 0; i < 4; i++) {
            int nd = base + ng * 4 + i;
            if (nd >= n) break;
            float4 o0 = make_float4(fmaxf(acc[i][0] + bs[cg * 8 + 0], 0.f),
                                    fmaxf(acc[i][1] + bs[cg * 8 + 1], 0.f),
                                    fmaxf(acc[i][2] + bs[cg * 8 + 2], 0.f),
                                    fmaxf(acc[i][3] + bs[cg * 8 + 3], 0.f));
            float4 o1 = make_float4(fmaxf(acc[i][4] + bs[cg * 8 + 4], 0.f),
                                    fmaxf(acc[i][5] + bs[cg * 8 + 5], 0.f),
                                    fmaxf(acc[i][6] + bs[cg * 8 + 6], 0.f),
                                    fmaxf(acc[i][7] + bs[cg * 8 + 7], 0.f));
            float4* o = (float4*)&g_xp[(size_t)nd * 128 + cg * 8];
            o[0] = o0; o[1] = o1;
        }
    }
}

// ---------------- GEMM4a -----------------------------------------------------
__global__ void __launch_bounds__(128) k_gemm4a(const float* __restrict__ Wl,
                                                const float* __restrict__ bl, int n) {
    extern __shared__ float sm[];
    float* Ws = sm;
    float* At = Ws + 128 * 64;
    float* bs = At + 128 * AT_S;
    int tid = threadIdx.x;
    for (int i = tid; i < 2048; i += 128) ((float4*)Ws)[i] = ((const float4*)Wl)[i];
    if (tid < 64) bs[tid] = bl[tid];
    int base = blockIdx.x * 64;
    for (int i = tid; i < 2048; i += 128) {
        int ndl = i >> 5, c4 = i & 31;
        int nd = base + ndl;
        float4 v = make_float4(0.f, 0.f, 0.f, 0.f);
        if (nd < n) v = ((const float4*)&g_aggr[(size_t)nd * 128])[c4];
        int k0 = c4 * 4;
        At[(k0 + 0) * AT_S + ndl] = v.x;
        At[(k0 + 1) * AT_S + ndl] = v.y;
        At[(k0 + 2) * AT_S + ndl] = v.z;
        At[(k0 + 3) * AT_S + ndl] = v.w;
    }
    __syncthreads();
    {
        MAINLOOP(128, 64, 7, 3)
#pragma unroll
        for (int i = 0; i < 4; i++) {
            int nd = base + ng * 4 + i;
            if (nd >= n) break;
            float4 o0 = make_float4(acc[i][0] + bs[cg * 8 + 0], acc[i][1] + bs[cg * 8 + 1],
                                    acc[i][2] + bs[cg * 8 + 2], acc[i][3] + bs[cg * 8 + 3]);
            float4 o1 = make_float4(acc[i][4] + bs[cg * 8 + 4], acc[i][5] + bs[cg * 8 + 5],
                                    acc[i][6] + bs[cg * 8 + 6], acc[i][7] + bs[cg * 8 + 7]);
            float4* o = (float4*)&g_o2[(size_t)nd * 64 + cg * 8];
            o[0] = o0; o[1] = o1;
        }
    }
}

// ---------------- GEMM4b -----------------------------------------------------
__global__ void __launch_bounds__(128) k_gemm4b(const float* __restrict__ Wr,
                                                const float* __restrict__ Wf,
                                                const float* __restrict__ bf,
                                                float* __restrict__ out,
                                                int n, int write_logits) {
    extern __shared__ float sm[];
    float* Ws = sm;
    float* At = Ws + 128 * 64;
    float* wf = At + 128 * AT_S;
    int tid = threadIdx.x;
    for (int i = tid; i < 2048; i += 128) ((float4*)Ws)[i] = ((const float4*)Wr)[i];
    if (tid < 64) wf[tid] = Wf[tid];
    int base = blockIdx.x * 64;
    for (int i = tid; i < 2048; i += 128) {
        int ndl = i >> 5, c4 = i & 31;
        int nd = base + ndl;
        float4 v = make_float4(0.f, 0.f, 0.f, 0.f);
        if (nd < n) v = ((const float4*)&g_x2[(size_t)nd * 128])[c4];
        int k0 = c4 * 4;
        At[(k0 + 0) * AT_S + ndl] = v.x;
        At[(k0 + 1) * AT_S + ndl] = v.y;
        At[(k0 + 2) * AT_S + ndl] = v.z;
        At[(k0 + 3) * AT_S + ndl] = v.w;
    }
    __syncthreads();
    {
        MAINLOOP(128, 64, 7, 3)
        float bf0 = bf[0];
#pragma unroll
        for (int i = 0; i < 4; i++) {
            int nd = base + ng * 4 + i;
            float lp = 0.f;
            if (nd < n) {
                float4 a0 = ((const float4*)&g_o2[(size_t)nd * 64 + cg * 8])[0];
                float4 a1 = ((const float4*)&g_o2[(size_t)nd * 64 + cg * 8])[1];
                float ov[8] = {a0.x, a0.y, a0.z, a0.w, a1.x, a1.y, a1.z, a1.w};
#pragma unroll
                for (int j = 0; j < 8; j++)
                    lp += sigmoidf_(acc[i][j] + ov[j]) * wf[cg * 8 + j];
            }
            lp += __shfl_xor_sync(0xffffffffu, lp, 1);
            lp += __shfl_xor_sync(0xffffffffu, lp, 2);
            lp += __shfl_xor_sync(0xffffffffu, lp, 4);
            if (cg == 0 && nd < n) {
                float logit = lp + bf0;
                out[nd] = sigmoidf_(logit);
                if (write_logits) out[n + nd] = logit;
            }
        }
    }
}

// ---------------- launch ------------------------------------------------------
extern "C" void kernel_launch(void* const* d_in, const int* in_sizes, int n_in,
                              void* d_out, int out_size) {
    const float* x   = (const float*)d_in[0];
    const int*   ei  = (const int*)d_in[1];
    const float* W1  = (const float*)d_in[2];
    const float* b1  = (const float*)d_in[3];
    const float* gamma = (const float*)d_in[4];
    const float* beta  = (const float*)d_in[5];
    const float* W2  = (const float*)d_in[6];
    const float* b2  = (const float*)d_in[7];
    const float* Wp  = (const float*)d_in[8];
    const float* bp  = (const float*)d_in[9];
    const float* Wl  = (const float*)d_in[10];
    const float* bl  = (const float*)d_in[11];
    const float* Wr  = (const float*)d_in[12];
    const float* Wf  = (const float*)d_in[13];
    const float* bf  = (const float*)d_in[14];
    float* out = (float*)d_out;

    int n = in_sizes[0] / 64;
    int E = in_sizes[1] / 2;
    const int* src = ei;
    const int* dst = ei + E;
    int write_logits = (out_size >= 2 * n) ? 1 : 0;

    const int S1 = (64 * 128 + 64 * AT_S + 128) * 4;
    const int S2 = (128 * 64 + 128 * AT_S + 512 + 64) * 4;
    const int S3 = (128 * 128 + 128 * AT_S + 128) * 4;
    const int S4 = (128 * 64 + 128 * AT_S + 64) * 4;
    cudaFuncSetAttribute(k_gemm1,  cudaFuncAttributeMaxDynamicSharedMemorySize, S1);
    cudaFuncSetAttribute(k_gemm2,  cudaFuncAttributeMaxDynamicSharedMemorySize, S2);
    cudaFuncSetAttribute(k_gemm3,  cudaFuncAttributeMaxDynamicSharedMemorySize, S3);
    cudaFuncSetAttribute(k_gemm4a, cudaFuncAttributeMaxDynamicSharedMemorySize, S4);
    cudaFuncSetAttribute(k_gemm4b, cudaFuncAttributeMaxDynamicSharedMemorySize, S4);

    // CSR build + prep
    k_zero_small<<<(n + 255) / 256, 256>>>(n);
    k_prep<<<(n * 16 + 255) / 256, 256>>>(x, n);
    k_hist<<<(E + 255) / 256, 256>>>(dst, E);
    k_scan<<<1, 1024>>>(n, E);
    k_scatter<<<(E + 255) / 256, 256>>>(src, dst, E);

    int gb = (n * 32 + 255) / 256;   // warp-per-node gathers
    k_gather_gen<<<gb, 256>>>(n);

    int nb = (n + 63) / 64;
    k_gemm1<<<nb, 256, S1>>>(x, W1, b1, n);
    k_colstats<<<(n + 255) / 256, 128>>>(n);
    k_stats_final<<<1, 128>>>(n);
    k_gemm2<<<nb, 128, S2>>>(gamma, beta, W2, b2, n);
    k_gemm3<<<nb, 256, S3>>>(Wp, bp, n);
    k_gather_sage<<<gb, 256>>>(n);
    k_gemm4a<<<nb, 128, S4>>>(Wl, bl, n);
    k_gemm4b<<<nb, 128, S4>>>(Wr, Wf, bf, out, n, write_logits);
}

// round 6
// speedup vs baseline: 1.8608x; 1.0130x over previous
#include <cuda_runtime.h>
#include <math.h>

#define NN 50000
#define EE 800000

// ---------------- scratch (device globals) ----------------------------------
__device__ float g_pq    [NN * 128];   // p=exp(msg) [0..63], q=p*msg [64..127]
__device__ float g_dennum[NN * 128];   // den [0..63], num [64..127]
__device__ float g_h1    [NN * 128];
__device__ float g_x2    [NN * 128];
__device__ float g_xp    [NN * 128];
__device__ float g_aggr  [NN * 128];
__device__ float g_o2    [NN * 64];
__device__ float g_sum[128], g_sumsq[128], g_mu[128], g_istd[128];
// CSR
__device__ int g_deg[NN];
__device__ int g_off[NN + 1];
__device__ int g_cur[NN];
__device__ int g_adj[EE];

__device__ __forceinline__ float sigmoidf_(float v) { return 1.0f / (1.0f + __expf(-v)); }

#define AT_S 68   // transposed A tile row stride (64 nodes + 4 pad)

// ---------------- small zero init -------------------------------------------
__global__ void k_zero_small(int n) {
    int i = blockIdx.x * blockDim.x + threadIdx.x;
    if (i < n) g_deg[i] = 0;
    if (i < 128) { g_sum[i] = 0.f; g_sumsq[i] = 0.f; }
}

// ---------------- per-node precompute: p, q, sigmoid(x) ---------------------
__global__ void k_prep(const float* __restrict__ x, int n) {
    int tid = blockIdx.x * blockDim.x + threadIdx.x;
    if (tid >= n * 16) return;
    int nd = tid >> 4, c = tid & 15;
    float4 v = ((const float4*)x)[(size_t)nd * 16 + c];
    float m0 = fmaxf(v.x, 0.f) + 1e-7f;
    float m1 = fmaxf(v.y, 0.f) + 1e-7f;
    float m2 = fmaxf(v.z, 0.f) + 1e-7f;
    float m3 = fmaxf(v.w, 0.f) + 1e-7f;
    float p0 = expf(m0), p1 = expf(m1), p2 = expf(m2), p3 = expf(m3);
    float4* row = (float4*)&g_pq[(size_t)nd * 128];
    row[c]      = make_float4(p0, p1, p2, p3);
    row[16 + c] = make_float4(p0 * m0, p1 * m1, p2 * m2, p3 * m3);
    ((float4*)&g_x2[(size_t)nd * 128])[c] =
        make_float4(sigmoidf_(v.x), sigmoidf_(v.y), sigmoidf_(v.z), sigmoidf_(v.w));
}

// ---------------- CSR build --------------------------------------------------
__global__ void k_hist(const int* __restrict__ dst, int E) {
    int e = blockIdx.x * blockDim.x + threadIdx.x;
    if (e < E) atomicAdd(&g_deg[dst[e]], 1);
}

// Parallel scan: per-thread chunk sums -> warp shfl scan -> warp0 scans
// 32 warp partials -> add back, then each thread writes its chunk prefix.
__global__ void __launch_bounds__(1024) k_scan(int n, int E) {
    __shared__ int warp_part[32];
    int t = threadIdx.x;
    int lane = t & 31, wid = t >> 5;
    int chunk = (n + 1023) / 1024;
    int s0 = t * chunk, s1 = min(n, s0 + chunk);
    int s = 0;
    for (int i = s0; i < s1; i++) s += g_deg[i];
    // inclusive warp scan of s
    int inc = s;
#pragma unroll
    for (int d = 1; d < 32; d <<= 1) {
        int v = __shfl_up_sync(0xffffffffu, inc, d);
        if (lane >= d) inc += v;
    }
    if (lane == 31) warp_part[wid] = inc;
    __syncthreads();
    if (wid == 0) {
        int w = warp_part[lane];
        int winc = w;
#pragma unroll
        for (int d = 1; d < 32; d <<= 1) {
            int v = __shfl_up_sync(0xffffffffu, winc, d);
            if (lane >= d) winc += v;
        }
        warp_part[lane] = winc - w;   // exclusive
    }
    __syncthreads();
    int run = warp_part[wid] + inc - s;   // exclusive prefix of this thread
    for (int i = s0; i < s1; i++) {
        g_off[i] = run; g_cur[i] = run;
        run += g_deg[i];
    }
    if (t == 1023) g_off[n] = E;
}

__global__ void k_scatter(const int* __restrict__ src, const int* __restrict__ dst, int E) {
    int e = blockIdx.x * blockDim.x + threadIdx.x;
    if (e >= E) return;
    int pos = atomicAdd(&g_cur[dst[e]], 1);
    g_adj[pos] = src[e];
}

// ---------------- warp-per-dst gathers (atomic-free) ------------------------
__global__ void k_gather_gen(int n) {
    int w = (blockIdx.x * blockDim.x + threadIdx.x) >> 5;
    int lane = threadIdx.x & 31;
    if (w >= n) return;
    int e = g_off[w], end = g_off[w + 1];
    float4 acc = make_float4(0.f, 0.f, 0.f, 0.f);
    for (; e + 4 <= end; e += 4) {
        int s0 = g_adj[e], s1 = g_adj[e + 1], s2 = g_adj[e + 2], s3 = g_adj[e + 3];
        float4 v0 = ((const float4*)g_pq)[(size_t)s0 * 32 + lane];
        float4 v1 = ((const float4*)g_pq)[(size_t)s1 * 32 + lane];
        float4 v2 = ((const float4*)g_pq)[(size_t)s2 * 32 + lane];
        float4 v3 = ((const float4*)g_pq)[(size_t)s3 * 32 + lane];
        acc.x += v0.x + v1.x + v2.x + v3.x;
        acc.y += v0.y + v1.y + v2.y + v3.y;
        acc.z += v0.z + v1.z + v2.z + v3.z;
        acc.w += v0.w + v1.w + v2.w + v3.w;
    }
    for (; e < end; e++) {
        int s = g_adj[e];
        float4 v = ((const float4*)g_pq)[(size_t)s * 32 + lane];
        acc.x += v.x; acc.y += v.y; acc.z += v.z; acc.w += v.w;
    }
    ((float4*)g_dennum)[(size_t)w * 32 + lane] = acc;
}

__global__ void k_gather_sage(int n) {
    int w = (blockIdx.x * blockDim.x + threadIdx.x) >> 5;
    int lane = threadIdx.x & 31;
    if (w >= n) return;
    int e = g_off[w], end = g_off[w + 1];
    float4 acc = make_float4(0.f, 0.f, 0.f, 0.f);
    for (; e + 4 <= end; e += 4) {
        int s0 = g_adj[e], s1 = g_adj[e + 1], s2 = g_adj[e + 2], s3 = g_adj[e + 3];
        float4 v0 = ((const float4*)g_xp)[(size_t)s0 * 32 + lane];
        float4 v1 = ((const float4*)g_xp)[(size_t)s1 * 32 + lane];
        float4 v2 = ((const float4*)g_xp)[(size_t)s2 * 32 + lane];
        float4 v3 = ((const float4*)g_xp)[(size_t)s3 * 32 + lane];
        acc.x += v0.x + v1.x + v2.x + v3.x;
        acc.y += v0.y + v1.y + v2.y + v3.y;
        acc.z += v0.z + v1.z + v2.z + v3.z;
        acc.w += v0.w + v1.w + v2.w + v3.w;
    }
    for (; e < end; e++) {
        int s = g_adj[e];
        float4 v = ((const float4*)g_xp)[(size_t)s * 32 + lane];
        acc.x += v.x; acc.y += v.y; acc.z += v.z; acc.w += v.w;
    }
    ((float4*)g_aggr)[(size_t)w * 32 + lane] = acc;
}

// ============ tiled GEMM bodies =============================================
#define MAINLOOP(CIN, COUT, CGMASK, NGSHIFT)                                    \
    int cg = tid & (CGMASK);                                                    \
    int ng = tid >> (NGSHIFT);                                                  \
    float acc[4][8];                                                            \
    _Pragma("unroll")                                                           \
    for (int i = 0; i < 4; i++)                                                 \
        _Pragma("unroll")                                                       \
        for (int j = 0; j < 8; j++) acc[i][j] = 0.f;                            \
    const float* Ap = At + ng * 4;                                              \
    const float* Wp_ = Ws + cg * 8;                                             \
    _Pragma("unroll 8")                                                         \
    for (int k = 0; k < (CIN); k++) {                                           \
        float4 a4 = *(const float4*)&Ap[k * AT_S];                              \
        float4 w0 = *(const float4*)&Wp_[k * (COUT)];                           \
        float4 w1 = *(const float4*)&Wp_[k * (COUT) + 4];                       \
        float av[4] = {a4.x, a4.y, a4.z, a4.w};                                 \
        float wv[8] = {w0.x, w0.y, w0.z, w0.w, w1.x, w1.y, w1.z, w1.w};         \
        _Pragma("unroll")                                                       \
        for (int i = 0; i < 4; i++)                                             \
            _Pragma("unroll")                                                   \
            for (int j = 0; j < 8; j++) acc[i][j] += av[i] * wv[j];             \
    }

// ---------------- GEMM1 ------------------------------------------------------
__global__ void __launch_bounds__(256) k_gemm1(const float* __restrict__ x,
                                               const float* __restrict__ W1,
                                               const float* __restrict__ b1, int n) {
    extern __shared__ float sm[];
    float* Ws = sm;
    float* At = Ws + 64 * 128;
    float* bs = At + 64 * AT_S;
    int tid = threadIdx.x;
    for (int i = tid; i < 2048; i += 256) ((float4*)Ws)[i] = ((const float4*)W1)[i];
    if (tid < 128) bs[tid] = b1[tid];
    int base = blockIdx.x * 64;
    for (int i = tid; i < 1024; i += 256) {
        int ndl = i >> 4, c4 = i & 15;
        int nd = base + ndl;
        float4 in4 = make_float4(0.f, 0.f, 0.f, 0.f);
        if (nd < n) {
            float4 de = ((const float4*)&g_dennum[(size_t)nd * 128])[c4];
            float4 nu = ((const float4*)&g_dennum[(size_t)nd * 128])[16 + c4];
            float4 xv = ((const float4*)x)[(size_t)nd * 16 + c4];
            in4.x = nu.x / (de.x > 0.f ? de.x : 1.f) + xv.x;
            in4.y = nu.y / (de.y > 0.f ? de.y : 1.f) + xv.y;
            in4.z = nu.z / (de.z > 0.f ? de.z : 1.f) + xv.z;
            in4.w = nu.w / (de.w > 0.f ? de.w : 1.f) + xv.w;
        }
        int k0 = c4 * 4;
        At[(k0 + 0) * AT_S + ndl] = in4.x;
        At[(k0 + 1) * AT_S + ndl] = in4.y;
        At[(k0 + 2) * AT_S + ndl] = in4.z;
        At[(k0 + 3) * AT_S + ndl] = in4.w;
    }
    __syncthreads();
    {
        MAINLOOP(64, 128, 15, 4)
#pragma unroll
        for (int i = 0; i < 4; i++) {
            int nd = base + ng * 4 + i;
            if (nd >= n) break;
            float4 o0 = make_float4(acc[i][0] + bs[cg * 8 + 0], acc[i][1] + bs[cg * 8 + 1],
                                    acc[i][2] + bs[cg * 8 + 2], acc[i][3] + bs[cg * 8 + 3]);
            float4 o1 = make_float4(acc[i][4] + bs[cg * 8 + 4], acc[i][5] + bs[cg * 8 + 5],
                                    acc[i][6] + bs[cg * 8 + 6], acc[i][7] + bs[cg * 8 + 7]);
            float4* o = (float4*)&g_h1[(size_t)nd * 128 + cg * 8];
            o[0] = o0; o[1] = o1;
        }
    }
}

// ---------------- BatchNorm stats --------------------------------------------
__global__ void k_colstats(int n) {
    int f = threadIdx.x;
    int start = blockIdx.x * 256;
    int end = min(n, start + 256);
    float s = 0.f, s2 = 0.f;
    for (int nd = start; nd < end; nd++) {
        float v = g_h1[(size_t)nd * 128 + f];
        s += v; s2 += v * v;
    }
    atomicAdd(&g_sum[f], s);
    atomicAdd(&g_sumsq[f], s2);
}

__global__ void k_stats_final(int n) {
    int f = threadIdx.x;
    float mu = g_sum[f] / (float)n;
    float var = g_sumsq[f] / (float)n - mu * mu;
    g_mu[f] = mu;
    g_istd[f] = rsqrtf(var + 1e-5f);
}

// ---------------- GEMM2 ------------------------------------------------------
__global__ void __launch_bounds__(128) k_gemm2(const float* __restrict__ gamma,
                                               const float* __restrict__ beta,
                                               const float* __restrict__ W2,
                                               const float* __restrict__ b2, int n) {
    extern __shared__ float sm[];
    float* Ws = sm;
    float* At = Ws + 128 * 64;
    float* prm = At + 128 * AT_S;
    float* bs = prm + 512;
    int tid = threadIdx.x;
    for (int i = tid; i < 2048; i += 128) ((float4*)Ws)[i] = ((const float4*)W2)[i];
    if (tid < 128) {
        prm[tid]       = gamma[tid];
        prm[128 + tid] = beta[tid];
        prm[256 + tid] = g_mu[tid];
        prm[384 + tid] = g_istd[tid];
    }
    if (tid < 64) bs[tid] = b2[tid];
    __syncthreads();
    int base = blockIdx.x * 64;
    for (int i = tid; i < 2048; i += 128) {
        int ndl = i >> 5, c4 = i & 31;
        int nd = base + ndl;
        float4 v = make_float4(0.f, 0.f, 0.f, 0.f);
        if (nd < n) v = ((const float4*)&g_h1[(size_t)nd * 128])[c4];
        int k0 = c4 * 4;
#pragma unroll
        for (int q = 0; q < 4; q++) {
            float val = (q == 0) ? v.x : (q == 1) ? v.y : (q == 2) ? v.z : v.w;
            int col = k0 + q;
            val = (val - prm[256 + col]) * prm[384 + col] * prm[col] + prm[128 + col];
            At[col * AT_S + ndl] = fmaxf(val, 0.f);
        }
    }
    __syncthreads();
    {
        MAINLOOP(128, 64, 7, 3)
#pragma unroll
        for (int i = 0; i < 4; i++) {
            int nd = base + ng * 4 + i;
            if (nd >= n) break;
            float4 o0 = make_float4(sigmoidf_(acc[i][0] + bs[cg * 8 + 0]),
                                    sigmoidf_(acc[i][1] + bs[cg * 8 + 1]),
                                    sigmoidf_(acc[i][2] + bs[cg * 8 + 2]),
                                    sigmoidf_(acc[i][3] + bs[cg * 8 + 3]));
            float4 o1 = make_float4(sigmoidf_(acc[i][4] + bs[cg * 8 + 4]),
                                    sigmoidf_(acc[i][5] + bs[cg * 8 + 5]),
                                    sigmoidf_(acc[i][6] + bs[cg * 8 + 6]),
                                    sigmoidf_(acc[i][7] + bs[cg * 8 + 7]));
            float4* o = (float4*)&g_x2[(size_t)nd * 128 + 64 + cg * 8];
            o[0] = o0; o[1] = o1;
        }
    }
}

// ---------------- GEMM3 ------------------------------------------------------
__global__ void __launch_bounds__(256) k_gemm3(const float* __restrict__ Wp,
                                               const float* __restrict__ bp, int n) {
    extern __shared__ float sm[];
    float* Ws = sm;
    float* At = Ws + 128 * 128;
    float* bs = At + 128 * AT_S;
    int tid = threadIdx.x;
    for (int i = tid; i < 4096; i += 256) ((float4*)Ws)[i] = ((const float4*)Wp)[i];
    if (tid < 128) bs[tid] = bp[tid];
    int base = blockIdx.x * 64;
    for (int i = tid; i < 2048; i += 256) {
        int ndl = i >> 5, c4 = i & 31;
        int nd = base + ndl;
        float4 v = make_float4(0.f, 0.f, 0.f, 0.f);
        if (nd < n) v = ((const float4*)&g_x2[(size_t)nd * 128])[c4];
        int k0 = c4 * 4;
        At[(k0 + 0) * AT_S + ndl] = v.x;
        At[(k0 + 1) * AT_S + ndl] = v.y;
        At[(k0 + 2) * AT_S + ndl] = v.z;
        At[(k0 + 3) * AT_S + ndl] = v.w;
    }
    __syncthreads();
    {
        MAINLOOP(128, 128, 15, 4)
#pragma unroll
        for (int i = 0; i < 4; i++) {
            int nd = base + ng * 4 + i;
            if (nd >= n) break;
            float4 o0 = make_float4(fmaxf(acc[i][0] + bs[cg * 8 + 0], 0.f),
                                    fmaxf(acc[i][1] + bs[cg * 8 + 1], 0.f),
                                    fmaxf(acc[i][2] + bs[cg * 8 + 2], 0.f),
                                    fmaxf(acc[i][3] + bs[cg * 8 + 3], 0.f));
            float4 o1 = make_float4(fmaxf(acc[i][4] + bs[cg * 8 + 4], 0.f),
                                    fmaxf(acc[i][5] + bs[cg * 8 + 5], 0.f),
                                    fmaxf(acc[i][6] + bs[cg * 8 + 6], 0.f),
                                    fmaxf(acc[i][7] + bs[cg * 8 + 7], 0.f));
            float4* o = (float4*)&g_xp[(size_t)nd * 128 + cg * 8];
            o[0] = o0; o[1] = o1;
        }
    }
}

// ---------------- GEMM4a -----------------------------------------------------
__global__ void __launch_bounds__(128) k_gemm4a(const float* __restrict__ Wl,
                                                const float* __restrict__ bl, int n) {
    extern __shared__ float sm[];
    float* Ws = sm;
    float* At = Ws + 128 * 64;
    float* bs = At + 128 * AT_S;
    int tid = threadIdx.x;
    for (int i = tid; i < 2048; i += 128) ((float4*)Ws)[i] = ((const float4*)Wl)[i];
    if (tid < 64) bs[tid] = bl[tid];
    int base = blockIdx.x * 64;
    for (int i = tid; i < 2048; i += 128) {
        int ndl = i >> 5, c4 = i & 31;
        int nd = base + ndl;
        float4 v = make_float4(0.f, 0.f, 0.f, 0.f);
        if (nd < n) v = ((const float4*)&g_aggr[(size_t)nd * 128])[c4];
        int k0 = c4 * 4;
        At[(k0 + 0) * AT_S + ndl] = v.x;
        At[(k0 + 1) * AT_S + ndl] = v.y;
        At[(k0 + 2) * AT_S + ndl] = v.z;
        At[(k0 + 3) * AT_S + ndl] = v.w;
    }
    __syncthreads();
    {
        MAINLOOP(128, 64, 7, 3)
#pragma unroll
        for (int i = 0; i < 4; i++) {
            int nd = base + ng * 4 + i;
            if (nd >= n) break;
            float4 o0 = make_float4(acc[i][0] + bs[cg * 8 + 0], acc[i][1] + bs[cg * 8 + 1],
                                    acc[i][2] + bs[cg * 8 + 2], acc[i][3] + bs[cg * 8 + 3]);
            float4 o1 = make_float4(acc[i][4] + bs[cg * 8 + 4], acc[i][5] + bs[cg * 8 + 5],
                                    acc[i][6] + bs[cg * 8 + 6], acc[i][7] + bs[cg * 8 + 7]);
            float4* o = (float4*)&g_o2[(size_t)nd * 64 + cg * 8];
            o[0] = o0; o[1] = o1;
        }
    }
}

// ---------------- GEMM4b -----------------------------------------------------
__global__ void __launch_bounds__(128) k_gemm4b(const float* __restrict__ Wr,
                                                const float* __restrict__ Wf,
                                                const float* __restrict__ bf,
                                                float* __restrict__ out,
                                                int n, int write_logits) {
    extern __shared__ float sm[];
    float* Ws = sm;
    float* At = Ws + 128 * 64;
    float* wf = At + 128 * AT_S;
    int tid = threadIdx.x;
    for (int i = tid; i < 2048; i += 128) ((float4*)Ws)[i] = ((const float4*)Wr)[i];
    if (tid < 64) wf[tid] = Wf[tid];
    int base = blockIdx.x * 64;
    for (int i = tid; i < 2048; i += 128) {
        int ndl = i >> 5, c4 = i & 31;
        int nd = base + ndl;
        float4 v = make_float4(0.f, 0.f, 0.f, 0.f);
        if (nd < n) v = ((const float4*)&g_x2[(size_t)nd * 128])[c4];
        int k0 = c4 * 4;
        At[(k0 + 0) * AT_S + ndl] = v.x;
        At[(k0 + 1) * AT_S + ndl] = v.y;
        At[(k0 + 2) * AT_S + ndl] = v.z;
        At[(k0 + 3) * AT_S + ndl] = v.w;
    }
    __syncthreads();
    {
        MAINLOOP(128, 64, 7, 3)
        float bf0 = bf[0];
#pragma unroll
        for (int i = 0; i < 4; i++) {
            int nd = base + ng * 4 + i;
            float lp = 0.f;
            if (nd < n) {
                float4 a0 = ((const float4*)&g_o2[(size_t)nd * 64 + cg * 8])[0];
                float4 a1 = ((const float4*)&g_o2[(size_t)nd * 64 + cg * 8])[1];
                float ov[8] = {a0.x, a0.y, a0.z, a0.w, a1.x, a1.y, a1.z, a1.w};
#pragma unroll
                for (int j = 0; j < 8; j++)
                    lp += sigmoidf_(acc[i][j] + ov[j]) * wf[cg * 8 + j];
            }
            lp += __shfl_xor_sync(0xffffffffu, lp, 1);
            lp += __shfl_xor_sync(0xffffffffu, lp, 2);
            lp += __shfl_xor_sync(0xffffffffu, lp, 4);
            if (cg == 0 && nd < n) {
                float logit = lp + bf0;
                out[nd] = sigmoidf_(logit);
                if (write_logits) out[n + nd] = logit;
            }
        }
    }
}

// ---------------- launch ------------------------------------------------------
extern "C" void kernel_launch(void* const* d_in, const int* in_sizes, int n_in,
                              void* d_out, int out_size) {
    const float* x   = (const float*)d_in[0];
    const int*   ei  = (const int*)d_in[1];
    const float* W1  = (const float*)d_in[2];
    const float* b1  = (const float*)d_in[3];
    const float* gamma = (const float*)d_in[4];
    const float* beta  = (const float*)d_in[5];
    const float* W2  = (const float*)d_in[6];
    const float* b2  = (const float*)d_in[7];
    const float* Wp  = (const float*)d_in[8];
    const float* bp  = (const float*)d_in[9];
    const float* Wl  = (const float*)d_in[10];
    const float* bl  = (const float*)d_in[11];
    const float* Wr  = (const float*)d_in[12];
    const float* Wf  = (const float*)d_in[13];
    const float* bf  = (const float*)d_in[14];
    float* out = (float*)d_out;

    int n = in_sizes[0] / 64;
    int E = in_sizes[1] / 2;
    const int* src = ei;
    const int* dst = ei + E;
    int write_logits = (out_size >= 2 * n) ? 1 : 0;

    const int S1 = (64 * 128 + 64 * AT_S + 128) * 4;
    const int S2 = (128 * 64 + 128 * AT_S + 512 + 64) * 4;
    const int S3 = (128 * 128 + 128 * AT_S + 128) * 4;
    const int S4 = (128 * 64 + 128 * AT_S + 64) * 4;
    cudaFuncSetAttribute(k_gemm1,  cudaFuncAttributeMaxDynamicSharedMemorySize, S1);
    cudaFuncSetAttribute(k_gemm2,  cudaFuncAttributeMaxDynamicSharedMemorySize, S2);
    cudaFuncSetAttribute(k_gemm3,  cudaFuncAttributeMaxDynamicSharedMemorySize, S3);
    cudaFuncSetAttribute(k_gemm4a, cudaFuncAttributeMaxDynamicSharedMemorySize, S4);
    cudaFuncSetAttribute(k_gemm4b, cudaFuncAttributeMaxDynamicSharedMemorySize, S4);

    // CSR build + prep
    k_zero_small<<<(n + 255) / 256, 256>>>(n);
    k_prep<<<(n * 16 + 255) / 256, 256>>>(x, n);
    k_hist<<<(E + 255) / 256, 256>>>(dst, E);
    k_scan<<<1, 1024>>>(n, E);
    k_scatter<<<(E + 255) / 256, 256>>>(src, dst, E);

    int gb = (n * 32 + 255) / 256;   // warp-per-node gathers
    k_gather_gen<<<gb, 256>>>(n);

    int nb = (n + 63) / 64;
    k_gemm1<<<nb, 256, S1>>>(x, W1, b1, n);
    k_colstats<<<(n + 255) / 256, 128>>>(n);
    k_stats_final<<<1, 128>>>(n);
    k_gemm2<<<nb, 128, S2>>>(gamma, beta, W2, b2, n);
    k_gemm3<<<nb, 256, S3>>>(Wp, bp, n);
    k_gather_sage<<<gb, 256>>>(n);
    k_gemm4a<<<nb, 128, S4>>>(Wl, bl, n);
    k_gemm4b<<<nb, 128, S4>>>(Wr, Wf, bf, out, n, write_logits);
}

// round 7
// speedup vs baseline: 2.1760x; 1.1694x over previous
#include <cuda_runtime.h>
#include <math.h>

#define NN 50000
#define EE 800000

// ---------------- scratch (device globals) ----------------------------------
__device__ float g_pq    [NN * 128];
__device__ float g_dennum[NN * 128];
__device__ float g_h1    [NN * 128];
__device__ float g_x2    [NN * 128];
__device__ float g_xp    [NN * 128];
__device__ float g_aggr  [NN * 128];
__device__ float g_o2    [NN * 64];
__device__ float g_sum[128], g_sumsq[128], g_mu[128], g_istd[128];
// CSR
__device__ int g_deg[NN];
__device__ int g_off[NN + 1];
__device__ int g_cur[NN];
__device__ int g_adj[EE];
__device__ int g_bsum[64];
__device__ int g_boff[64];

__device__ __forceinline__ float sigmoidf_(float v) { return 1.0f / (1.0f + __expf(-v)); }

#define AT_S 68

// ---------------- small zero init -------------------------------------------
__global__ void k_zero_small(int n) {
    int i = blockIdx.x * blockDim.x + threadIdx.x;
    if (i < n) g_deg[i] = 0;
    if (i < 128) { g_sum[i] = 0.f; g_sumsq[i] = 0.f; }
}

// ---------------- per-node precompute ----------------------------------------
__global__ void k_prep(const float* __restrict__ x, int n) {
    int tid = blockIdx.x * blockDim.x + threadIdx.x;
    if (tid >= n * 16) return;
    int nd = tid >> 4, c = tid & 15;
    float4 v = ((const float4*)x)[(size_t)nd * 16 + c];
    float m0 = fmaxf(v.x, 0.f) + 1e-7f;
    float m1 = fmaxf(v.y, 0.f) + 1e-7f;
    float m2 = fmaxf(v.z, 0.f) + 1e-7f;
    float m3 = fmaxf(v.w, 0.f) + 1e-7f;
    float p0 = expf(m0), p1 = expf(m1), p2 = expf(m2), p3 = expf(m3);
    float4* row = (float4*)&g_pq[(size_t)nd * 128];
    row[c]      = make_float4(p0, p1, p2, p3);
    row[16 + c] = make_float4(p0 * m0, p1 * m1, p2 * m2, p3 * m3);
    ((float4*)&g_x2[(size_t)nd * 128])[c] =
        make_float4(sigmoidf_(v.x), sigmoidf_(v.y), sigmoidf_(v.z), sigmoidf_(v.w));
}

// ---------------- CSR build ---------------------------------------------------
__global__ void k_hist(const int* __restrict__ dst, int E) {
    int e = blockIdx.x * blockDim.x + threadIdx.x;
    if (e < E) atomicAdd(&g_deg[dst[e]], 1);
}

// Phase A: per-block scan (1024 nodes/block), write in-block exclusive prefix
// to g_off and block total to g_bsum.
__global__ void __launch_bounds__(1024) k_scanA(int n) {
    __shared__ int wp[32];
    int t = threadIdx.x, lane = t & 31, wid = t >> 5;
    int node = blockIdx.x * 1024 + t;
    int d = (node < n) ? g_deg[node] : 0;
    int inc = d;
#pragma unroll
    for (int s = 1; s < 32; s <<= 1) {
        int v = __shfl_up_sync(0xffffffffu, inc, s);
        if (lane >= s) inc += v;
    }
    if (lane == 31) wp[wid] = inc;
    __syncthreads();
    if (wid == 0) {
        int w = wp[lane], winc = w;
#pragma unroll
        for (int s = 1; s < 32; s <<= 1) {
            int v = __shfl_up_sync(0xffffffffu, winc, s);
            if (lane >= s) winc += v;
        }
        wp[lane] = winc - w;   // exclusive warp offsets
    }
    __syncthreads();
    int ex = wp[wid] + inc - d;
    if (node < n) g_off[node] = ex;
    if (t == 1023) g_bsum[blockIdx.x] = ex + d;
}

// Phase B: scan block totals (<= 64 blocks) in one block of 64 threads.
__global__ void k_scanB(int nb, int n, int E) {
    int t = threadIdx.x, lane = t & 31, wid = t >> 5;
    __shared__ int w0tot;
    int v = (t < nb) ? g_bsum[t] : 0;
    int inc = v;
#pragma unroll
    for (int s = 1; s < 32; s <<= 1) {
        int u = __shfl_up_sync(0xffffffffu, inc, s);
        if (lane >= s) inc += u;
    }
    if (t == 31) w0tot = inc;
    __syncthreads();
    int ex = inc - v + (wid ? w0tot : 0);
    if (t < nb) g_boff[t] = ex;
    if (t == 0) g_off[n] = E;
}

// Phase C: add block offsets, mirror to g_cur.
__global__ void __launch_bounds__(1024) k_scanC(int n) {
    int node = blockIdx.x * 1024 + threadIdx.x;
    if (node >= n) return;
    int o = g_off[node] + g_boff[blockIdx.x];
    g_off[node] = o;
    g_cur[node] = o;
}

__global__ void k_scatter(const int* __restrict__ src, const int* __restrict__ dst, int E) {
    int e = blockIdx.x * blockDim.x + threadIdx.x;
    if (e >= E) return;
    int pos = atomicAdd(&g_cur[dst[e]], 1);
    g_adj[pos] = src[e];
}

// ---------------- warp-per-dst gathers ----------------------------------------
__global__ void k_gather_gen(int n) {
    int w = (blockIdx.x * blockDim.x + threadIdx.x) >> 5;
    int lane = threadIdx.x & 31;
    if (w >= n) return;
    int e = g_off[w], end = g_off[w + 1];
    float4 acc = make_float4(0.f, 0.f, 0.f, 0.f);
    for (; e + 4 <= end; e += 4) {
        int s0 = g_adj[e], s1 = g_adj[e + 1], s2 = g_adj[e + 2], s3 = g_adj[e + 3];
        float4 v0 = ((const float4*)g_pq)[(size_t)s0 * 32 + lane];
        float4 v1 = ((const float4*)g_pq)[(size_t)s1 * 32 + lane];
        float4 v2 = ((const float4*)g_pq)[(size_t)s2 * 32 + lane];
        float4 v3 = ((const float4*)g_pq)[(size_t)s3 * 32 + lane];
        acc.x += v0.x + v1.x + v2.x + v3.x;
        acc.y += v0.y + v1.y + v2.y + v3.y;
        acc.z += v0.z + v1.z + v2.z + v3.z;
        acc.w += v0.w + v1.w + v2.w + v3.w;
    }
    for (; e < end; e++) {
        int s = g_adj[e];
        float4 v = ((const float4*)g_pq)[(size_t)s * 32 + lane];
        acc.x += v.x; acc.y += v.y; acc.z += v.z; acc.w += v.w;
    }
    ((float4*)g_dennum)[(size_t)w * 32 + lane] = acc;
}

__global__ void k_gather_sage(int n) {
    int w = (blockIdx.x * blockDim.x + threadIdx.x) >> 5;
    int lane = threadIdx.x & 31;
    if (w >= n) return;
    int e = g_off[w], end = g_off[w + 1];
    float4 acc = make_float4(0.f, 0.f, 0.f, 0.f);
    for (; e + 4 <= end; e += 4) {
        int s0 = g_adj[e], s1 = g_adj[e + 1], s2 = g_adj[e + 2], s3 = g_adj[e + 3];
        float4 v0 = ((const float4*)g_xp)[(size_t)s0 * 32 + lane];
        float4 v1 = ((const float4*)g_xp)[(size_t)s1 * 32 + lane];
        float4 v2 = ((const float4*)g_xp)[(size_t)s2 * 32 + lane];
        float4 v3 = ((const float4*)g_xp)[(size_t)s3 * 32 + lane];
        acc.x += v0.x + v1.x + v2.x + v3.x;
        acc.y += v0.y + v1.y + v2.y + v3.y;
        acc.z += v0.z + v1.z + v2.z + v3.z;
        acc.w += v0.w + v1.w + v2.w + v3.w;
    }
    for (; e < end; e++) {
        int s = g_adj[e];
        float4 v = ((const float4*)g_xp)[(size_t)s * 32 + lane];
        acc.x += v.x; acc.y += v.y; acc.z += v.z; acc.w += v.w;
    }
    ((float4*)g_aggr)[(size_t)w * 32 + lane] = acc;
}

// ============ tiled GEMM bodies =============================================
#define MAINLOOP(CIN, COUT, CGMASK, NGSHIFT)                                    \
    int cg = tid & (CGMASK);                                                    \
    int ng = tid >> (NGSHIFT);                                                  \
    float acc[4][8];                                                            \
    _Pragma("unroll")                                                           \
    for (int i = 0; i < 4; i++)                                                 \
        _Pragma("unroll")                                                       \
        for (int j = 0; j < 8; j++) acc[i][j] = 0.f;                            \
    const float* Ap = At + ng * 4;                                              \
    const float* Wp_ = Ws + cg * 8;                                             \
    _Pragma("unroll 8")                                                         \
    for (int k = 0; k < (CIN); k++) {                                           \
        float4 a4 = *(const float4*)&Ap[k * AT_S];                              \
        float4 w0 = *(const float4*)&Wp_[k * (COUT)];                           \
        float4 w1 = *(const float4*)&Wp_[k * (COUT) + 4];                       \
        float av[4] = {a4.x, a4.y, a4.z, a4.w};                                 \
        float wv[8] = {w0.x, w0.y, w0.z, w0.w, w1.x, w1.y, w1.z, w1.w};         \
        _Pragma("unroll")                                                       \
        for (int i = 0; i < 4; i++)                                             \
            _Pragma("unroll")                                                   \
            for (int j = 0; j < 8; j++) acc[i][j] += av[i] * wv[j];             \
    }

// ---------------- GEMM1 ------------------------------------------------------
__global__ void __launch_bounds__(256) k_gemm1(const float* __restrict__ x,
                                               const float* __restrict__ W1,
                                               const float* __restrict__ b1, int n) {
    extern __shared__ float sm[];
    float* Ws = sm;
    float* At = Ws + 64 * 128;
    float* bs = At + 64 * AT_S;
    int tid = threadIdx.x;
    for (int i = tid; i < 2048; i += 256) ((float4*)Ws)[i] = ((const float4*)W1)[i];
    if (tid < 128) bs[tid] = b1[tid];
    int base = blockIdx.x * 64;
    for (int i = tid; i < 1024; i += 256) {
        int ndl = i >> 4, c4 = i & 15;
        int nd = base + ndl;
        float4 in4 = make_float4(0.f, 0.f, 0.f, 0.f);
        if (nd < n) {
            float4 de = ((const float4*)&g_dennum[(size_t)nd * 128])[c4];
            float4 nu = ((const float4*)&g_dennum[(size_t)nd * 128])[16 + c4];
            float4 xv = ((const float4*)x)[(size_t)nd * 16 + c4];
            in4.x = nu.x / (de.x > 0.f ? de.x : 1.f) + xv.x;
            in4.y = nu.y / (de.y > 0.f ? de.y : 1.f) + xv.y;
            in4.z = nu.z / (de.z > 0.f ? de.z : 1.f) + xv.z;
            in4.w = nu.w / (de.w > 0.f ? de.w : 1.f) + xv.w;
        }
        int k0 = c4 * 4;
        At[(k0 + 0) * AT_S + ndl] = in4.x;
        At[(k0 + 1) * AT_S + ndl] = in4.y;
        At[(k0 + 2) * AT_S + ndl] = in4.z;
        At[(k0 + 3) * AT_S + ndl] = in4.w;
    }
    __syncthreads();
    {
        MAINLOOP(64, 128, 15, 4)
#pragma unroll
        for (int i = 0; i < 4; i++) {
            int nd = base + ng * 4 + i;
            if (nd >= n) break;
            float4 o0 = make_float4(acc[i][0] + bs[cg * 8 + 0], acc[i][1] + bs[cg * 8 + 1],
                                    acc[i][2] + bs[cg * 8 + 2], acc[i][3] + bs[cg * 8 + 3]);
            float4 o1 = make_float4(acc[i][4] + bs[cg * 8 + 4], acc[i][5] + bs[cg * 8 + 5],
                                    acc[i][6] + bs[cg * 8 + 6], acc[i][7] + bs[cg * 8 + 7]);
            float4* o = (float4*)&g_h1[(size_t)nd * 128 + cg * 8];
            o[0] = o0; o[1] = o1;
        }
    }
}

// ---------------- BatchNorm stats ---------------------------------------------
__global__ void k_colstats(int n) {
    int f = threadIdx.x;
    int start = blockIdx.x * 256;
    int end = min(n, start + 256);
    float s = 0.f, s2 = 0.f;
    for (int nd = start; nd < end; nd++) {
        float v = g_h1[(size_t)nd * 128 + f];
        s += v; s2 += v * v;
    }
    atomicAdd(&g_sum[f], s);
    atomicAdd(&g_sumsq[f], s2);
}

__global__ void k_stats_final(int n) {
    int f = threadIdx.x;
    float mu = g_sum[f] / (float)n;
    float var = g_sumsq[f] / (float)n - mu * mu;
    g_mu[f] = mu;
    g_istd[f] = rsqrtf(var + 1e-5f);
}

// ---------------- GEMM2 --------------------------------------------------------
__global__ void __launch_bounds__(128) k_gemm2(const float* __restrict__ gamma,
                                               const float* __restrict__ beta,
                                               const float* __restrict__ W2,
                                               const float* __restrict__ b2, int n) {
    extern __shared__ float sm[];
    float* Ws = sm;
    float* At = Ws + 128 * 64;
    float* prm = At + 128 * AT_S;
    float* bs = prm + 512;
    int tid = threadIdx.x;
    for (int i = tid; i < 2048; i += 128) ((float4*)Ws)[i] = ((const float4*)W2)[i];
    if (tid < 128) {
        prm[tid]       = gamma[tid];
        prm[128 + tid] = beta[tid];
        prm[256 + tid] = g_mu[tid];
        prm[384 + tid] = g_istd[tid];
    }
    if (tid < 64) bs[tid] = b2[tid];
    __syncthreads();
    int base = blockIdx.x * 64;
    for (int i = tid; i < 2048; i += 128) {
        int ndl = i >> 5, c4 = i & 31;
        int nd = base + ndl;
        float4 v = make_float4(0.f, 0.f, 0.f, 0.f);
        if (nd < n) v = ((const float4*)&g_h1[(size_t)nd * 128])[c4];
        int k0 = c4 * 4;
#pragma unroll
        for (int q = 0; q < 4; q++) {
            float val = (q == 0) ? v.x : (q == 1) ? v.y : (q == 2) ? v.z : v.w;
            int col = k0 + q;
            val = (val - prm[256 + col]) * prm[384 + col] * prm[col] + prm[128 + col];
            At[col * AT_S + ndl] = fmaxf(val, 0.f);
        }
    }
    __syncthreads();
    {
        MAINLOOP(128, 64, 7, 3)
#pragma unroll
        for (int i = 0; i < 4; i++) {
            int nd = base + ng * 4 + i;
            if (nd >= n) break;
            float4 o0 = make_float4(sigmoidf_(acc[i][0] + bs[cg * 8 + 0]),
                                    sigmoidf_(acc[i][1] + bs[cg * 8 + 1]),
                                    sigmoidf_(acc[i][2] + bs[cg * 8 + 2]),
                                    sigmoidf_(acc[i][3] + bs[cg * 8 + 3]));
            float4 o1 = make_float4(sigmoidf_(acc[i][4] + bs[cg * 8 + 4]),
                                    sigmoidf_(acc[i][5] + bs[cg * 8 + 5]),
                                    sigmoidf_(acc[i][6] + bs[cg * 8 + 6]),
                                    sigmoidf_(acc[i][7] + bs[cg * 8 + 7]));
            float4* o = (float4*)&g_x2[(size_t)nd * 128 + 64 + cg * 8];
            o[0] = o0; o[1] = o1;
        }
    }
}

// ---------------- GEMM3 --------------------------------------------------------
__global__ void __launch_bounds__(256) k_gemm3(const float* __restrict__ Wp,
                                               const float* __restrict__ bp, int n) {
    extern __shared__ float sm[];
    float* Ws = sm;
    float* At = Ws + 128 * 128;
    float* bs = At + 128 * AT_S;
    int tid = threadIdx.x;
    for (int i = tid; i < 4096; i += 256) ((float4*)Ws)[i] = ((const float4*)Wp)[i];
    if (tid < 128) bs[tid] = bp[tid];
    int base = blockIdx.x * 64;
    for (int i = tid; i < 2048; i += 256) {
        int ndl = i >> 5, c4 = i & 31;
        int nd = base + ndl;
        float4 v = make_float4(0.f, 0.f, 0.f, 0.f);
        if (nd < n) v = ((const float4*)&g_x2[(size_t)nd * 128])[c4];
        int k0 = c4 * 4;
        At[(k0 + 0) * AT_S + ndl] = v.x;
        At[(k0 + 1) * AT_S + ndl] = v.y;
        At[(k0 + 2) * AT_S + ndl] = v.z;
        At[(k0 + 3) * AT_S + ndl] = v.w;
    }
    __syncthreads();
    {
        MAINLOOP(128, 128, 15, 4)
#pragma unroll
        for (int i = 0; i < 4; i++) {
            int nd = base + ng * 4 + i;
            if (nd >= n) break;
            float4 o0 = make_float4(fmaxf(acc[i][0] + bs[cg * 8 + 0], 0.f),
                                    fmaxf(acc[i][1] + bs[cg * 8 + 1], 0.f),
                                    fmaxf(acc[i][2] + bs[cg * 8 + 2], 0.f),
                                    fmaxf(acc[i][3] + bs[cg * 8 + 3], 0.f));
            float4 o1 = make_float4(fmaxf(acc[i][4] + bs[cg * 8 + 4], 0.f),
                                    fmaxf(acc[i][5] + bs[cg * 8 + 5], 0.f),
                                    fmaxf(acc[i][6] + bs[cg * 8 + 6], 0.f),
                                    fmaxf(acc[i][7] + bs[cg * 8 + 7], 0.f));
            float4* o = (float4*)&g_xp[(size_t)nd * 128 + cg * 8];
            o[0] = o0; o[1] = o1;
        }
    }
}

// ---------------- GEMM4a -------------------------------------------------------
__global__ void __launch_bounds__(128) k_gemm4a(const float* __restrict__ Wl,
                                                const float* __restrict__ bl, int n) {
    extern __shared__ float sm[];
    float* Ws = sm;
    float* At = Ws + 128 * 64;
    float* bs = At + 128 * AT_S;
    int tid = threadIdx.x;
    for (int i = tid; i < 2048; i += 128) ((float4*)Ws)[i] = ((const float4*)Wl)[i];
    if (tid < 64) bs[tid] = bl[tid];
    int base = blockIdx.x * 64;
    for (int i = tid; i < 2048; i += 128) {
        int ndl = i >> 5, c4 = i & 31;
        int nd = base + ndl;
        float4 v = make_float4(0.f, 0.f, 0.f, 0.f);
        if (nd < n) v = ((const float4*)&g_aggr[(size_t)nd * 128])[c4];
        int k0 = c4 * 4;
        At[(k0 + 0) * AT_S + ndl] = v.x;
        At[(k0 + 1) * AT_S + ndl] = v.y;
        At[(k0 + 2) * AT_S + ndl] = v.z;
        At[(k0 + 3) * AT_S + ndl] = v.w;
    }
    __syncthreads();
    {
        MAINLOOP(128, 64, 7, 3)
#pragma unroll
        for (int i = 0; i < 4; i++) {
            int nd = base + ng * 4 + i;
            if (nd >= n) break;
            float4 o0 = make_float4(acc[i][0] + bs[cg * 8 + 0], acc[i][1] + bs[cg * 8 + 1],
                                    acc[i][2] + bs[cg * 8 + 2], acc[i][3] + bs[cg * 8 + 3]);
            float4 o1 = make_float4(acc[i][4] + bs[cg * 8 + 4], acc[i][5] + bs[cg * 8 + 5],
                                    acc[i][6] + bs[cg * 8 + 6], acc[i][7] + bs[cg * 8 + 7]);
            float4* o = (float4*)&g_o2[(size_t)nd * 64 + cg * 8];
            o[0] = o0; o[1] = o1;
        }
    }
}

// ---------------- GEMM4b -------------------------------------------------------
__global__ void __launch_bounds__(128) k_gemm4b(const float* __restrict__ Wr,
                                                const float* __restrict__ Wf,
                                                const float* __restrict__ bf,
                                                float* __restrict__ out,
                                                int n, int write_logits) {
    extern __shared__ float sm[];
    float* Ws = sm;
    float* At = Ws + 128 * 64;
    float* wf = At + 128 * AT_S;
    int tid = threadIdx.x;
    for (int i = tid; i < 2048; i += 128) ((float4*)Ws)[i] = ((const float4*)Wr)[i];
    if (tid < 64) wf[tid] = Wf[tid];
    int base = blockIdx.x * 64;
    for (int i = tid; i < 2048; i += 128) {
        int ndl = i >> 5, c4 = i & 31;
        int nd = base + ndl;
        float4 v = make_float4(0.f, 0.f, 0.f, 0.f);
        if (nd < n) v = ((const float4*)&g_x2[(size_t)nd * 128])[c4];
        int k0 = c4 * 4;
        At[(k0 + 0) * AT_S + ndl] = v.x;
        At[(k0 + 1) * AT_S + ndl] = v.y;
        At[(k0 + 2) * AT_S + ndl] = v.z;
        At[(k0 + 3) * AT_S + ndl] = v.w;
    }
    __syncthreads();
    {
        MAINLOOP(128, 64, 7, 3)
        float bf0 = bf[0];
#pragma unroll
        for (int i = 0; i < 4; i++) {
            int nd = base + ng * 4 + i;
            float lp = 0.f;
            if (nd < n) {
                float4 a0 = ((const float4*)&g_o2[(size_t)nd * 64 + cg * 8])[0];
                float4 a1 = ((const float4*)&g_o2[(size_t)nd * 64 + cg * 8])[1];
                float ov[8] = {a0.x, a0.y, a0.z, a0.w, a1.x, a1.y, a1.z, a1.w};
#pragma unroll
                for (int j = 0; j < 8; j++)
                    lp += sigmoidf_(acc[i][j] + ov[j]) * wf[cg * 8 + j];
            }
            lp += __shfl_xor_sync(0xffffffffu, lp, 1);
            lp += __shfl_xor_sync(0xffffffffu, lp, 2);
            lp += __shfl_xor_sync(0xffffffffu, lp, 4);
            if (cg == 0 && nd < n) {
                float logit = lp + bf0;
                out[nd] = sigmoidf_(logit);
                if (write_logits) out[n + nd] = logit;
            }
        }
    }
}

// ---------------- launch --------------------------------------------------------
extern "C" void kernel_launch(void* const* d_in, const int* in_sizes, int n_in,
                              void* d_out, int out_size) {
    const float* x   = (const float*)d_in[0];
    const int*   ei  = (const int*)d_in[1];
    const float* W1  = (const float*)d_in[2];
    const float* b1  = (const float*)d_in[3];
    const float* gamma = (const float*)d_in[4];
    const float* beta  = (const float*)d_in[5];
    const float* W2  = (const float*)d_in[6];
    const float* b2  = (const float*)d_in[7];
    const float* Wp  = (const float*)d_in[8];
    const float* bp  = (const float*)d_in[9];
    const float* Wl  = (const float*)d_in[10];
    const float* bl  = (const float*)d_in[11];
    const float* Wr  = (const float*)d_in[12];
    const float* Wf  = (const float*)d_in[13];
    const float* bf  = (const float*)d_in[14];
    float* out = (float*)d_out;

    int n = in_sizes[0] / 64;
    int E = in_sizes[1] / 2;
    const int* src = ei;
    const int* dst = ei + E;
    int write_logits = (out_size >= 2 * n) ? 1 : 0;

    const int S1 = (64 * 128 + 64 * AT_S + 128) * 4;
    const int S2 = (128 * 64 + 128 * AT_S + 512 + 64) * 4;
    const int S3 = (128 * 128 + 128 * AT_S + 128) * 4;
    const int S4 = (128 * 64 + 128 * AT_S + 64) * 4;
    cudaFuncSetAttribute(k_gemm1,  cudaFuncAttributeMaxDynamicSharedMemorySize, S1);
    cudaFuncSetAttribute(k_gemm2,  cudaFuncAttributeMaxDynamicSharedMemorySize, S2);
    cudaFuncSetAttribute(k_gemm3,  cudaFuncAttributeMaxDynamicSharedMemorySize, S3);
    cudaFuncSetAttribute(k_gemm4a, cudaFuncAttributeMaxDynamicSharedMemorySize, S4);
    cudaFuncSetAttribute(k_gemm4b, cudaFuncAttributeMaxDynamicSharedMemorySize, S4);

    // CSR build + prep
    k_zero_small<<<(n + 255) / 256, 256>>>(n);
    k_prep<<<(n * 16 + 255) / 256, 256>>>(x, n);
    k_hist<<<(E + 255) / 256, 256>>>(dst, E);
    int nb1024 = (n + 1023) / 1024;
    k_scanA<<<nb1024, 1024>>>(n);
    k_scanB<<<1, 64>>>(nb1024, n, E);
    k_scanC<<<nb1024, 1024>>>(n);
    k_scatter<<<(E + 255) / 256, 256>>>(src, dst, E);

    int gb = (n * 32 + 255) / 256;
    k_gather_gen<<<gb, 256>>>(n);

    int nb = (n + 63) / 64;
    k_gemm1<<<nb, 256, S1>>>(x, W1, b1, n);
    k_colstats<<<(n + 255) / 256, 128>>>(n);
    k_stats_final<<<1, 128>>>(n);
    k_gemm2<<<nb, 128, S2>>>(gamma, beta, W2, b2, n);
    k_gemm3<<<nb, 256, S3>>>(Wp, bp, n);
    k_gather_sage<<<gb, 256>>>(n);
    k_gemm4a<<<nb, 128, S4>>>(Wl, bl, n);
    k_gemm4b<<<nb, 128, S4>>>(Wr, Wf, bf, out, n, write_logits);
}

// round 8
// speedup vs baseline: 2.1989x; 1.0105x over previous
#include <cuda_runtime.h>
#include <math.h>

#define NN 50000
#define EE 800000

// ---------------- scratch (device globals) ----------------------------------
__device__ float g_pq    [NN * 128];
__device__ float g_dennum[NN * 128];
__device__ float g_h1    [NN * 128];
__device__ float g_x2    [NN * 128];
__device__ float g_xp    [NN * 128];
__device__ float g_aggr  [NN * 128];
__device__ float g_sum[128], g_sumsq[128], g_mu[128], g_istd[128];
// CSR
__device__ int g_deg[NN];
__device__ int g_off[NN + 1];
__device__ int g_cur[NN];
__device__ int g_adj[EE];
__device__ int g_bsum[64];
__device__ int g_boff[64];

__device__ __forceinline__ float sigmoidf_(float v) { return 1.0f / (1.0f + __expf(-v)); }

#define AT_S 68

// ---------------- small zero init -------------------------------------------
__global__ void k_zero_small(int n) {
    int i = blockIdx.x * blockDim.x + threadIdx.x;
    if (i < n) g_deg[i] = 0;
    if (i < 128) { g_sum[i] = 0.f; g_sumsq[i] = 0.f; }
}

// ---------------- per-node precompute ----------------------------------------
__global__ void k_prep(const float* __restrict__ x, int n) {
    int tid = blockIdx.x * blockDim.x + threadIdx.x;
    if (tid >= n * 16) return;
    int nd = tid >> 4, c = tid & 15;
    float4 v = ((const float4*)x)[(size_t)nd * 16 + c];
    float m0 = fmaxf(v.x, 0.f) + 1e-7f;
    float m1 = fmaxf(v.y, 0.f) + 1e-7f;
    float m2 = fmaxf(v.z, 0.f) + 1e-7f;
    float m3 = fmaxf(v.w, 0.f) + 1e-7f;
    float p0 = expf(m0), p1 = expf(m1), p2 = expf(m2), p3 = expf(m3);
    float4* row = (float4*)&g_pq[(size_t)nd * 128];
    row[c]      = make_float4(p0, p1, p2, p3);
    row[16 + c] = make_float4(p0 * m0, p1 * m1, p2 * m2, p3 * m3);
    ((float4*)&g_x2[(size_t)nd * 128])[c] =
        make_float4(sigmoidf_(v.x), sigmoidf_(v.y), sigmoidf_(v.z), sigmoidf_(v.w));
}

// ---------------- CSR build ---------------------------------------------------
__global__ void k_hist(const int* __restrict__ dst, int E) {
    int e = blockIdx.x * blockDim.x + threadIdx.x;
    if (e < E) atomicAdd(&g_deg[dst[e]], 1);
}

__global__ void __launch_bounds__(1024) k_scanA(int n) {
    __shared__ int wp[32];
    int t = threadIdx.x, lane = t & 31, wid = t >> 5;
    int node = blockIdx.x * 1024 + t;
    int d = (node < n) ? g_deg[node] : 0;
    int inc = d;
#pragma unroll
    for (int s = 1; s < 32; s <<= 1) {
        int v = __shfl_up_sync(0xffffffffu, inc, s);
        if (lane >= s) inc += v;
    }
    if (lane == 31) wp[wid] = inc;
    __syncthreads();
    if (wid == 0) {
        int w = wp[lane], winc = w;
#pragma unroll
        for (int s = 1; s < 32; s <<= 1) {
            int v = __shfl_up_sync(0xffffffffu, winc, s);
            if (lane >= s) winc += v;
        }
        wp[lane] = winc - w;
    }
    __syncthreads();
    int ex = wp[wid] + inc - d;
    if (node < n) g_off[node] = ex;
    if (t == 1023) g_bsum[blockIdx.x] = ex + d;
}

__global__ void k_scanB(int nb, int n, int E) {
    int t = threadIdx.x, lane = t & 31, wid = t >> 5;
    __shared__ int w0tot;
    int v = (t < nb) ? g_bsum[t] : 0;
    int inc = v;
#pragma unroll
    for (int s = 1; s < 32; s <<= 1) {
        int u = __shfl_up_sync(0xffffffffu, inc, s);
        if (lane >= s) inc += u;
    }
    if (t == 31) w0tot = inc;
    __syncthreads();
    int ex = inc - v + (wid ? w0tot : 0);
    if (t < nb) g_boff[t] = ex;
    if (t == 0) g_off[n] = E;
}

__global__ void __launch_bounds__(1024) k_scanC(int n) {
    int node = blockIdx.x * 1024 + threadIdx.x;
    if (node >= n) return;
    int o = g_off[node] + g_boff[blockIdx.x];
    g_off[node] = o;
    g_cur[node] = o;
}

__global__ void k_scatter(const int* __restrict__ src, const int* __restrict__ dst, int E) {
    int e = blockIdx.x * blockDim.x + threadIdx.x;
    if (e >= E) return;
    int pos = atomicAdd(&g_cur[dst[e]], 1);
    g_adj[pos] = src[e];
}

// ---------------- warp-per-dst gathers ----------------------------------------
__global__ void k_gather_gen(int n) {
    int w = (blockIdx.x * blockDim.x + threadIdx.x) >> 5;
    int lane = threadIdx.x & 31;
    if (w >= n) return;
    int e = g_off[w], end = g_off[w + 1];
    float4 acc = make_float4(0.f, 0.f, 0.f, 0.f);
    for (; e + 4 <= end; e += 4) {
        int s0 = g_adj[e], s1 = g_adj[e + 1], s2 = g_adj[e + 2], s3 = g_adj[e + 3];
        float4 v0 = ((const float4*)g_pq)[(size_t)s0 * 32 + lane];
        float4 v1 = ((const float4*)g_pq)[(size_t)s1 * 32 + lane];
        float4 v2 = ((const float4*)g_pq)[(size_t)s2 * 32 + lane];
        float4 v3 = ((const float4*)g_pq)[(size_t)s3 * 32 + lane];
        acc.x += v0.x + v1.x + v2.x + v3.x;
        acc.y += v0.y + v1.y + v2.y + v3.y;
        acc.z += v0.z + v1.z + v2.z + v3.z;
        acc.w += v0.w + v1.w + v2.w + v3.w;
    }
    for (; e < end; e++) {
        int s = g_adj[e];
        float4 v = ((const float4*)g_pq)[(size_t)s * 32 + lane];
        acc.x += v.x; acc.y += v.y; acc.z += v.z; acc.w += v.w;
    }
    ((float4*)g_dennum)[(size_t)w * 32 + lane] = acc;
}

__global__ void k_gather_sage(int n) {
    int w = (blockIdx.x * blockDim.x + threadIdx.x) >> 5;
    int lane = threadIdx.x & 31;
    if (w >= n) return;
    int e = g_off[w], end = g_off[w + 1];
    float4 acc = make_float4(0.f, 0.f, 0.f, 0.f);
    for (; e + 4 <= end; e += 4) {
        int s0 = g_adj[e], s1 = g_adj[e + 1], s2 = g_adj[e + 2], s3 = g_adj[e + 3];
        float4 v0 = ((const float4*)g_xp)[(size_t)s0 * 32 + lane];
        float4 v1 = ((const float4*)g_xp)[(size_t)s1 * 32 + lane];
        float4 v2 = ((const float4*)g_xp)[(size_t)s2 * 32 + lane];
        float4 v3 = ((const float4*)g_xp)[(size_t)s3 * 32 + lane];
        acc.x += v0.x + v1.x + v2.x + v3.x;
        acc.y += v0.y + v1.y + v2.y + v3.y;
        acc.z += v0.z + v1.z + v2.z + v3.z;
        acc.w += v0.w + v1.w + v2.w + v3.w;
    }
    for (; e < end; e++) {
        int s = g_adj[e];
        float4 v = ((const float4*)g_xp)[(size_t)s * 32 + lane];
        acc.x += v.x; acc.y += v.y; acc.z += v.z; acc.w += v.w;
    }
    ((float4*)g_aggr)[(size_t)w * 32 + lane] = acc;
}

// ============ tiled GEMM bodies =============================================
// acc/cg/ng declared by caller; computes acc += At-tile @ Ws-tile.
#define MLBODY(CIN, COUT)                                                       \
    {                                                                           \
        const float* Ap = At + ng * 4;                                          \
        const float* Wq = Ws + cg * 8;                                          \
        _Pragma("unroll 8")                                                     \
        for (int k = 0; k < (CIN); k++) {                                       \
            float4 a4 = *(const float4*)&Ap[k * AT_S];                          \
            float4 w0 = *(const float4*)&Wq[k * (COUT)];                        \
            float4 w1 = *(const float4*)&Wq[k * (COUT) + 4];                    \
            float av[4] = {a4.x, a4.y, a4.z, a4.w};                             \
            float wv[8] = {w0.x, w0.y, w0.z, w0.w, w1.x, w1.y, w1.z, w1.w};     \
            _Pragma("unroll")                                                   \
            for (int i = 0; i < 4; i++)                                         \
                _Pragma("unroll")                                               \
                for (int j = 0; j < 8; j++) acc[i][j] += av[i] * wv[j];         \
        }                                                                       \
    }

#define DECL_ACC(CGMASK, NGSHIFT)                                               \
    int cg = tid & (CGMASK);                                                    \
    int ng = tid >> (NGSHIFT);                                                  \
    float acc[4][8];                                                            \
    _Pragma("unroll")                                                           \
    for (int i = 0; i < 4; i++)                                                 \
        _Pragma("unroll")                                                       \
        for (int j = 0; j < 8; j++) acc[i][j] = 0.f;

// ---------------- GEMM1 (+fused column stats) --------------------------------
__global__ void __launch_bounds__(256) k_gemm1(const float* __restrict__ x,
                                               const float* __restrict__ W1,
                                               const float* __restrict__ b1, int n) {
    extern __shared__ float sm[];
    float* Ws = sm;               // 64*128
    float* At = Ws + 64 * 128;    // 64*AT_S
    float* bs = At + 64 * AT_S;   // 128
    int tid = threadIdx.x;
    for (int i = tid; i < 2048; i += 256) ((float4*)Ws)[i] = ((const float4*)W1)[i];
    if (tid < 128) bs[tid] = b1[tid];
    int base = blockIdx.x * 64;
    for (int i = tid; i < 1024; i += 256) {
        int ndl = i >> 4, c4 = i & 15;
        int nd = base + ndl;
        float4 in4 = make_float4(0.f, 0.f, 0.f, 0.f);
        if (nd < n) {
            float4 de = ((const float4*)&g_dennum[(size_t)nd * 128])[c4];
            float4 nu = ((const float4*)&g_dennum[(size_t)nd * 128])[16 + c4];
            float4 xv = ((const float4*)x)[(size_t)nd * 16 + c4];
            in4.x = nu.x / (de.x > 0.f ? de.x : 1.f) + xv.x;
            in4.y = nu.y / (de.y > 0.f ? de.y : 1.f) + xv.y;
            in4.z = nu.z / (de.z > 0.f ? de.z : 1.f) + xv.z;
            in4.w = nu.w / (de.w > 0.f ? de.w : 1.f) + xv.w;
        }
        int k0 = c4 * 4;
        At[(k0 + 0) * AT_S + ndl] = in4.x;
        At[(k0 + 1) * AT_S + ndl] = in4.y;
        At[(k0 + 2) * AT_S + ndl] = in4.z;
        At[(k0 + 3) * AT_S + ndl] = in4.w;
    }
    __syncthreads();
    DECL_ACC(15, 4)
    MLBODY(64, 128)
    // store h1 and accumulate per-thread column stats
    float ls[8], lq[8];
#pragma unroll
    for (int j = 0; j < 8; j++) { ls[j] = 0.f; lq[j] = 0.f; }
#pragma unroll
    for (int i = 0; i < 4; i++) {
        int nd = base + ng * 4 + i;
        if (nd >= n) break;
        float v[8];
#pragma unroll
        for (int j = 0; j < 8; j++) {
            v[j] = acc[i][j] + bs[cg * 8 + j];
            ls[j] += v[j];
            lq[j] += v[j] * v[j];
        }
        float4* o = (float4*)&g_h1[(size_t)nd * 128 + cg * 8];
        o[0] = make_float4(v[0], v[1], v[2], v[3]);
        o[1] = make_float4(v[4], v[5], v[6], v[7]);
    }
    // block-level column reduction in smem (reuse At), then global atomics
    __syncthreads();
    float* ssum = At;         // 128
    float* ssq  = At + 128;   // 128
    if (tid < 128) { ssum[tid] = 0.f; ssq[tid] = 0.f; }
    __syncthreads();
#pragma unroll
    for (int j = 0; j < 8; j++) {
        atomicAdd(&ssum[cg * 8 + j], ls[j]);
        atomicAdd(&ssq[cg * 8 + j], lq[j]);
    }
    __syncthreads();
    if (tid < 128) {
        atomicAdd(&g_sum[tid], ssum[tid]);
        atomicAdd(&g_sumsq[tid], ssq[tid]);
    }
}

__global__ void k_stats_final(int n) {
    int f = threadIdx.x;
    float mu = g_sum[f] / (float)n;
    float var = g_sumsq[f] / (float)n - mu * mu;
    g_mu[f] = mu;
    g_istd[f] = rsqrtf(var + 1e-5f);
}

// ---------------- GEMM2 --------------------------------------------------------
__global__ void __launch_bounds__(128) k_gemm2(const float* __restrict__ gamma,
                                               const float* __restrict__ beta,
                                               const float* __restrict__ W2,
                                               const float* __restrict__ b2, int n) {
    extern __shared__ float sm[];
    float* Ws = sm;
    float* At = Ws + 128 * 64;
    float* prm = At + 128 * AT_S;
    float* bs = prm + 512;
    int tid = threadIdx.x;
    for (int i = tid; i < 2048; i += 128) ((float4*)Ws)[i] = ((const float4*)W2)[i];
    if (tid < 128) {
        prm[tid]       = gamma[tid];
        prm[128 + tid] = beta[tid];
        prm[256 + tid] = g_mu[tid];
        prm[384 + tid] = g_istd[tid];
    }
    if (tid < 64) bs[tid] = b2[tid];
    __syncthreads();
    int base = blockIdx.x * 64;
    for (int i = tid; i < 2048; i += 128) {
        int ndl = i >> 5, c4 = i & 31;
        int nd = base + ndl;
        float4 v = make_float4(0.f, 0.f, 0.f, 0.f);
        if (nd < n) v = ((const float4*)&g_h1[(size_t)nd * 128])[c4];
        int k0 = c4 * 4;
#pragma unroll
        for (int q = 0; q < 4; q++) {
            float val = (q == 0) ? v.x : (q == 1) ? v.y : (q == 2) ? v.z : v.w;
            int col = k0 + q;
            val = (val - prm[256 + col]) * prm[384 + col] * prm[col] + prm[128 + col];
            At[col * AT_S + ndl] = fmaxf(val, 0.f);
        }
    }
    __syncthreads();
    DECL_ACC(7, 3)
    MLBODY(128, 64)
#pragma unroll
    for (int i = 0; i < 4; i++) {
        int nd = base + ng * 4 + i;
        if (nd >= n) break;
        float4 o0 = make_float4(sigmoidf_(acc[i][0] + bs[cg * 8 + 0]),
                                sigmoidf_(acc[i][1] + bs[cg * 8 + 1]),
                                sigmoidf_(acc[i][2] + bs[cg * 8 + 2]),
                                sigmoidf_(acc[i][3] + bs[cg * 8 + 3]));
        float4 o1 = make_float4(sigmoidf_(acc[i][4] + bs[cg * 8 + 4]),
                                sigmoidf_(acc[i][5] + bs[cg * 8 + 5]),
                                sigmoidf_(acc[i][6] + bs[cg * 8 + 6]),
                                sigmoidf_(acc[i][7] + bs[cg * 8 + 7]));
        float4* o = (float4*)&g_x2[(size_t)nd * 128 + 64 + cg * 8];
        o[0] = o0; o[1] = o1;
    }
}

// ---------------- GEMM3 --------------------------------------------------------
__global__ void __launch_bounds__(256) k_gemm3(const float* __restrict__ Wp,
                                               const float* __restrict__ bp, int n) {
    extern __shared__ float sm[];
    float* Ws = sm;
    float* At = Ws + 128 * 128;
    float* bs = At + 128 * AT_S;
    int tid = threadIdx.x;
    for (int i = tid; i < 4096; i += 256) ((float4*)Ws)[i] = ((const float4*)Wp)[i];
    if (tid < 128) bs[tid] = bp[tid];
    int base = blockIdx.x * 64;
    for (int i = tid; i < 2048; i += 256) {
        int ndl = i >> 5, c4 = i & 31;
        int nd = base + ndl;
        float4 v = make_float4(0.f, 0.f, 0.f, 0.f);
        if (nd < n) v = ((const float4*)&g_x2[(size_t)nd * 128])[c4];
        int k0 = c4 * 4;
        At[(k0 + 0) * AT_S + ndl] = v.x;
        At[(k0 + 1) * AT_S + ndl] = v.y;
        At[(k0 + 2) * AT_S + ndl] = v.z;
        At[(k0 + 3) * AT_S + ndl] = v.w;
    }
    __syncthreads();
    DECL_ACC(15, 4)
    MLBODY(128, 128)
#pragma unroll
    for (int i = 0; i < 4; i++) {
        int nd = base + ng * 4 + i;
        if (nd >= n) break;
        float4 o0 = make_float4(fmaxf(acc[i][0] + bs[cg * 8 + 0], 0.f),
                                fmaxf(acc[i][1] + bs[cg * 8 + 1], 0.f),
                                fmaxf(acc[i][2] + bs[cg * 8 + 2], 0.f),
                                fmaxf(acc[i][3] + bs[cg * 8 + 3], 0.f));
        float4 o1 = make_float4(fmaxf(acc[i][4] + bs[cg * 8 + 4], 0.f),
                                fmaxf(acc[i][5] + bs[cg * 8 + 5], 0.f),
                                fmaxf(acc[i][6] + bs[cg * 8 + 6], 0.f),
                                fmaxf(acc[i][7] + bs[cg * 8 + 7], 0.f));
        float4* o = (float4*)&g_xp[(size_t)nd * 128 + cg * 8];
        o[0] = o0; o[1] = o1;
    }
}

// ---------------- fused GEMM4: sigmoid(aggr@Wl + x2@Wr + bl) @ Wf + bf ---------
__global__ void __launch_bounds__(128) k_gemm4(const float* __restrict__ Wl,
                                               const float* __restrict__ bl,
                                               const float* __restrict__ Wr,
                                               const float* __restrict__ Wf,
                                               const float* __restrict__ bf,
                                               float* __restrict__ out,
                                               int n, int write_logits) {
    extern __shared__ float sm[];
    float* Ws = sm;               // 128*64
    float* At = Ws + 128 * 64;    // 128*AT_S
    float* bs = At + 128 * AT_S;  // 64
    float* wf = bs + 64;          // 64
    int tid = threadIdx.x;
    int base = blockIdx.x * 64;

    // phase 1: Wl x aggr
    for (int i = tid; i < 2048; i += 128) ((float4*)Ws)[i] = ((const float4*)Wl)[i];
    if (tid < 64) { bs[tid] = bl[tid]; wf[tid] = Wf[tid]; }
    for (int i = tid; i < 2048; i += 128) {
        int ndl = i >> 5, c4 = i & 31;
        int nd = base + ndl;
        float4 v = make_float4(0.f, 0.f, 0.f, 0.f);
        if (nd < n) v = ((const float4*)&g_aggr[(size_t)nd * 128])[c4];
        int k0 = c4 * 4;
        At[(k0 + 0) * AT_S + ndl] = v.x;
        At[(k0 + 1) * AT_S + ndl] = v.y;
        At[(k0 + 2) * AT_S + ndl] = v.z;
        At[(k0 + 3) * AT_S + ndl] = v.w;
    }
    __syncthreads();
    DECL_ACC(7, 3)
    MLBODY(128, 64)
    __syncthreads();   // done reading phase-1 smem

    // phase 2: Wr x x2 (accumulate into same acc)
    for (int i = tid; i < 2048; i += 128) ((float4*)Ws)[i] = ((const float4*)Wr)[i];
    for (int i = tid; i < 2048; i += 128) {
        int ndl = i >> 5, c4 = i & 31;
        int nd = base + ndl;
        float4 v = make_float4(0.f, 0.f, 0.f, 0.f);
        if (nd < n) v = ((const float4*)&g_x2[(size_t)nd * 128])[c4];
        int k0 = c4 * 4;
        At[(k0 + 0) * AT_S + ndl] = v.x;
        At[(k0 + 1) * AT_S + ndl] = v.y;
        At[(k0 + 2) * AT_S + ndl] = v.z;
        At[(k0 + 3) * AT_S + ndl] = v.w;
    }
    __syncthreads();
    MLBODY(128, 64)

    float bf0 = bf[0];
#pragma unroll
    for (int i = 0; i < 4; i++) {
        int nd = base + ng * 4 + i;
        float lp = 0.f;
        if (nd < n) {
#pragma unroll
            for (int j = 0; j < 8; j++)
                lp += sigmoidf_(acc[i][j] + bs[cg * 8 + j]) * wf[cg * 8 + j];
        }
        lp += __shfl_xor_sync(0xffffffffu, lp, 1);
        lp += __shfl_xor_sync(0xffffffffu, lp, 2);
        lp += __shfl_xor_sync(0xffffffffu, lp, 4);
        if (cg == 0 && nd < n) {
            float logit = lp + bf0;
            out[nd] = sigmoidf_(logit);
            if (write_logits) out[n + nd] = logit;
        }
    }
}

// ---------------- launch --------------------------------------------------------
extern "C" void kernel_launch(void* const* d_in, const int* in_sizes, int n_in,
                              void* d_out, int out_size) {
    const float* x   = (const float*)d_in[0];
    const int*   ei  = (const int*)d_in[1];
    const float* W1  = (const float*)d_in[2];
    const float* b1  = (const float*)d_in[3];
    const float* gamma = (const float*)d_in[4];
    const float* beta  = (const float*)d_in[5];
    const float* W2  = (const float*)d_in[6];
    const float* b2  = (const float*)d_in[7];
    const float* Wp  = (const float*)d_in[8];
    const float* bp  = (const float*)d_in[9];
    const float* Wl  = (const float*)d_in[10];
    const float* bl  = (const float*)d_in[11];
    const float* Wr  = (const float*)d_in[12];
    const float* Wf  = (const float*)d_in[13];
    const float* bf  = (const float*)d_in[14];
    float* out = (float*)d_out;

    int n = in_sizes[0] / 64;
    int E = in_sizes[1] / 2;
    const int* src = ei;
    const int* dst = ei + E;
    int write_logits = (out_size >= 2 * n) ? 1 : 0;

    const int S1 = (64 * 128 + 64 * AT_S + 128) * 4;
    const int S2 = (128 * 64 + 128 * AT_S + 512 + 64) * 4;
    const int S3 = (128 * 128 + 128 * AT_S + 128) * 4;
    const int S4 = (128 * 64 + 128 * AT_S + 128) * 4;
    cudaFuncSetAttribute(k_gemm1, cudaFuncAttributeMaxDynamicSharedMemorySize, S1);
    cudaFuncSetAttribute(k_gemm2, cudaFuncAttributeMaxDynamicSharedMemorySize, S2);
    cudaFuncSetAttribute(k_gemm3, cudaFuncAttributeMaxDynamicSharedMemorySize, S3);
    cudaFuncSetAttribute(k_gemm4, cudaFuncAttributeMaxDynamicSharedMemorySize, S4);

    // CSR build + prep
    k_zero_small<<<(n + 255) / 256, 256>>>(n);
    k_prep<<<(n * 16 + 255) / 256, 256>>>(x, n);
    k_hist<<<(E + 255) / 256, 256>>>(dst, E);
    int nb1024 = (n + 1023) / 1024;
    k_scanA<<<nb1024, 1024>>>(n);
    k_scanB<<<1, 64>>>(nb1024, n, E);
    k_scanC<<<nb1024, 1024>>>(n);
    k_scatter<<<(E + 255) / 256, 256>>>(src, dst, E);

    int gb = (n * 32 + 255) / 256;
    k_gather_gen<<<gb, 256>>>(n);

    int nb = (n + 63) / 64;
    k_gemm1<<<nb, 256, S1>>>(x, W1, b1, n);
    k_stats_final<<<1, 128>>>(n);
    k_gemm2<<<nb, 128, S2>>>(gamma, beta, W2, b2, n);
    k_gemm3<<<nb, 256, S3>>>(Wp, bp, n);
    k_gather_sage<<<gb, 256>>>(n);
    k_gemm4<<<nb, 128, S4>>>(Wl, bl, Wr, Wf, bf, out, n, write_logits);
}

// round 9
// speedup vs baseline: 2.2163x; 1.0079x over previous
#include <cuda_runtime.h>
#include <math.h>

#define NN 50000
#define EE 800000

// ---------------- scratch (device globals) ----------------------------------
__device__ float g_pq    [NN * 128];
__device__ float g_dennum[NN * 128];
__device__ float g_h1    [NN * 128];
__device__ float g_x2    [NN * 128];
__device__ float g_xp    [NN * 128];
__device__ float g_aggr  [NN * 128];
__device__ float g_sum[128], g_sumsq[128], g_mu[128], g_istd[128];
// CSR
__device__ int g_deg[NN];
__device__ int g_off[NN + 1];
__device__ int g_cur[NN];
__device__ int g_adj[EE];
__device__ int g_bsum[64];
__device__ int g_boff[64];

__device__ __forceinline__ float sigmoidf_(float v) { return 1.0f / (1.0f + __expf(-v)); }

typedef unsigned long long ull;

__device__ __forceinline__ ull pack2s(float a) {
    ull r;
    asm("mov.b64 %0, {%1, %1};" : "=l"(r) : "f"(a));
    return r;
}
__device__ __forceinline__ void unpack2(ull v, float& a, float& b) {
    asm("mov.b64 {%0, %1}, %2;" : "=f"(a), "=f"(b) : "l"(v));
}
__device__ __forceinline__ ull fma2(ull a, ull b, ull c) {
    ull r;
    asm("fma.rn.f32x2 %0, %1, %2, %3;" : "=l"(r) : "l"(a), "l"(b), "l"(c));
    return r;
}

#define AT_S 68

// ---------------- small zero init -------------------------------------------
__global__ void k_zero_small(int n) {
    int i = blockIdx.x * blockDim.x + threadIdx.x;
    if (i < n) g_deg[i] = 0;
    if (i < 128) { g_sum[i] = 0.f; g_sumsq[i] = 0.f; }
}

// ---------------- per-node precompute ----------------------------------------
__global__ void k_prep(const float* __restrict__ x, int n) {
    int tid = blockIdx.x * blockDim.x + threadIdx.x;
    if (tid >= n * 16) return;
    int nd = tid >> 4, c = tid & 15;
    float4 v = ((const float4*)x)[(size_t)nd * 16 + c];
    float m0 = fmaxf(v.x, 0.f) + 1e-7f;
    float m1 = fmaxf(v.y, 0.f) + 1e-7f;
    float m2 = fmaxf(v.z, 0.f) + 1e-7f;
    float m3 = fmaxf(v.w, 0.f) + 1e-7f;
    float p0 = expf(m0), p1 = expf(m1), p2 = expf(m2), p3 = expf(m3);
    float4* row = (float4*)&g_pq[(size_t)nd * 128];
    row[c]      = make_float4(p0, p1, p2, p3);
    row[16 + c] = make_float4(p0 * m0, p1 * m1, p2 * m2, p3 * m3);
    ((float4*)&g_x2[(size_t)nd * 128])[c] =
        make_float4(sigmoidf_(v.x), sigmoidf_(v.y), sigmoidf_(v.z), sigmoidf_(v.w));
}

// ---------------- CSR build ---------------------------------------------------
__global__ void k_hist(const int* __restrict__ dst, int E) {
    int e = blockIdx.x * blockDim.x + threadIdx.x;
    if (e < E) atomicAdd(&g_deg[dst[e]], 1);
}

__global__ void __launch_bounds__(1024) k_scanA(int n) {
    __shared__ int wp[32];
    int t = threadIdx.x, lane = t & 31, wid = t >> 5;
    int node = blockIdx.x * 1024 + t;
    int d = (node < n) ? g_deg[node] : 0;
    int inc = d;
#pragma unroll
    for (int s = 1; s < 32; s <<= 1) {
        int v = __shfl_up_sync(0xffffffffu, inc, s);
        if (lane >= s) inc += v;
    }
    if (lane == 31) wp[wid] = inc;
    __syncthreads();
    if (wid == 0) {
        int w = wp[lane], winc = w;
#pragma unroll
        for (int s = 1; s < 32; s <<= 1) {
            int v = __shfl_up_sync(0xffffffffu, winc, s);
            if (lane >= s) winc += v;
        }
        wp[lane] = winc - w;
    }
    __syncthreads();
    int ex = wp[wid] + inc - d;
    if (node < n) g_off[node] = ex;
    if (t == 1023) g_bsum[blockIdx.x] = ex + d;
}

__global__ void k_scanB(int nb, int n, int E) {
    int t = threadIdx.x, lane = t & 31, wid = t >> 5;
    __shared__ int w0tot;
    int v = (t < nb) ? g_bsum[t] : 0;
    int inc = v;
#pragma unroll
    for (int s = 1; s < 32; s <<= 1) {
        int u = __shfl_up_sync(0xffffffffu, inc, s);
        if (lane >= s) inc += u;
    }
    if (t == 31) w0tot = inc;
    __syncthreads();
    int ex = inc - v + (wid ? w0tot : 0);
    if (t < nb) g_boff[t] = ex;
    if (t == 0) g_off[n] = E;
}

__global__ void __launch_bounds__(1024) k_scanC(int n) {
    int node = blockIdx.x * 1024 + threadIdx.x;
    if (node >= n) return;
    int o = g_off[node] + g_boff[blockIdx.x];
    g_off[node] = o;
    g_cur[node] = o;
}

__global__ void k_scatter(const int* __restrict__ src, const int* __restrict__ dst, int E) {
    int e = blockIdx.x * blockDim.x + threadIdx.x;
    if (e >= E) return;
    int pos = atomicAdd(&g_cur[dst[e]], 1);
    g_adj[pos] = src[e];
}

// ---------------- warp-per-dst gathers ----------------------------------------
__global__ void k_gather_gen(int n) {
    int w = (blockIdx.x * blockDim.x + threadIdx.x) >> 5;
    int lane = threadIdx.x & 31;
    if (w >= n) return;
    int e = g_off[w], end = g_off[w + 1];
    float4 acc = make_float4(0.f, 0.f, 0.f, 0.f);
    for (; e + 4 <= end; e += 4) {
        int s0 = g_adj[e], s1 = g_adj[e + 1], s2 = g_adj[e + 2], s3 = g_adj[e + 3];
        float4 v0 = ((const float4*)g_pq)[(size_t)s0 * 32 + lane];
        float4 v1 = ((const float4*)g_pq)[(size_t)s1 * 32 + lane];
        float4 v2 = ((const float4*)g_pq)[(size_t)s2 * 32 + lane];
        float4 v3 = ((const float4*)g_pq)[(size_t)s3 * 32 + lane];
        acc.x += v0.x + v1.x + v2.x + v3.x;
        acc.y += v0.y + v1.y + v2.y + v3.y;
        acc.z += v0.z + v1.z + v2.z + v3.z;
        acc.w += v0.w + v1.w + v2.w + v3.w;
    }
    for (; e < end; e++) {
        int s = g_adj[e];
        float4 v = ((const float4*)g_pq)[(size_t)s * 32 + lane];
        acc.x += v.x; acc.y += v.y; acc.z += v.z; acc.w += v.w;
    }
    ((float4*)g_dennum)[(size_t)w * 32 + lane] = acc;
}

__global__ void k_gather_sage(int n) {
    int w = (blockIdx.x * blockDim.x + threadIdx.x) >> 5;
    int lane = threadIdx.x & 31;
    if (w >= n) return;
    int e = g_off[w], end = g_off[w + 1];
    float4 acc = make_float4(0.f, 0.f, 0.f, 0.f);
    for (; e + 4 <= end; e += 4) {
        int s0 = g_adj[e], s1 = g_adj[e + 1], s2 = g_adj[e + 2], s3 = g_adj[e + 3];
        float4 v0 = ((const float4*)g_xp)[(size_t)s0 * 32 + lane];
        float4 v1 = ((const float4*)g_xp)[(size_t)s1 * 32 + lane];
        float4 v2 = ((const float4*)g_xp)[(size_t)s2 * 32 + lane];
        float4 v3 = ((const float4*)g_xp)[(size_t)s3 * 32 + lane];
        acc.x += v0.x + v1.x + v2.x + v3.x;
        acc.y += v0.y + v1.y + v2.y + v3.y;
        acc.z += v0.z + v1.z + v2.z + v3.z;
        acc.w += v0.w + v1.w + v2.w + v3.w;
    }
    for (; e < end; e++) {
        int s = g_adj[e];
        float4 v = ((const float4*)g_xp)[(size_t)s * 32 + lane];
        acc.x += v.x; acc.y += v.y; acc.z += v.z; acc.w += v.w;
    }
    ((float4*)g_aggr)[(size_t)w * 32 + lane] = acc;
}

// ============ tiled GEMM bodies (packed f32x2) ===============================
// acc2[4][4] of b64 pairs; each pair = 2 consecutive output columns.
#define DECL_ACC2(CGMASK, NGSHIFT)                                              \
    int cg = tid & (CGMASK);                                                    \
    int ng = tid >> (NGSHIFT);                                                  \
    ull acc2[4][4];                                                             \
    _Pragma("unroll")                                                           \
    for (int i = 0; i < 4; i++)                                                 \
        _Pragma("unroll")                                                       \
        for (int j = 0; j < 4; j++) acc2[i][j] = 0ull;

#define MLBODY2(CIN, COUT)                                                      \
    {                                                                           \
        const float* Ap = At + ng * 4;                                          \
        const ull* Wq = (const ull*)(Ws + cg * 8);                              \
        _Pragma("unroll 8")                                                     \
        for (int k = 0; k < (CIN); k++) {                                       \
            float4 a4 = *(const float4*)&Ap[k * AT_S];                          \
            ulonglong2 wa = *(const ulonglong2*)(Wq + k * ((COUT) / 2));        \
            ulonglong2 wb = *(const ulonglong2*)(Wq + k * ((COUT) / 2) + 2);    \
            ull av[4] = {pack2s(a4.x), pack2s(a4.y), pack2s(a4.z), pack2s(a4.w)};\
            _Pragma("unroll")                                                   \
            for (int i = 0; i < 4; i++) {                                       \
                acc2[i][0] = fma2(av[i], wa.x, acc2[i][0]);                     \
                acc2[i][1] = fma2(av[i], wa.y, acc2[i][1]);                     \
                acc2[i][2] = fma2(av[i], wb.x, acc2[i][2]);                     \
                acc2[i][3] = fma2(av[i], wb.y, acc2[i][3]);                     \
            }                                                                   \
        }                                                                       \
    }

#define UNPACK_ACC()                                                            \
    float acc[4][8];                                                            \
    _Pragma("unroll")                                                           \
    for (int i = 0; i < 4; i++)                                                 \
        _Pragma("unroll")                                                       \
        for (int j = 0; j < 4; j++)                                             \
            unpack2(acc2[i][j], acc[i][2 * j], acc[i][2 * j + 1]);

// ---------------- GEMM1 (+fused column stats) --------------------------------
__global__ void __launch_bounds__(256) k_gemm1(const float* __restrict__ x,
                                               const float* __restrict__ W1,
                                               const float* __restrict__ b1, int n) {
    extern __shared__ float sm[];
    float* Ws = sm;               // 64*128
    float* At = Ws + 64 * 128;    // 64*AT_S
    float* bs = At + 64 * AT_S;   // 128
    int tid = threadIdx.x;
    for (int i = tid; i < 2048; i += 256) ((float4*)Ws)[i] = ((const float4*)W1)[i];
    if (tid < 128) bs[tid] = b1[tid];
    int base = blockIdx.x * 64;
    for (int i = tid; i < 1024; i += 256) {
        int ndl = i >> 4, c4 = i & 15;
        int nd = base + ndl;
        float4 in4 = make_float4(0.f, 0.f, 0.f, 0.f);
        if (nd < n) {
            float4 de = ((const float4*)&g_dennum[(size_t)nd * 128])[c4];
            float4 nu = ((const float4*)&g_dennum[(size_t)nd * 128])[16 + c4];
            float4 xv = ((const float4*)x)[(size_t)nd * 16 + c4];
            in4.x = nu.x / (de.x > 0.f ? de.x : 1.f) + xv.x;
            in4.y = nu.y / (de.y > 0.f ? de.y : 1.f) + xv.y;
            in4.z = nu.z / (de.z > 0.f ? de.z : 1.f) + xv.z;
            in4.w = nu.w / (de.w > 0.f ? de.w : 1.f) + xv.w;
        }
        int k0 = c4 * 4;
        At[(k0 + 0) * AT_S + ndl] = in4.x;
        At[(k0 + 1) * AT_S + ndl] = in4.y;
        At[(k0 + 2) * AT_S + ndl] = in4.z;
        At[(k0 + 3) * AT_S + ndl] = in4.w;
    }
    __syncthreads();
    DECL_ACC2(15, 4)
    MLBODY2(64, 128)
    UNPACK_ACC()
    float ls[8], lq[8];
#pragma unroll
    for (int j = 0; j < 8; j++) { ls[j] = 0.f; lq[j] = 0.f; }
#pragma unroll
    for (int i = 0; i < 4; i++) {
        int nd = base + ng * 4 + i;
        if (nd >= n) break;
        float v[8];
#pragma unroll
        for (int j = 0; j < 8; j++) {
            v[j] = acc[i][j] + bs[cg * 8 + j];
            ls[j] += v[j];
            lq[j] += v[j] * v[j];
        }
        float4* o = (float4*)&g_h1[(size_t)nd * 128 + cg * 8];
        o[0] = make_float4(v[0], v[1], v[2], v[3]);
        o[1] = make_float4(v[4], v[5], v[6], v[7]);
    }
    __syncthreads();
    float* ssum = At;
    float* ssq  = At + 128;
    if (tid < 128) { ssum[tid] = 0.f; ssq[tid] = 0.f; }
    __syncthreads();
#pragma unroll
    for (int j = 0; j < 8; j++) {
        atomicAdd(&ssum[cg * 8 + j], ls[j]);
        atomicAdd(&ssq[cg * 8 + j], lq[j]);
    }
    __syncthreads();
    if (tid < 128) {
        atomicAdd(&g_sum[tid], ssum[tid]);
        atomicAdd(&g_sumsq[tid], ssq[tid]);
    }
}

__global__ void k_stats_final(int n) {
    int f = threadIdx.x;
    float mu = g_sum[f] / (float)n;
    float var = g_sumsq[f] / (float)n - mu * mu;
    g_mu[f] = mu;
    g_istd[f] = rsqrtf(var + 1e-5f);
}

// ---------------- GEMM2 --------------------------------------------------------
__global__ void __launch_bounds__(128) k_gemm2(const float* __restrict__ gamma,
                                               const float* __restrict__ beta,
                                               const float* __restrict__ W2,
                                               const float* __restrict__ b2, int n) {
    extern __shared__ float sm[];
    float* Ws = sm;
    float* At = Ws + 128 * 64;
    float* prm = At + 128 * AT_S;
    float* bs = prm + 512;
    int tid = threadIdx.x;
    for (int i = tid; i < 2048; i += 128) ((float4*)Ws)[i] = ((const float4*)W2)[i];
    if (tid < 128) {
        prm[tid]       = gamma[tid];
        prm[128 + tid] = beta[tid];
        prm[256 + tid] = g_mu[tid];
        prm[384 + tid] = g_istd[tid];
    }
    if (tid < 64) bs[tid] = b2[tid];
    __syncthreads();
    int base = blockIdx.x * 64;
    for (int i = tid; i < 2048; i += 128) {
        int ndl = i >> 5, c4 = i & 31;
        int nd = base + ndl;
        float4 v = make_float4(0.f, 0.f, 0.f, 0.f);
        if (nd < n) v = ((const float4*)&g_h1[(size_t)nd * 128])[c4];
        int k0 = c4 * 4;
#pragma unroll
        for (int q = 0; q < 4; q++) {
            float val = (q == 0) ? v.x : (q == 1) ? v.y : (q == 2) ? v.z : v.w;
            int col = k0 + q;
            val = (val - prm[256 + col]) * prm[384 + col] * prm[col] + prm[128 + col];
            At[col * AT_S + ndl] = fmaxf(val, 0.f);
        }
    }
    __syncthreads();
    DECL_ACC2(7, 3)
    MLBODY2(128, 64)
    UNPACK_ACC()
#pragma unroll
    for (int i = 0; i < 4; i++) {
        int nd = base + ng * 4 + i;
        if (nd >= n) break;
        float4 o0 = make_float4(sigmoidf_(acc[i][0] + bs[cg * 8 + 0]),
                                sigmoidf_(acc[i][1] + bs[cg * 8 + 1]),
                                sigmoidf_(acc[i][2] + bs[cg * 8 + 2]),
                                sigmoidf_(acc[i][3] + bs[cg * 8 + 3]));
        float4 o1 = make_float4(sigmoidf_(acc[i][4] + bs[cg * 8 + 4]),
                                sigmoidf_(acc[i][5] + bs[cg * 8 + 5]),
                                sigmoidf_(acc[i][6] + bs[cg * 8 + 6]),
                                sigmoidf_(acc[i][7] + bs[cg * 8 + 7]));
        float4* o = (float4*)&g_x2[(size_t)nd * 128 + 64 + cg * 8];
        o[0] = o0; o[1] = o1;
    }
}

// ---------------- GEMM3 --------------------------------------------------------
__global__ void __launch_bounds__(256) k_gemm3(const float* __restrict__ Wp,
                                               const float* __restrict__ bp, int n) {
    extern __shared__ float sm[];
    float* Ws = sm;
    float* At = Ws + 128 * 128;
    float* bs = At + 128 * AT_S;
    int tid = threadIdx.x;
    for (int i = tid; i < 4096; i += 256) ((float4*)Ws)[i] = ((const float4*)Wp)[i];
    if (tid < 128) bs[tid] = bp[tid];
    int base = blockIdx.x * 64;
    for (int i = tid; i < 2048; i += 256) {
        int ndl = i >> 5, c4 = i & 31;
        int nd = base + ndl;
        float4 v = make_float4(0.f, 0.f, 0.f, 0.f);
        if (nd < n) v = ((const float4*)&g_x2[(size_t)nd * 128])[c4];
        int k0 = c4 * 4;
        At[(k0 + 0) * AT_S + ndl] = v.x;
        At[(k0 + 1) * AT_S + ndl] = v.y;
        At[(k0 + 2) * AT_S + ndl] = v.z;
        At[(k0 + 3) * AT_S + ndl] = v.w;
    }
    __syncthreads();
    DECL_ACC2(15, 4)
    MLBODY2(128, 128)
    UNPACK_ACC()
#pragma unroll
    for (int i = 0; i < 4; i++) {
        int nd = base + ng * 4 + i;
        if (nd >= n) break;
        float4 o0 = make_float4(fmaxf(acc[i][0] + bs[cg * 8 + 0], 0.f),
                                fmaxf(acc[i][1] + bs[cg * 8 + 1], 0.f),
                                fmaxf(acc[i][2] + bs[cg * 8 + 2], 0.f),
                                fmaxf(acc[i][3] + bs[cg * 8 + 3], 0.f));
        float4 o1 = make_float4(fmaxf(acc[i][4] + bs[cg * 8 + 4], 0.f),
                                fmaxf(acc[i][5] + bs[cg * 8 + 5], 0.f),
                                fmaxf(acc[i][6] + bs[cg * 8 + 6], 0.f),
                                fmaxf(acc[i][7] + bs[cg * 8 + 7], 0.f));
        float4* o = (float4*)&g_xp[(size_t)nd * 128 + cg * 8];
        o[0] = o0; o[1] = o1;
    }
}

// ---------------- fused GEMM4 ---------------------------------------------------
__global__ void __launch_bounds__(128) k_gemm4(const float* __restrict__ Wl,
                                               const float* __restrict__ bl,
                                               const float* __restrict__ Wr,
                                               const float* __restrict__ Wf,
                                               const float* __restrict__ bf,
                                               float* __restrict__ out,
                                               int n, int write_logits) {
    extern __shared__ float sm[];
    float* Ws = sm;
    float* At = Ws + 128 * 64;
    float* bs = At + 128 * AT_S;
    float* wf = bs + 64;
    int tid = threadIdx.x;
    int base = blockIdx.x * 64;

    for (int i = tid; i < 2048; i += 128) ((float4*)Ws)[i] = ((const float4*)Wl)[i];
    if (tid < 64) { bs[tid] = bl[tid]; wf[tid] = Wf[tid]; }
    for (int i = tid; i < 2048; i += 128) {
        int ndl = i >> 5, c4 = i & 31;
        int nd = base + ndl;
        float4 v = make_float4(0.f, 0.f, 0.f, 0.f);
        if (nd < n) v = ((const float4*)&g_aggr[(size_t)nd * 128])[c4];
        int k0 = c4 * 4;
        At[(k0 + 0) * AT_S + ndl] = v.x;
        At[(k0 + 1) * AT_S + ndl] = v.y;
        At[(k0 + 2) * AT_S + ndl] = v.z;
        At[(k0 + 3) * AT_S + ndl] = v.w;
    }
    __syncthreads();
    DECL_ACC2(7, 3)
    MLBODY2(128, 64)
    __syncthreads();

    for (int i = tid; i < 2048; i += 128) ((float4*)Ws)[i] = ((const float4*)Wr)[i];
    for (int i = tid; i < 2048; i += 128) {
        int ndl = i >> 5, c4 = i & 31;
        int nd = base + ndl;
        float4 v = make_float4(0.f, 0.f, 0.f, 0.f);
        if (nd < n) v = ((const float4*)&g_x2[(size_t)nd * 128])[c4];
        int k0 = c4 * 4;
        At[(k0 + 0) * AT_S + ndl] = v.x;
        At[(k0 + 1) * AT_S + ndl] = v.y;
        At[(k0 + 2) * AT_S + ndl] = v.z;
        At[(k0 + 3) * AT_S + ndl] = v.w;
    }
    __syncthreads();
    MLBODY2(128, 64)
    UNPACK_ACC()

    float bf0 = bf[0];
#pragma unroll
    for (int i = 0; i < 4; i++) {
        int nd = base + ng * 4 + i;
        float lp = 0.f;
        if (nd < n) {
#pragma unroll
            for (int j = 0; j < 8; j++)
                lp += sigmoidf_(acc[i][j] + bs[cg * 8 + j]) * wf[cg * 8 + j];
        }
        lp += __shfl_xor_sync(0xffffffffu, lp, 1);
        lp += __shfl_xor_sync(0xffffffffu, lp, 2);
        lp += __shfl_xor_sync(0xffffffffu, lp, 4);
        if (cg == 0 && nd < n) {
            float logit = lp + bf0;
            out[nd] = sigmoidf_(logit);
            if (write_logits) out[n + nd] = logit;
        }
    }
}

// ---------------- launch --------------------------------------------------------
extern "C" void kernel_launch(void* const* d_in, const int* in_sizes, int n_in,
                              void* d_out, int out_size) {
    const float* x   = (const float*)d_in[0];
    const int*   ei  = (const int*)d_in[1];
    const float* W1  = (const float*)d_in[2];
    const float* b1  = (const float*)d_in[3];
    const float* gamma = (const float*)d_in[4];
    const float* beta  = (const float*)d_in[5];
    const float* W2  = (const float*)d_in[6];
    const float* b2  = (const float*)d_in[7];
    const float* Wp  = (const float*)d_in[8];
    const float* bp  = (const float*)d_in[9];
    const float* Wl  = (const float*)d_in[10];
    const float* bl  = (const float*)d_in[11];
    const float* Wr  = (const float*)d_in[12];
    const float* Wf  = (const float*)d_in[13];
    const float* bf  = (const float*)d_in[14];
    float* out = (float*)d_out;

    int n = in_sizes[0] / 64;
    int E = in_sizes[1] / 2;
    const int* src = ei;
    const int* dst = ei + E;
    int write_logits = (out_size >= 2 * n) ? 1 : 0;

    const int S1 = (64 * 128 + 64 * AT_S + 128) * 4;
    const int S2 = (128 * 64 + 128 * AT_S + 512 + 64) * 4;
    const int S3 = (128 * 128 + 128 * AT_S + 128) * 4;
    const int S4 = (128 * 64 + 128 * AT_S + 128) * 4;
    cudaFuncSetAttribute(k_gemm1, cudaFuncAttributeMaxDynamicSharedMemorySize, S1);
    cudaFuncSetAttribute(k_gemm2, cudaFuncAttributeMaxDynamicSharedMemorySize, S2);
    cudaFuncSetAttribute(k_gemm3, cudaFuncAttributeMaxDynamicSharedMemorySize, S3);
    cudaFuncSetAttribute(k_gemm4, cudaFuncAttributeMaxDynamicSharedMemorySize, S4);

    k_zero_small<<<(n + 255) / 256, 256>>>(n);
    k_prep<<<(n * 16 + 255) / 256, 256>>>(x, n);
    k_hist<<<(E + 255) / 256, 256>>>(dst, E);
    int nb1024 = (n + 1023) / 1024;
    k_scanA<<<nb1024, 1024>>>(n);
    k_scanB<<<1, 64>>>(nb1024, n, E);
    k_scanC<<<nb1024, 1024>>>(n);
    k_scatter<<<(E + 255) / 256, 256>>>(src, dst, E);

    int gb = (n * 32 + 255) / 256;
    k_gather_gen<<<gb, 256>>>(n);

    int nb = (n + 63) / 64;
    k_gemm1<<<nb, 256, S1>>>(x, W1, b1, n);
    k_stats_final<<<1, 128>>>(n);
    k_gemm2<<<nb, 128, S2>>>(gamma, beta, W2, b2, n);
    k_gemm3<<<nb, 256, S3>>>(Wp, bp, n);
    k_gather_sage<<<gb, 256>>>(n);
    k_gemm4<<<nb, 128, S4>>>(Wl, bl, Wr, Wf, bf, out, n, write_logits);
}

// round 10
// speedup vs baseline: 2.2169x; 1.0002x over previous
#include <cuda_runtime.h>
#include <math.h>

#define NN 50000
#define EE 800000

// ---------------- scratch (device globals) ----------------------------------
__device__ float g_pq    [NN * 128];
__device__ float g_dennum[NN * 128];
__device__ float g_h1    [NN * 128];
__device__ float g_x2    [NN * 128];
__device__ float g_xpl   [NN * 64];    // xp @ Wl (pre-multiplied before gather)
__device__ float g_aggr  [NN * 64];    // sum of xpl over in-edges
__device__ float g_sum[128], g_sumsq[128];
// CSR
__device__ int g_deg[NN];
__device__ int g_off[NN + 1];
__device__ int g_cur[NN];
__device__ int g_adj[EE];
__device__ int g_bsum[64];
__device__ int g_boff[64];

__device__ __forceinline__ float sigmoidf_(float v) { return 1.0f / (1.0f + __expf(-v)); }

typedef unsigned long long ull;

__device__ __forceinline__ ull pack2s(float a) {
    ull r;
    asm("mov.b64 %0, {%1, %1};" : "=l"(r) : "f"(a));
    return r;
}
__device__ __forceinline__ void unpack2(ull v, float& a, float& b) {
    asm("mov.b64 {%0, %1}, %2;" : "=f"(a), "=f"(b) : "l"(v));
}
__device__ __forceinline__ ull fma2(ull a, ull b, ull c) {
    ull r;
    asm("fma.rn.f32x2 %0, %1, %2, %3;" : "=l"(r) : "l"(a), "l"(b), "l"(c));
    return r;
}

#define AT_S 68

// ---------------- per-node precompute (+deg zero) ----------------------------
__global__ void k_prep(const float* __restrict__ x, int n) {
    int tid = blockIdx.x * blockDim.x + threadIdx.x;
    if (tid >= n * 16) return;
    int nd = tid >> 4, c = tid & 15;
    if (c == 0) g_deg[nd] = 0;
    float4 v = ((const float4*)x)[(size_t)nd * 16 + c];
    float m0 = fmaxf(v.x, 0.f) + 1e-7f;
    float m1 = fmaxf(v.y, 0.f) + 1e-7f;
    float m2 = fmaxf(v.z, 0.f) + 1e-7f;
    float m3 = fmaxf(v.w, 0.f) + 1e-7f;
    float p0 = expf(m0), p1 = expf(m1), p2 = expf(m2), p3 = expf(m3);
    float4* row = (float4*)&g_pq[(size_t)nd * 128];
    row[c]      = make_float4(p0, p1, p2, p3);
    row[16 + c] = make_float4(p0 * m0, p1 * m1, p2 * m2, p3 * m3);
    ((float4*)&g_x2[(size_t)nd * 128])[c] =
        make_float4(sigmoidf_(v.x), sigmoidf_(v.y), sigmoidf_(v.z), sigmoidf_(v.w));
}

// ---------------- CSR build ---------------------------------------------------
__global__ void k_hist(const int* __restrict__ dst, int E) {
    int e = blockIdx.x * blockDim.x + threadIdx.x;
    if (e < E) atomicAdd(&g_deg[dst[e]], 1);
}

__global__ void __launch_bounds__(1024) k_scanA(int n) {
    __shared__ int wp[32];
    int t = threadIdx.x, lane = t & 31, wid = t >> 5;
    int node = blockIdx.x * 1024 + t;
    int d = (node < n) ? g_deg[node] : 0;
    int inc = d;
#pragma unroll
    for (int s = 1; s < 32; s <<= 1) {
        int v = __shfl_up_sync(0xffffffffu, inc, s);
        if (lane >= s) inc += v;
    }
    if (lane == 31) wp[wid] = inc;
    __syncthreads();
    if (wid == 0) {
        int w = wp[lane], winc = w;
#pragma unroll
        for (int s = 1; s < 32; s <<= 1) {
            int v = __shfl_up_sync(0xffffffffu, winc, s);
            if (lane >= s) winc += v;
        }
        wp[lane] = winc - w;
    }
    __syncthreads();
    int ex = wp[wid] + inc - d;
    if (node < n) g_off[node] = ex;
    if (t == 1023) g_bsum[blockIdx.x] = ex + d;
}

// also zeroes BN stat accumulators (runs before gemm1)
__global__ void k_scanB(int nb, int n, int E) {
    int t = threadIdx.x, lane = t & 31, wid = t >> 5;
    __shared__ int w0tot;
    if (t < 64) {
        g_sum[t] = 0.f; g_sum[t + 64] = 0.f;
        g_sumsq[t] = 0.f; g_sumsq[t + 64] = 0.f;
    }
    int v = (t < nb) ? g_bsum[t] : 0;
    int inc = v;
#pragma unroll
    for (int s = 1; s < 32; s <<= 1) {
        int u = __shfl_up_sync(0xffffffffu, inc, s);
        if (lane >= s) inc += u;
    }
    if (t == 31) w0tot = inc;
    __syncthreads();
    int ex = inc - v + (wid ? w0tot : 0);
    if (t < nb) g_boff[t] = ex;
    if (t == 0) g_off[n] = E;
}

__global__ void __launch_bounds__(1024) k_scanC(int n) {
    int node = blockIdx.x * 1024 + threadIdx.x;
    if (node >= n) return;
    int o = g_off[node] + g_boff[blockIdx.x];
    g_off[node] = o;
    g_cur[node] = o;
}

__global__ void k_scatter(const int* __restrict__ src, const int* __restrict__ dst, int E) {
    int e = blockIdx.x * blockDim.x + threadIdx.x;
    if (e >= E) return;
    int pos = atomicAdd(&g_cur[dst[e]], 1);
    g_adj[pos] = src[e];
}

// ---------------- gathers ------------------------------------------------------
// warp-per-dst, 128-wide (GENConv pq)
__global__ void k_gather_gen(int n) {
    int w = (blockIdx.x * blockDim.x + threadIdx.x) >> 5;
    int lane = threadIdx.x & 31;
    if (w >= n) return;
    int e = g_off[w], end = g_off[w + 1];
    float4 acc = make_float4(0.f, 0.f, 0.f, 0.f);
    for (; e + 4 <= end; e += 4) {
        int s0 = g_adj[e], s1 = g_adj[e + 1], s2 = g_adj[e + 2], s3 = g_adj[e + 3];
        float4 v0 = ((const float4*)g_pq)[(size_t)s0 * 32 + lane];
        float4 v1 = ((const float4*)g_pq)[(size_t)s1 * 32 + lane];
        float4 v2 = ((const float4*)g_pq)[(size_t)s2 * 32 + lane];
        float4 v3 = ((const float4*)g_pq)[(size_t)s3 * 32 + lane];
        acc.x += v0.x + v1.x + v2.x + v3.x;
        acc.y += v0.y + v1.y + v2.y + v3.y;
        acc.z += v0.z + v1.z + v2.z + v3.z;
        acc.w += v0.w + v1.w + v2.w + v3.w;
    }
    for (; e < end; e++) {
        int s = g_adj[e];
        float4 v = ((const float4*)g_pq)[(size_t)s * 32 + lane];
        acc.x += v.x; acc.y += v.y; acc.z += v.z; acc.w += v.w;
    }
    ((float4*)g_dennum)[(size_t)w * 32 + lane] = acc;
}

// half-warp-per-dst, 64-wide (SAGE xpl)
__global__ void k_gather_sage(int n) {
    int w = (blockIdx.x * blockDim.x + threadIdx.x) >> 4;
    int lane = threadIdx.x & 15;
    if (w >= n) return;
    int e = g_off[w], end = g_off[w + 1];
    float4 acc = make_float4(0.f, 0.f, 0.f, 0.f);
    for (; e + 4 <= end; e += 4) {
        int s0 = g_adj[e], s1 = g_adj[e + 1], s2 = g_adj[e + 2], s3 = g_adj[e + 3];
        float4 v0 = ((const float4*)g_xpl)[(size_t)s0 * 16 + lane];
        float4 v1 = ((const float4*)g_xpl)[(size_t)s1 * 16 + lane];
        float4 v2 = ((const float4*)g_xpl)[(size_t)s2 * 16 + lane];
        float4 v3 = ((const float4*)g_xpl)[(size_t)s3 * 16 + lane];
        acc.x += v0.x + v1.x + v2.x + v3.x;
        acc.y += v0.y + v1.y + v2.y + v3.y;
        acc.z += v0.z + v1.z + v2.z + v3.z;
        acc.w += v0.w + v1.w + v2.w + v3.w;
    }
    for (; e < end; e++) {
        int s = g_adj[e];
        float4 v = ((const float4*)g_xpl)[(size_t)s * 16 + lane];
        acc.x += v.x; acc.y += v.y; acc.z += v.z; acc.w += v.w;
    }
    ((float4*)g_aggr)[(size_t)w * 16 + lane] = acc;
}

// ============ tiled GEMM bodies (packed f32x2) ===============================
#define DECL_ACC2(CGMASK, NGSHIFT)                                              \
    int cg = tid & (CGMASK);                                                    \
    int ng = tid >> (NGSHIFT);                                                  \
    ull acc2[4][4];                                                             \
    _Pragma("unroll")                                                           \
    for (int i = 0; i < 4; i++)                                                 \
        _Pragma("unroll")                                                       \
        for (int j = 0; j < 4; j++) acc2[i][j] = 0ull;

#define MLBODY2(CIN, COUT)                                                      \
    {                                                                           \
        const float* Ap = At + ng * 4;                                          \
        const ull* Wq = (const ull*)(Ws + cg * 8);                              \
        _Pragma("unroll 8")                                                     \
        for (int k = 0; k < (CIN); k++) {                                       \
            float4 a4 = *(const float4*)&Ap[k * AT_S];                          \
            ulonglong2 wa = *(const ulonglong2*)(Wq + k * ((COUT) / 2));        \
            ulonglong2 wb = *(const ulonglong2*)(Wq + k * ((COUT) / 2) + 2);    \
            ull av[4] = {pack2s(a4.x), pack2s(a4.y), pack2s(a4.z), pack2s(a4.w)};\
            _Pragma("unroll")                                                   \
            for (int i = 0; i < 4; i++) {                                       \
                acc2[i][0] = fma2(av[i], wa.x, acc2[i][0]);                     \
                acc2[i][1] = fma2(av[i], wa.y, acc2[i][1]);                     \
                acc2[i][2] = fma2(av[i], wb.x, acc2[i][2]);                     \
                acc2[i][3] = fma2(av[i], wb.y, acc2[i][3]);                     \
            }                                                                   \
        }                                                                       \
    }

#define UNPACK_ACC()                                                            \
    float acc[4][8];                                                            \
    _Pragma("unroll")                                                           \
    for (int i = 0; i < 4; i++)                                                 \
        _Pragma("unroll")                                                       \
        for (int j = 0; j < 4; j++)                                             \
            unpack2(acc2[i][j], acc[i][2 * j], acc[i][2 * j + 1]);

// ---------------- GEMM1 (+fused column stats) --------------------------------
__global__ void __launch_bounds__(256) k_gemm1(const float* __restrict__ x,
                                               const float* __restrict__ W1,
                                               const float* __restrict__ b1, int n) {
    extern __shared__ float sm[];
    float* Ws = sm;
    float* At = Ws + 64 * 128;
    float* bs = At + 64 * AT_S;
    int tid = threadIdx.x;
    for (int i = tid; i < 2048; i += 256) ((float4*)Ws)[i] = ((const float4*)W1)[i];
    if (tid < 128) bs[tid] = b1[tid];
    int base = blockIdx.x * 64;
    for (int i = tid; i < 1024; i += 256) {
        int ndl = i >> 4, c4 = i & 15;
        int nd = base + ndl;
        float4 in4 = make_float4(0.f, 0.f, 0.f, 0.f);
        if (nd < n) {
            float4 de = ((const float4*)&g_dennum[(size_t)nd * 128])[c4];
            float4 nu = ((const float4*)&g_dennum[(size_t)nd * 128])[16 + c4];
            float4 xv = ((const float4*)x)[(size_t)nd * 16 + c4];
            in4.x = nu.x / (de.x > 0.f ? de.x : 1.f) + xv.x;
            in4.y = nu.y / (de.y > 0.f ? de.y : 1.f) + xv.y;
            in4.z = nu.z / (de.z > 0.f ? de.z : 1.f) + xv.z;
            in4.w = nu.w / (de.w > 0.f ? de.w : 1.f) + xv.w;
        }
        int k0 = c4 * 4;
        At[(k0 + 0) * AT_S + ndl] = in4.x;
        At[(k0 + 1) * AT_S + ndl] = in4.y;
        At[(k0 + 2) * AT_S + ndl] = in4.z;
        At[(k0 + 3) * AT_S + ndl] = in4.w;
    }
    __syncthreads();
    DECL_ACC2(15, 4)
    MLBODY2(64, 128)
    UNPACK_ACC()
    float ls[8], lq[8];
#pragma unroll
    for (int j = 0; j < 8; j++) { ls[j] = 0.f; lq[j] = 0.f; }
#pragma unroll
    for (int i = 0; i < 4; i++) {
        int nd = base + ng * 4 + i;
        if (nd >= n) break;
        float v[8];
#pragma unroll
        for (int j = 0; j < 8; j++) {
            v[j] = acc[i][j] + bs[cg * 8 + j];
            ls[j] += v[j];
            lq[j] += v[j] * v[j];
        }
        float4* o = (float4*)&g_h1[(size_t)nd * 128 + cg * 8];
        o[0] = make_float4(v[0], v[1], v[2], v[3]);
        o[1] = make_float4(v[4], v[5], v[6], v[7]);
    }
    __syncthreads();
    float* ssum = At;
    float* ssq  = At + 128;
    if (tid < 128) { ssum[tid] = 0.f; ssq[tid] = 0.f; }
    __syncthreads();
#pragma unroll
    for (int j = 0; j < 8; j++) {
        atomicAdd(&ssum[cg * 8 + j], ls[j]);
        atomicAdd(&ssq[cg * 8 + j], lq[j]);
    }
    __syncthreads();
    if (tid < 128) {
        atomicAdd(&g_sum[tid], ssum[tid]);
        atomicAdd(&g_sumsq[tid], ssq[tid]);
    }
}

// ---------------- GEMM2 (computes BN stats from g_sum inline) ------------------
__global__ void __launch_bounds__(128) k_gemm2(const float* __restrict__ gamma,
                                               const float* __restrict__ beta,
                                               const float* __restrict__ W2,
                                               const float* __restrict__ b2, int n) {
    extern __shared__ float sm[];
    float* Ws = sm;
    float* At = Ws + 128 * 64;
    float* prm = At + 128 * AT_S;
    float* bs = prm + 512;
    int tid = threadIdx.x;
    for (int i = tid; i < 2048; i += 128) ((float4*)Ws)[i] = ((const float4*)W2)[i];
    if (tid < 128) {
        prm[tid]       = gamma[tid];
        prm[128 + tid] = beta[tid];
        float fn = (float)n;
        float mu = g_sum[tid] / fn;
        float var = g_sumsq[tid] / fn - mu * mu;
        prm[256 + tid] = mu;
        prm[384 + tid] = rsqrtf(var + 1e-5f);
    }
    if (tid < 64) bs[tid] = b2[tid];
    __syncthreads();
    int base = blockIdx.x * 64;
    for (int i = tid; i < 2048; i += 128) {
        int ndl = i >> 5, c4 = i & 31;
        int nd = base + ndl;
        float4 v = make_float4(0.f, 0.f, 0.f, 0.f);
        if (nd < n) v = ((const float4*)&g_h1[(size_t)nd * 128])[c4];
        int k0 = c4 * 4;
#pragma unroll
        for (int q = 0; q < 4; q++) {
            float val = (q == 0) ? v.x : (q == 1) ? v.y : (q == 2) ? v.z : v.w;
            int col = k0 + q;
            val = (val - prm[256 + col]) * prm[384 + col] * prm[col] + prm[128 + col];
            At[col * AT_S + ndl] = fmaxf(val, 0.f);
        }
    }
    __syncthreads();
    DECL_ACC2(7, 3)
    MLBODY2(128, 64)
    UNPACK_ACC()
#pragma unroll
    for (int i = 0; i < 4; i++) {
        int nd = base + ng * 4 + i;
        if (nd >= n) break;
        float4 o0 = make_float4(sigmoidf_(acc[i][0] + bs[cg * 8 + 0]),
                                sigmoidf_(acc[i][1] + bs[cg * 8 + 1]),
                                sigmoidf_(acc[i][2] + bs[cg * 8 + 2]),
                                sigmoidf_(acc[i][3] + bs[cg * 8 + 3]));
        float4 o1 = make_float4(sigmoidf_(acc[i][4] + bs[cg * 8 + 4]),
                                sigmoidf_(acc[i][5] + bs[cg * 8 + 5]),
                                sigmoidf_(acc[i][6] + bs[cg * 8 + 6]),
                                sigmoidf_(acc[i][7] + bs[cg * 8 + 7]));
        float4* o = (float4*)&g_x2[(size_t)nd * 128 + 64 + cg * 8];
        o[0] = o0; o[1] = o1;
    }
}

// ---------------- GEMM3: xp = relu(x2@Wp+bp); xpl = xp@Wl (fused) --------------
__global__ void __launch_bounds__(256) k_gemm3(const float* __restrict__ Wp,
                                               const float* __restrict__ bp,
                                               const float* __restrict__ Wl, int n) {
    extern __shared__ float sm[];
    float* Ws = sm;                // 128*128 (Wp), stage2: first 128*64 = Wl
    float* At = Ws + 128 * 128;    // 128*AT_S
    float* bs = At + 128 * AT_S;   // 128
    int tid = threadIdx.x;
    for (int i = tid; i < 4096; i += 256) ((float4*)Ws)[i] = ((const float4*)Wp)[i];
    if (tid < 128) bs[tid] = bp[tid];
    int base = blockIdx.x * 64;
    for (int i = tid; i < 2048; i += 256) {
        int ndl = i >> 5, c4 = i & 31;
        int nd = base + ndl;
        float4 v = make_float4(0.f, 0.f, 0.f, 0.f);
        if (nd < n) v = ((const float4*)&g_x2[(size_t)nd * 128])[c4];
        int k0 = c4 * 4;
        At[(k0 + 0) * AT_S + ndl] = v.x;
        At[(k0 + 1) * AT_S + ndl] = v.y;
        At[(k0 + 2) * AT_S + ndl] = v.z;
        At[(k0 + 3) * AT_S + ndl] = v.w;
    }
    __syncthreads();
    DECL_ACC2(15, 4)
    MLBODY2(128, 128)
    UNPACK_ACC()
    // xp values (bias + relu)
    float xpv[4][8];
#pragma unroll
    for (int i = 0; i < 4; i++)
#pragma unroll
        for (int j = 0; j < 8; j++)
            xpv[i][j] = fmaxf(acc[i][j] + bs[cg * 8 + j], 0.f);
    __syncthreads();   // done reading At (x2) and Ws (Wp)
    // overwrite weights with Wl, write xp transposed into At
    for (int i = tid; i < 2048; i += 256) ((float4*)Ws)[i] = ((const float4*)Wl)[i];
#pragma unroll
    for (int i = 0; i < 4; i++)
#pragma unroll
        for (int j = 0; j < 8; j++)
            At[(cg * 8 + j) * AT_S + (ng * 4 + i)] = xpv[i][j];
    __syncthreads();
    // stage 2: xpl = xp @ Wl   (2 nodes x 8 cols per thread)
    int cg2 = tid & 7, ng2 = tid >> 3;   // cg2 0..7, ng2 0..31
    ull a2[2][4];
#pragma unroll
    for (int i = 0; i < 2; i++)
#pragma unroll
        for (int j = 0; j < 4; j++) a2[i][j] = 0ull;
    {
        const float* Ap2 = At + ng2 * 2;
        const ull* Wq2 = (const ull*)(Ws + cg2 * 8);
#pragma unroll 8
        for (int k = 0; k < 128; k++) {
            float2 a = *(const float2*)&Ap2[k * AT_S];
            ulonglong2 wa = *(const ulonglong2*)(Wq2 + k * 32);
            ulonglong2 wb = *(const ulonglong2*)(Wq2 + k * 32 + 2);
            ull av0 = pack2s(a.x), av1 = pack2s(a.y);
            a2[0][0] = fma2(av0, wa.x, a2[0][0]);
            a2[0][1] = fma2(av0, wa.y, a2[0][1]);
            a2[0][2] = fma2(av0, wb.x, a2[0][2]);
            a2[0][3] = fma2(av0, wb.y, a2[0][3]);
            a2[1][0] = fma2(av1, wa.x, a2[1][0]);
            a2[1][1] = fma2(av1, wa.y, a2[1][1]);
            a2[1][2] = fma2(av1, wb.x, a2[1][2]);
            a2[1][3] = fma2(av1, wb.y, a2[1][3]);
        }
    }
#pragma unroll
    for (int i = 0; i < 2; i++) {
        int nd = base + ng2 * 2 + i;
        if (nd >= n) break;
        float v[8];
#pragma unroll
        for (int j = 0; j < 4; j++) unpack2(a2[i][j], v[2 * j], v[2 * j + 1]);
        float4* o = (float4*)&g_xpl[(size_t)nd * 64 + cg2 * 8];
        o[0] = make_float4(v[0], v[1], v[2], v[3]);
        o[1] = make_float4(v[4], v[5], v[6], v[7]);
    }
}

// ---------------- GEMM4: sigmoid(aggr_l + x2@Wr + bl) @ Wf + bf ----------------
__global__ void __launch_bounds__(128) k_gemm4(const float* __restrict__ Wr,
                                               const float* __restrict__ bl,
                                               const float* __restrict__ Wf,
                                               const float* __restrict__ bf,
                                               float* __restrict__ out,
                                               int n, int write_logits) {
    extern __shared__ float sm[];
    float* Ws = sm;               // 128*64
    float* At = Ws + 128 * 64;    // 128*AT_S
    float* bs = At + 128 * AT_S;  // 64
    float* wf = bs + 64;          // 64
    int tid = threadIdx.x;
    int base = blockIdx.x * 64;
    for (int i = tid; i < 2048; i += 128) ((float4*)Ws)[i] = ((const float4*)Wr)[i];
    if (tid < 64) { bs[tid] = bl[tid]; wf[tid] = Wf[tid]; }
    for (int i = tid; i < 2048; i += 128) {
        int ndl = i >> 5, c4 = i & 31;
        int nd = base + ndl;
        float4 v = make_float4(0.f, 0.f, 0.f, 0.f);
        if (nd < n) v = ((const float4*)&g_x2[(size_t)nd * 128])[c4];
        int k0 = c4 * 4;
        At[(k0 + 0) * AT_S + ndl] = v.x;
        At[(k0 + 1) * AT_S + ndl] = v.y;
        At[(k0 + 2) * AT_S + ndl] = v.z;
        At[(k0 + 3) * AT_S + ndl] = v.w;
    }
    __syncthreads();
    DECL_ACC2(7, 3)
    MLBODY2(128, 64)
    UNPACK_ACC()
    float bf0 = bf[0];
#pragma unroll
    for (int i = 0; i < 4; i++) {
        int nd = base + ng * 4 + i;
        float lp = 0.f;
        if (nd < n) {
            float4 a0 = ((const float4*)&g_aggr[(size_t)nd * 64 + cg * 8])[0];
            float4 a1 = ((const float4*)&g_aggr[(size_t)nd * 64 + cg * 8])[1];
            float av[8] = {a0.x, a0.y, a0.z, a0.w, a1.x, a1.y, a1.z, a1.w};
#pragma unroll
            for (int j = 0; j < 8; j++)
                lp += sigmoidf_(acc[i][j] + av[j] + bs[cg * 8 + j]) * wf[cg * 8 + j];
        }
        lp += __shfl_xor_sync(0xffffffffu, lp, 1);
        lp += __shfl_xor_sync(0xffffffffu, lp, 2);
        lp += __shfl_xor_sync(0xffffffffu, lp, 4);
        if (cg == 0 && nd < n) {
            float logit = lp + bf0;
            out[nd] = sigmoidf_(logit);
            if (write_logits) out[n + nd] = logit;
        }
    }
}

// ---------------- launch --------------------------------------------------------
extern "C" void kernel_launch(void* const* d_in, const int* in_sizes, int n_in,
                              void* d_out, int out_size) {
    const float* x   = (const float*)d_in[0];
    const int*   ei  = (const int*)d_in[1];
    const float* W1  = (const float*)d_in[2];
    const float* b1  = (const float*)d_in[3];
    const float* gamma = (const float*)d_in[4];
    const float* beta  = (const float*)d_in[5];
    const float* W2  = (const float*)d_in[6];
    const float* b2  = (const float*)d_in[7];
    const float* Wp  = (const float*)d_in[8];
    const float* bp  = (const float*)d_in[9];
    const float* Wl  = (const float*)d_in[10];
    const float* bl  = (const float*)d_in[11];
    const float* Wr  = (const float*)d_in[12];
    const float* Wf  = (const float*)d_in[13];
    const float* bf  = (const float*)d_in[14];
    float* out = (float*)d_out;

    int n = in_sizes[0] / 64;
    int E = in_sizes[1] / 2;
    const int* src = ei;
    const int* dst = ei + E;
    int write_logits = (out_size >= 2 * n) ? 1 : 0;

    const int S1 = (64 * 128 + 64 * AT_S + 128) * 4;
    const int S2 = (128 * 64 + 128 * AT_S + 512 + 64) * 4;
    const int S3 = (128 * 128 + 128 * AT_S + 128) * 4;
    const int S4 = (128 * 64 + 128 * AT_S + 128) * 4;
    cudaFuncSetAttribute(k_gemm1, cudaFuncAttributeMaxDynamicSharedMemorySize, S1);
    cudaFuncSetAttribute(k_gemm2, cudaFuncAttributeMaxDynamicSharedMemorySize, S2);
    cudaFuncSetAttribute(k_gemm3, cudaFuncAttributeMaxDynamicSharedMemorySize, S3);
    cudaFuncSetAttribute(k_gemm4, cudaFuncAttributeMaxDynamicSharedMemorySize, S4);

    k_prep<<<(n * 16 + 255) / 256, 256>>>(x, n);
    k_hist<<<(E + 255) / 256, 256>>>(dst, E);
    int nb1024 = (n + 1023) / 1024;
    k_scanA<<<nb1024, 1024>>>(n);
    k_scanB<<<1, 64>>>(nb1024, n, E);
    k_scanC<<<nb1024, 1024>>>(n);
    k_scatter<<<(E + 255) / 256, 256>>>(src, dst, E);

    k_gather_gen<<<(n * 32 + 255) / 256, 256>>>(n);

    int nb = (n + 63) / 64;
    k_gemm1<<<nb, 256, S1>>>(x, W1, b1, n);
    k_gemm2<<<nb, 128, S2>>>(gamma, beta, W2, b2, n);
    k_gemm3<<<nb, 256, S3>>>(Wp, bp, Wl, n);
    k_gather_sage<<<(n * 16 + 255) / 256, 256>>>(n);
    k_gemm4<<<nb, 128, S4>>>(Wr, bl, Wf, bf, out, n, write_logits);
}